// round 1
// baseline (speedup 1.0000x reference)
#include <cuda_runtime.h>
#include <cuda_bf16.h>
#include <math.h>

// ----------------------------------------------------------------------------
// GATv2 Transformer: N=50000 nodes, E=800000 edges, DIM=128, HEADS=2, DEPTH=2,
// MLP=512. fp32 throughout.
// ----------------------------------------------------------------------------

#define MAXN 50000
#define MAXE 800000
#define DIM 128
#define HD 256           // HEADS*DIM
#define MLPD 512

// ------------------------- scratch (device globals) -------------------------
__device__ __align__(256) float g_h   [(size_t)MAXN * DIM];
__device__ __align__(256) float g_xl  [(size_t)MAXN * HD];
__device__ __align__(256) float g_xr  [(size_t)MAXN * HD];
__device__ __align__(256) float g_gout[(size_t)MAXN * HD];
__device__ __align__(256) float g_mid [(size_t)MAXN * MLPD];
__device__ __align__(256) float g_score[(size_t)MAXE * 2];
__device__ __align__(256) unsigned g_smax[(size_t)MAXN * 2];
__device__ __align__(256) float g_denom[(size_t)MAXN * 2];
__device__ __align__(256) int g_src[MAXE];
__device__ __align__(256) int g_dst[MAXE];
__device__ int g_is64;

// ------------------------- helpers -------------------------
__device__ __forceinline__ unsigned fenc(float f) {
    unsigned u = __float_as_uint(f);
    return (u >> 31) ? ~u : (u | 0x80000000u);
}
__device__ __forceinline__ float fdec(unsigned u) {
    return (u >> 31) ? __uint_as_float(u & 0x7fffffffu) : __uint_as_float(~u);
}

// ------------------------- edge dtype detect/decode -------------------------
__global__ void detect_kernel(const void* edges, int E, int N) {
    __shared__ int bad;
    if (threadIdx.x == 0) bad = 0;
    __syncthreads();
    const long long* p = (const long long*)edges;
    int n = E < 2048 ? E : 2048;
    for (int i = threadIdx.x; i < n; i += blockDim.x) {
        long long v = p[i];
        if (v < 0 || v >= (long long)N) atomicOr(&bad, 1);
    }
    __syncthreads();
    if (threadIdx.x == 0) g_is64 = bad ? 0 : 1;
}

__global__ void decode_kernel(const void* edges, int E) {
    int i = blockIdx.x * blockDim.x + threadIdx.x;
    if (i >= E) return;
    if (g_is64) {
        const long long* p = (const long long*)edges;
        g_src[i] = (int)p[i];
        g_dst[i] = (int)p[(size_t)E + i];
    } else {
        const int* p = (const int*)edges;
        g_src[i] = p[i];
        g_dst[i] = p[(size_t)E + i];
    }
}

// ------------------------- layernorm (warp per row) -------------------------
__global__ void ln_kernel(const float* __restrict__ x, const float* __restrict__ g,
                          const float* __restrict__ b, float* __restrict__ out, int N) {
    int row = (blockIdx.x * blockDim.x + threadIdx.x) >> 5;
    int lane = threadIdx.x & 31;
    if (row >= N) return;
    const float4* xr = (const float4*)x + (size_t)row * 32;
    float4 v = xr[lane];
    float s  = v.x + v.y + v.z + v.w;
    float sq = v.x*v.x + v.y*v.y + v.z*v.z + v.w*v.w;
    #pragma unroll
    for (int o = 16; o; o >>= 1) {
        s  += __shfl_xor_sync(0xffffffffu, s,  o);
        sq += __shfl_xor_sync(0xffffffffu, sq, o);
    }
    float m   = s * (1.0f / 128.0f);
    float var = sq * (1.0f / 128.0f) - m * m;
    float inv = rsqrtf(var + 1e-5f);
    float4 gg = ((const float4*)g)[lane];
    float4 bb = ((const float4*)b)[lane];
    float4 o4;
    o4.x = (v.x - m) * inv * gg.x + bb.x;
    o4.y = (v.y - m) * inv * gg.y + bb.y;
    o4.z = (v.z - m) * inv * gg.z + bb.z;
    o4.w = (v.w - m) * inv * gg.w + bb.w;
    ((float4*)out + (size_t)row * 32)[lane] = o4;
}

// ------------------------- SGEMM: C = A[M,K]@B[K,N] + bias (+C) -------------
// BM=BN=128, BK=16, 256 threads, 8x8 microtile. K%16==0, N%128==0 assumed.
template<bool ACCUM, bool GELU>
__global__ __launch_bounds__(256)
void gemm_kernel(const float* __restrict__ A, const float* __restrict__ B,
                 const float* __restrict__ bias, float* __restrict__ C,
                 int M, int K, int N) {
    __shared__ float As[128][16];
    __shared__ float Bs[16][128];
    const int tid = threadIdx.x;
    const int tx = tid & 15, ty = tid >> 4;
    const int m0 = blockIdx.y * 128, n0 = blockIdx.x * 128;

    float acc[8][8];
    #pragma unroll
    for (int i = 0; i < 8; i++)
        #pragma unroll
        for (int j = 0; j < 8; j++) acc[i][j] = 0.0f;

    for (int k0 = 0; k0 < K; k0 += 16) {
        #pragma unroll
        for (int t = 0; t < 2; t++) {
            int f = tid + t * 256;          // 0..511 float4 slots (128x16)
            int r = f >> 2, c4 = f & 3;
            float4 v = make_float4(0.f, 0.f, 0.f, 0.f);
            if (m0 + r < M)
                v = *(const float4*)(A + (size_t)(m0 + r) * K + k0 + c4 * 4);
            *(float4*)(&As[r][c4 * 4]) = v;
        }
        #pragma unroll
        for (int t = 0; t < 2; t++) {
            int f = tid + t * 256;          // 0..511 float4 slots (16x128)
            int r = f >> 5, c4 = f & 31;
            *(float4*)(&Bs[r][c4 * 4]) =
                *(const float4*)(B + (size_t)(k0 + r) * N + n0 + c4 * 4);
        }
        __syncthreads();
        #pragma unroll
        for (int kk = 0; kk < 16; kk++) {
            float a[8], b[8];
            #pragma unroll
            for (int i = 0; i < 8; i++) a[i] = As[ty * 8 + i][kk];
            float4 b0 = *(const float4*)(&Bs[kk][tx * 8]);
            float4 b1 = *(const float4*)(&Bs[kk][tx * 8 + 4]);
            b[0]=b0.x; b[1]=b0.y; b[2]=b0.z; b[3]=b0.w;
            b[4]=b1.x; b[5]=b1.y; b[6]=b1.z; b[7]=b1.w;
            #pragma unroll
            for (int i = 0; i < 8; i++)
                #pragma unroll
                for (int j = 0; j < 8; j++)
                    acc[i][j] += a[i] * b[j];
        }
        __syncthreads();
    }

    #pragma unroll
    for (int i = 0; i < 8; i++) {
        int gm = m0 + ty * 8 + i;
        if (gm >= M) continue;
        #pragma unroll
        for (int j = 0; j < 8; j++) {
            int gn = n0 + tx * 8 + j;
            float v = acc[i][j] + bias[gn];
            if (GELU) {
                float u = v;
                v = 0.5f * u * (1.0f + tanhf(0.7978845608028654f * (u + 0.044715f * u * u * u)));
            }
            size_t idx = (size_t)gm * N + gn;
            if (ACCUM) C[idx] = C[idx] + v; else C[idx] = v;
        }
    }
}

// ------------------------- clear per-layer accumulators ----------------------
__global__ void clear_kernel(int N) {
    int i = blockIdx.x * blockDim.x + threadIdx.x;
    if (i < 2 * N) { g_smax[i] = 0u; g_denom[i] = 0.0f; }
    if (i < N * HD) g_gout[i] = 0.0f;
}

// ------------------------- edge scores + segment max -------------------------
__global__ void score_kernel(const float* __restrict__ xl, const float* __restrict__ xr,
                             const float* __restrict__ att, int E) {
    int e = (blockIdx.x * blockDim.x + threadIdx.x) >> 5;
    int lane = threadIdx.x & 31;
    if (e >= E) return;
    int s = g_src[e], d = g_dst[e];
    const float4* xls = (const float4*)xl + (size_t)s * 64;
    const float4* xrd = (const float4*)xr + (size_t)d * 64;
    const float4* at4 = (const float4*)att;
    float sc[2];
    #pragma unroll
    for (int h = 0; h < 2; h++) {
        float4 l = xls[h * 32 + lane];
        float4 r = xrd[h * 32 + lane];
        float4 a = at4[h * 32 + lane];
        float4 v;
        v.x = l.x + r.x; v.x = v.x > 0.f ? v.x : 0.2f * v.x;
        v.y = l.y + r.y; v.y = v.y > 0.f ? v.y : 0.2f * v.y;
        v.z = l.z + r.z; v.z = v.z > 0.f ? v.z : 0.2f * v.z;
        v.w = l.w + r.w; v.w = v.w > 0.f ? v.w : 0.2f * v.w;
        float p = v.x * a.x + v.y * a.y + v.z * a.z + v.w * a.w;
        #pragma unroll
        for (int o = 16; o; o >>= 1) p += __shfl_xor_sync(0xffffffffu, p, o);
        sc[h] = p;
    }
    if (lane == 0) {
        g_score[2 * (size_t)e]     = sc[0];
        g_score[2 * (size_t)e + 1] = sc[1];
        atomicMax(&g_smax[2 * d],     fenc(sc[0]));
        atomicMax(&g_smax[2 * d + 1], fenc(sc[1]));
    }
}

// ------------------------- exp + segment sum ---------------------------------
__global__ void exp_kernel(int E2) {
    int i = blockIdx.x * blockDim.x + threadIdx.x;
    if (i >= E2) return;
    int e = i >> 1, h = i & 1;
    int d = g_dst[e];
    float sm = fdec(g_smax[2 * d + h]);
    float ex = expf(g_score[i] - sm);
    g_score[i] = ex;
    atomicAdd(&g_denom[2 * d + h], ex);
}

// ------------------------- weighted aggregation ------------------------------
__global__ void agg_kernel(const float* __restrict__ xl, int E) {
    int e = (blockIdx.x * blockDim.x + threadIdx.x) >> 5;
    int lane = threadIdx.x & 31;
    if (e >= E) return;
    int s = g_src[e], d = g_dst[e];
    float a0 = g_score[2 * (size_t)e]     / (g_denom[2 * d]     + 1e-16f);
    float a1 = g_score[2 * (size_t)e + 1] / (g_denom[2 * d + 1] + 1e-16f);
    const float4* xls = (const float4*)xl + (size_t)s * 64;
    float4 v0 = xls[lane];
    float4 v1 = xls[32 + lane];
    float* p0 = g_gout + (size_t)d * HD + lane * 4;
    // vector reduction atomics (sm_90+)
    atomicAdd((float4*)p0,         make_float4(a0 * v0.x, a0 * v0.y, a0 * v0.z, a0 * v0.w));
    atomicAdd((float4*)(p0 + 128), make_float4(a1 * v1.x, a1 * v1.y, a1 * v1.z, a1 * v1.w));
}

// ------------------------- add gat bias --------------------------------------
__global__ void addbias_kernel(const float* __restrict__ gat_b, int total) {
    int i = blockIdx.x * blockDim.x + threadIdx.x;
    if (i >= total) return;
    g_gout[i] += gat_b[i & (HD - 1)];
}

// ------------------------- launch --------------------------------------------
extern "C" void kernel_launch(void* const* d_in, const int* in_sizes, int n_in,
                              void* d_out, int out_size) {
    const float* x_in   = (const float*)d_in[0];
    const void*  edges  = d_in[1];
    const float* ln1_g  = (const float*)d_in[2];
    const float* ln1_b  = (const float*)d_in[3];
    const float* Wl     = (const float*)d_in[4];
    const float* bl     = (const float*)d_in[5];
    const float* Wr     = (const float*)d_in[6];
    const float* br     = (const float*)d_in[7];
    const float* att    = (const float*)d_in[8];
    const float* gat_b  = (const float*)d_in[9];
    const float* projW  = (const float*)d_in[10];
    const float* projb  = (const float*)d_in[11];
    const float* ln2_g  = (const float*)d_in[12];
    const float* ln2_b  = (const float*)d_in[13];
    const float* W1     = (const float*)d_in[14];
    const float* b1     = (const float*)d_in[15];
    const float* W2     = (const float*)d_in[16];
    const float* b2     = (const float*)d_in[17];

    const int N = in_sizes[0] / DIM;
    const int E = in_sizes[1] / 2;
    float* x = (float*)d_out;

    void *p_h, *p_xl, *p_xr, *p_gout, *p_mid;
    cudaGetSymbolAddress(&p_h, g_h);
    cudaGetSymbolAddress(&p_xl, g_xl);
    cudaGetSymbolAddress(&p_xr, g_xr);
    cudaGetSymbolAddress(&p_gout, g_gout);
    cudaGetSymbolAddress(&p_mid, g_mid);
    float* h    = (float*)p_h;
    float* xl   = (float*)p_xl;
    float* xr   = (float*)p_xr;
    float* gout = (float*)p_gout;
    float* mid  = (float*)p_mid;

    cudaMemcpyAsync(x, x_in, (size_t)N * DIM * sizeof(float), cudaMemcpyDeviceToDevice);

    detect_kernel<<<1, 256>>>(edges, E, N);
    decode_kernel<<<(E + 255) / 256, 256>>>(edges, E);

    const int ln_blocks = (N + 7) / 8;      // 8 rows (warps) per 256-thread block
    const int mtiles = (N + 127) / 128;

    for (int l = 0; l < 2; l++) {
        const float* Wl_l = Wl + (size_t)l * DIM * HD;
        const float* bl_l = bl + (size_t)l * HD;
        const float* Wr_l = Wr + (size_t)l * DIM * HD;
        const float* br_l = br + (size_t)l * HD;
        const float* at_l = att + (size_t)l * HD;
        const float* gb_l = gat_b + (size_t)l * HD;
        const float* pW_l = projW + (size_t)l * HD * DIM;
        const float* pb_l = projb + (size_t)l * DIM;
        const float* W1_l = W1 + (size_t)l * DIM * MLPD;
        const float* b1_l = b1 + (size_t)l * MLPD;
        const float* W2_l = W2 + (size_t)l * MLPD * DIM;
        const float* b2_l = b2 + (size_t)l * DIM;

        // PreNorm
        ln_kernel<<<ln_blocks, 256>>>(x, ln1_g + (size_t)l * DIM, ln1_b + (size_t)l * DIM, h, N);
        // xl = h@Wl+bl, xr = h@Wr+br
        gemm_kernel<false, false><<<dim3(HD / 128, mtiles), 256>>>(h, Wl_l, bl_l, xl, N, DIM, HD);
        gemm_kernel<false, false><<<dim3(HD / 128, mtiles), 256>>>(h, Wr_l, br_l, xr, N, DIM, HD);
        // GATv2 edge phase
        clear_kernel<<<(N * HD + 255) / 256, 256>>>(N);
        score_kernel<<<(E + 7) / 8, 256>>>(xl, xr, at_l, E);
        exp_kernel<<<(2 * E + 255) / 256, 256>>>(2 * E);
        agg_kernel<<<(E + 7) / 8, 256>>>(xl, E);
        addbias_kernel<<<(N * HD + 255) / 256, 256>>>(gb_l, N * HD);
        // x += gout @ proj_W + proj_b
        gemm_kernel<true, false><<<dim3(DIM / 128, mtiles), 256>>>(gout, pW_l, pb_l, x, N, HD, DIM);
        // FFN
        ln_kernel<<<ln_blocks, 256>>>(x, ln2_g + (size_t)l * DIM, ln2_b + (size_t)l * DIM, h, N);
        gemm_kernel<false, true><<<dim3(MLPD / 128, mtiles), 256>>>(h, W1_l, b1_l, mid, N, DIM, MLPD);
        gemm_kernel<true, false><<<dim3(DIM / 128, mtiles), 256>>>(mid, W2_l, b2_l, x, N, MLPD, DIM);
    }
}

// round 3
// speedup vs baseline: 1.1642x; 1.1642x over previous
#include <cuda_runtime.h>
#include <cuda_bf16.h>
#include <math.h>
#include <stdint.h>

// ----------------------------------------------------------------------------
// GATv2 Transformer: N=50000 nodes, E=800000 edges, DIM=128, HEADS=2, DEPTH=2,
// MLP=512. GEMMs via bf16 tensor-core MMA with 3-term fp32 error compensation.
// Fragments loaded with direct LDS (no ldmatrix -> no 16B alignment trap).
// ----------------------------------------------------------------------------

#define MAXN 50000
#define MAXE 800000
#define DIM 128
#define HD 256           // HEADS*DIM
#define MLPD 512

// ------------------------- scratch (device globals) -------------------------
__device__ __align__(256) float g_h   [(size_t)MAXN * DIM];
__device__ __align__(256) float g_xl  [(size_t)MAXN * HD];
__device__ __align__(256) float g_xr  [(size_t)MAXN * HD];
__device__ __align__(256) float g_gout[(size_t)MAXN * HD];
__device__ __align__(256) float g_mid [(size_t)MAXN * MLPD];
__device__ __align__(256) float g_score[(size_t)MAXE * 2];
__device__ __align__(256) unsigned g_smax[(size_t)MAXN * 2];
__device__ __align__(256) float g_denom[(size_t)MAXN * 2];
__device__ __align__(256) int g_src[MAXE];
__device__ __align__(256) int g_dst[MAXE];
__device__ int g_is64;

// ------------------------- helpers -------------------------
__device__ __forceinline__ unsigned fenc(float f) {
    unsigned u = __float_as_uint(f);
    return (u >> 31) ? ~u : (u | 0x80000000u);
}
__device__ __forceinline__ float fdec(unsigned u) {
    return (u >> 31) ? __uint_as_float(u & 0x7fffffffu) : __uint_as_float(~u);
}

// ------------------------- edge dtype detect/decode -------------------------
__global__ void detect_kernel(const void* edges, int E, int N) {
    __shared__ int bad;
    if (threadIdx.x == 0) bad = 0;
    __syncthreads();
    const long long* p = (const long long*)edges;
    int n = E < 2048 ? E : 2048;
    for (int i = threadIdx.x; i < n; i += blockDim.x) {
        long long v = p[i];
        if (v < 0 || v >= (long long)N) atomicOr(&bad, 1);
    }
    __syncthreads();
    if (threadIdx.x == 0) g_is64 = bad ? 0 : 1;
}

__global__ void decode_kernel(const void* edges, int E) {
    int i = blockIdx.x * blockDim.x + threadIdx.x;
    if (i >= E) return;
    if (g_is64) {
        const long long* p = (const long long*)edges;
        g_src[i] = (int)p[i];
        g_dst[i] = (int)p[(size_t)E + i];
    } else {
        const int* p = (const int*)edges;
        g_src[i] = p[i];
        g_dst[i] = p[(size_t)E + i];
    }
}

// ------------------------- layernorm (warp per row) -------------------------
__global__ void ln_kernel(const float* __restrict__ x, const float* __restrict__ g,
                          const float* __restrict__ b, float* __restrict__ out, int N) {
    int row = (blockIdx.x * blockDim.x + threadIdx.x) >> 5;
    int lane = threadIdx.x & 31;
    if (row >= N) return;
    const float4* xr = (const float4*)x + (size_t)row * 32;
    float4 v = xr[lane];
    float s  = v.x + v.y + v.z + v.w;
    float sq = v.x*v.x + v.y*v.y + v.z*v.z + v.w*v.w;
    #pragma unroll
    for (int o = 16; o; o >>= 1) {
        s  += __shfl_xor_sync(0xffffffffu, s,  o);
        sq += __shfl_xor_sync(0xffffffffu, sq, o);
    }
    float m   = s * (1.0f / 128.0f);
    float var = sq * (1.0f / 128.0f) - m * m;
    float inv = rsqrtf(var + 1e-5f);
    float4 gg = ((const float4*)g)[lane];
    float4 bb = ((const float4*)b)[lane];
    float4 o4;
    o4.x = (v.x - m) * inv * gg.x + bb.x;
    o4.y = (v.y - m) * inv * gg.y + bb.y;
    o4.z = (v.z - m) * inv * gg.z + bb.z;
    o4.w = (v.w - m) * inv * gg.w + bb.w;
    ((float4*)out + (size_t)row * 32)[lane] = o4;
}

// ------------------------- tensor-core GEMM --------------------------------
// C = A[M,K] @ B[K,N] + bias (+C, optional GELU). K%32==0, N%128==0.
// bf16 split: a = a_hi + a_lo; computes hi*hi + hi*lo + lo*hi in fp32 accum.

__device__ __forceinline__ void mma16816(float* c, const uint32_t* a, const uint32_t* b) {
    asm volatile(
        "mma.sync.aligned.m16n8k16.row.col.f32.bf16.bf16.f32 "
        "{%0,%1,%2,%3}, {%4,%5,%6,%7}, {%8,%9}, {%0,%1,%2,%3};"
        : "+f"(c[0]), "+f"(c[1]), "+f"(c[2]), "+f"(c[3])
        : "r"(a[0]), "r"(a[1]), "r"(a[2]), "r"(a[3]), "r"(b[0]), "r"(b[1]));
}

__device__ __forceinline__ void split_pack(float x, float y, uint32_t& hi, uint32_t& lo) {
    __nv_bfloat16 hx = __float2bfloat16_rn(x);
    __nv_bfloat16 hy = __float2bfloat16_rn(y);
    __nv_bfloat16 lx = __float2bfloat16_rn(x - __bfloat162float(hx));
    __nv_bfloat16 ly = __float2bfloat16_rn(y - __bfloat162float(hy));
    hi = ((uint32_t)__bfloat16_as_ushort(hy) << 16) | (uint32_t)__bfloat16_as_ushort(hx);
    lo = ((uint32_t)__bfloat16_as_ushort(ly) << 16) | (uint32_t)__bfloat16_as_ushort(lx);
}

// pitch 20 words: row-bank offset g*20 mod 32 hits {0,20,8,28,16,4,24,12} —
// combined with tg in 0..3 the 32 lanes of a fragment load are conflict-free.
#define SPITCH 20

template<bool ACCUM, bool GELU>
__global__ __launch_bounds__(256)
void gemm_kernel(const float* __restrict__ A, const float* __restrict__ B,
                 const float* __restrict__ bias, float* __restrict__ C,
                 int M, int K, int N) {
    __shared__ uint32_t As_hi[128][SPITCH];
    __shared__ uint32_t As_lo[128][SPITCH];
    __shared__ uint32_t Bs_hi[128][SPITCH];
    __shared__ uint32_t Bs_lo[128][SPITCH];

    const int tid  = threadIdx.x;
    const int lane = tid & 31;
    const int wid  = tid >> 5;
    const int warp_m = wid & 3;   // 4 groups of 32 rows
    const int warp_n = wid >> 2;  // 2 groups of 64 cols
    const int m0 = blockIdx.y * 128, n0 = blockIdx.x * 128;
    const int g  = lane >> 2;     // fragment row/col group
    const int tg = lane & 3;      // fragment k-pair index

    float acc[2][8][4];
    #pragma unroll
    for (int i = 0; i < 2; i++)
        #pragma unroll
        for (int j = 0; j < 8; j++)
            #pragma unroll
            for (int r = 0; r < 4; r++) acc[i][j][r] = 0.0f;

    for (int k0 = 0; k0 < K; k0 += 32) {
        // ---- stage A tile (128 x 32) as split bf16 pairs ----
        #pragma unroll
        for (int i = 0; i < 8; i++) {
            int idx = tid + i * 256;            // 2048 packed words
            int row = idx >> 4, kp = idx & 15;
            float2 v = make_float2(0.f, 0.f);
            if (m0 + row < M)
                v = *(const float2*)(A + (size_t)(m0 + row) * K + k0 + kp * 2);
            uint32_t hi, lo;
            split_pack(v.x, v.y, hi, lo);
            As_hi[row][kp] = hi;
            As_lo[row][kp] = lo;
        }
        // ---- stage B tile (32 x 128) transposed to [n][kp] ----
        #pragma unroll
        for (int i = 0; i < 8; i++) {
            int idx = tid + i * 256;
            int n = idx & 127, kp = idx >> 7;
            float bx = B[(size_t)(k0 + 2 * kp) * N + n0 + n];
            float by = B[(size_t)(k0 + 2 * kp + 1) * N + n0 + n];
            uint32_t hi, lo;
            split_pack(bx, by, hi, lo);
            Bs_hi[n][kp] = hi;
            Bs_lo[n][kp] = lo;
        }
        __syncthreads();

        #pragma unroll
        for (int ks = 0; ks < 2; ks++) {
            const int kb = ks * 4;             // k-pair base within 16-wide half
            // A fragments: 2 m-tiles of 16 rows
            uint32_t ah[2][4], al[2][4];
            #pragma unroll
            for (int mt = 0; mt < 2; mt++) {
                int r0 = warp_m * 32 + mt * 16;
                ah[mt][0] = As_hi[r0 + g    ][kb + tg];
                ah[mt][1] = As_hi[r0 + g + 8][kb + tg];
                ah[mt][2] = As_hi[r0 + g    ][kb + tg + 8];
                ah[mt][3] = As_hi[r0 + g + 8][kb + tg + 8];
                al[mt][0] = As_lo[r0 + g    ][kb + tg];
                al[mt][1] = As_lo[r0 + g + 8][kb + tg];
                al[mt][2] = As_lo[r0 + g    ][kb + tg + 8];
                al[mt][3] = As_lo[r0 + g + 8][kb + tg + 8];
            }
            #pragma unroll
            for (int nt = 0; nt < 8; nt++) {
                int col = warp_n * 64 + nt * 8 + g;
                uint32_t bh[2], blr[2];
                bh[0]  = Bs_hi[col][kb + tg];
                bh[1]  = Bs_hi[col][kb + tg + 8];
                blr[0] = Bs_lo[col][kb + tg];
                blr[1] = Bs_lo[col][kb + tg + 8];
                #pragma unroll
                for (int mt = 0; mt < 2; mt++) {
                    float* c = acc[mt][nt];
                    mma16816(c, ah[mt], bh);
                    mma16816(c, ah[mt], blr);
                    mma16816(c, al[mt], bh);
                }
            }
        }
        __syncthreads();
    }

    // ---- epilogue ----
    #pragma unroll
    for (int mt = 0; mt < 2; mt++) {
        int row = m0 + warp_m * 32 + mt * 16 + (lane >> 2);
        #pragma unroll
        for (int nt = 0; nt < 8; nt++) {
            int col = n0 + warp_n * 64 + nt * 8 + (lane & 3) * 2;
            float2 bb = *(const float2*)(bias + col);
            #pragma unroll
            for (int half = 0; half < 2; half++) {
                int r = row + half * 8;
                if (r >= M) continue;
                float v0 = acc[mt][nt][2 * half]     + bb.x;
                float v1 = acc[mt][nt][2 * half + 1] + bb.y;
                if (GELU) {
                    float u = v0;
                    v0 = 0.5f * u * (1.0f + tanhf(0.7978845608028654f * (u + 0.044715f * u * u * u)));
                    u = v1;
                    v1 = 0.5f * u * (1.0f + tanhf(0.7978845608028654f * (u + 0.044715f * u * u * u)));
                }
                float2* dst = (float2*)(C + (size_t)r * N + col);
                if (ACCUM) {
                    float2 old = *dst;
                    v0 += old.x; v1 += old.y;
                }
                *dst = make_float2(v0, v1);
            }
        }
    }
}

// ------------------------- clear per-layer accumulators ----------------------
__global__ void clear_kernel(int N) {
    int i = blockIdx.x * blockDim.x + threadIdx.x;
    if (i < 2 * N) { g_smax[i] = 0u; g_denom[i] = 0.0f; }
    if (i < N * HD) g_gout[i] = 0.0f;
}

// ------------------------- edge scores + segment max -------------------------
__global__ void score_kernel(const float* __restrict__ xl, const float* __restrict__ xr,
                             const float* __restrict__ att, int E) {
    int e = (blockIdx.x * blockDim.x + threadIdx.x) >> 5;
    int lane = threadIdx.x & 31;
    if (e >= E) return;
    int s = g_src[e], d = g_dst[e];
    const float4* xls = (const float4*)xl + (size_t)s * 64;
    const float4* xrd = (const float4*)xr + (size_t)d * 64;
    const float4* at4 = (const float4*)att;
    float sc[2];
    #pragma unroll
    for (int h = 0; h < 2; h++) {
        float4 l = xls[h * 32 + lane];
        float4 r = xrd[h * 32 + lane];
        float4 a = at4[h * 32 + lane];
        float4 v;
        v.x = l.x + r.x; v.x = v.x > 0.f ? v.x : 0.2f * v.x;
        v.y = l.y + r.y; v.y = v.y > 0.f ? v.y : 0.2f * v.y;
        v.z = l.z + r.z; v.z = v.z > 0.f ? v.z : 0.2f * v.z;
        v.w = l.w + r.w; v.w = v.w > 0.f ? v.w : 0.2f * v.w;
        float p = v.x * a.x + v.y * a.y + v.z * a.z + v.w * a.w;
        #pragma unroll
        for (int o = 16; o; o >>= 1) p += __shfl_xor_sync(0xffffffffu, p, o);
        sc[h] = p;
    }
    if (lane == 0) {
        g_score[2 * (size_t)e]     = sc[0];
        g_score[2 * (size_t)e + 1] = sc[1];
        atomicMax(&g_smax[2 * d],     fenc(sc[0]));
        atomicMax(&g_smax[2 * d + 1], fenc(sc[1]));
    }
}

// ------------------------- exp + segment sum ---------------------------------
__global__ void exp_kernel(int E2) {
    int i = blockIdx.x * blockDim.x + threadIdx.x;
    if (i >= E2) return;
    int e = i >> 1, h = i & 1;
    int d = g_dst[e];
    float sm = fdec(g_smax[2 * d + h]);
    float ex = expf(g_score[i] - sm);
    g_score[i] = ex;
    atomicAdd(&g_denom[2 * d + h], ex);
}

// ------------------------- weighted aggregation ------------------------------
__global__ void agg_kernel(const float* __restrict__ xl, int E) {
    int e = (blockIdx.x * blockDim.x + threadIdx.x) >> 5;
    int lane = threadIdx.x & 31;
    if (e >= E) return;
    int s = g_src[e], d = g_dst[e];
    float a0 = g_score[2 * (size_t)e]     / (g_denom[2 * d]     + 1e-16f);
    float a1 = g_score[2 * (size_t)e + 1] / (g_denom[2 * d + 1] + 1e-16f);
    const float4* xls = (const float4*)xl + (size_t)s * 64;
    float4 v0 = xls[lane];
    float4 v1 = xls[32 + lane];
    float* p0 = g_gout + (size_t)d * HD + lane * 4;
    atomicAdd((float4*)p0,         make_float4(a0 * v0.x, a0 * v0.y, a0 * v0.z, a0 * v0.w));
    atomicAdd((float4*)(p0 + 128), make_float4(a1 * v1.x, a1 * v1.y, a1 * v1.z, a1 * v1.w));
}

// ------------------------- add gat bias --------------------------------------
__global__ void addbias_kernel(const float* __restrict__ gat_b, int total) {
    int i = blockIdx.x * blockDim.x + threadIdx.x;
    if (i >= total) return;
    g_gout[i] += gat_b[i & (HD - 1)];
}

// ------------------------- launch --------------------------------------------
extern "C" void kernel_launch(void* const* d_in, const int* in_sizes, int n_in,
                              void* d_out, int out_size) {
    const float* x_in   = (const float*)d_in[0];
    const void*  edges  = d_in[1];
    const float* ln1_g  = (const float*)d_in[2];
    const float* ln1_b  = (const float*)d_in[3];
    const float* Wl     = (const float*)d_in[4];
    const float* bl     = (const float*)d_in[5];
    const float* Wr     = (const float*)d_in[6];
    const float* br     = (const float*)d_in[7];
    const float* att    = (const float*)d_in[8];
    const float* gat_b  = (const float*)d_in[9];
    const float* projW  = (const float*)d_in[10];
    const float* projb  = (const float*)d_in[11];
    const float* ln2_g  = (const float*)d_in[12];
    const float* ln2_b  = (const float*)d_in[13];
    const float* W1     = (const float*)d_in[14];
    const float* b1     = (const float*)d_in[15];
    const float* W2     = (const float*)d_in[16];
    const float* b2     = (const float*)d_in[17];

    const int N = in_sizes[0] / DIM;
    const int E = in_sizes[1] / 2;
    float* x = (float*)d_out;

    void *p_h, *p_xl, *p_xr, *p_gout, *p_mid;
    cudaGetSymbolAddress(&p_h, g_h);
    cudaGetSymbolAddress(&p_xl, g_xl);
    cudaGetSymbolAddress(&p_xr, g_xr);
    cudaGetSymbolAddress(&p_gout, g_gout);
    cudaGetSymbolAddress(&p_mid, g_mid);
    float* h    = (float*)p_h;
    float* xl   = (float*)p_xl;
    float* xr   = (float*)p_xr;
    float* gout = (float*)p_gout;
    float* mid  = (float*)p_mid;

    cudaMemcpyAsync(x, x_in, (size_t)N * DIM * sizeof(float), cudaMemcpyDeviceToDevice);

    detect_kernel<<<1, 256>>>(edges, E, N);
    decode_kernel<<<(E + 255) / 256, 256>>>(edges, E);

    const int ln_blocks = (N + 7) / 8;
    const int mtiles = (N + 127) / 128;

    for (int l = 0; l < 2; l++) {
        const float* Wl_l = Wl + (size_t)l * DIM * HD;
        const float* bl_l = bl + (size_t)l * HD;
        const float* Wr_l = Wr + (size_t)l * DIM * HD;
        const float* br_l = br + (size_t)l * HD;
        const float* at_l = att + (size_t)l * HD;
        const float* gb_l = gat_b + (size_t)l * HD;
        const float* pW_l = projW + (size_t)l * HD * DIM;
        const float* pb_l = projb + (size_t)l * DIM;
        const float* W1_l = W1 + (size_t)l * DIM * MLPD;
        const float* b1_l = b1 + (size_t)l * MLPD;
        const float* W2_l = W2 + (size_t)l * MLPD * DIM;
        const float* b2_l = b2 + (size_t)l * DIM;

        // PreNorm
        ln_kernel<<<ln_blocks, 256>>>(x, ln1_g + (size_t)l * DIM, ln1_b + (size_t)l * DIM, h, N);
        // xl = h@Wl+bl, xr = h@Wr+br
        gemm_kernel<false, false><<<dim3(HD / 128, mtiles), 256>>>(h, Wl_l, bl_l, xl, N, DIM, HD);
        gemm_kernel<false, false><<<dim3(HD / 128, mtiles), 256>>>(h, Wr_l, br_l, xr, N, DIM, HD);
        // GATv2 edge phase
        clear_kernel<<<(N * HD + 255) / 256, 256>>>(N);
        score_kernel<<<(E + 7) / 8, 256>>>(xl, xr, at_l, E);
        exp_kernel<<<(2 * E + 255) / 256, 256>>>(2 * E);
        agg_kernel<<<(E + 7) / 8, 256>>>(xl, E);
        addbias_kernel<<<(N * HD + 255) / 256, 256>>>(gb_l, N * HD);
        // x += gout @ proj_W + proj_b
        gemm_kernel<true, false><<<dim3(DIM / 128, mtiles), 256>>>(gout, pW_l, pb_l, x, N, HD, DIM);
        // FFN
        ln_kernel<<<ln_blocks, 256>>>(x, ln2_g + (size_t)l * DIM, ln2_b + (size_t)l * DIM, h, N);
        gemm_kernel<false, true><<<dim3(MLPD / 128, mtiles), 256>>>(h, W1_l, b1_l, mid, N, DIM, MLPD);
        gemm_kernel<true, false><<<dim3(DIM / 128, mtiles), 256>>>(mid, W2_l, b2_l, x, N, MLPD, DIM);
    }
}

// round 4
// speedup vs baseline: 1.2677x; 1.0889x over previous
#include <cuda_runtime.h>
#include <cuda_bf16.h>
#include <math.h>
#include <stdint.h>

// ----------------------------------------------------------------------------
// GATv2 Transformer: N=50000 nodes, E=800000 edges, DIM=128, HEADS=2, DEPTH=2,
// MLP=512. GEMMs via bf16 mma.sync with 3-term fp32 error compensation,
// double-buffered smem + register prefetch pipeline, XOR-swizzled smem.
// ----------------------------------------------------------------------------

#define MAXN 50000
#define MAXE 800000
#define DIM 128
#define HD 256           // HEADS*DIM
#define MLPD 512

// ------------------------- scratch (device globals) -------------------------
__device__ __align__(256) float g_h   [(size_t)MAXN * DIM];
__device__ __align__(256) float g_xl  [(size_t)MAXN * HD];
__device__ __align__(256) float g_xr  [(size_t)MAXN * HD];
__device__ __align__(256) float g_gout[(size_t)MAXN * HD];
__device__ __align__(256) float g_mid [(size_t)MAXN * MLPD];
__device__ __align__(256) float g_score[(size_t)MAXE * 2];
__device__ __align__(256) unsigned g_smax[(size_t)MAXN * 2];
__device__ __align__(256) float g_denom[(size_t)MAXN * 2];
__device__ __align__(256) int g_src[MAXE];
__device__ __align__(256) int g_dst[MAXE];
__device__ int g_is64;

// ------------------------- helpers -------------------------
__device__ __forceinline__ unsigned fenc(float f) {
    unsigned u = __float_as_uint(f);
    return (u >> 31) ? ~u : (u | 0x80000000u);
}
__device__ __forceinline__ float fdec(unsigned u) {
    return (u >> 31) ? __uint_as_float(u & 0x7fffffffu) : __uint_as_float(~u);
}

// ------------------------- edge dtype detect/decode -------------------------
__global__ void detect_kernel(const void* edges, int E, int N) {
    __shared__ int bad;
    if (threadIdx.x == 0) bad = 0;
    __syncthreads();
    const long long* p = (const long long*)edges;
    int n = E < 2048 ? E : 2048;
    for (int i = threadIdx.x; i < n; i += blockDim.x) {
        long long v = p[i];
        if (v < 0 || v >= (long long)N) atomicOr(&bad, 1);
    }
    __syncthreads();
    if (threadIdx.x == 0) g_is64 = bad ? 0 : 1;
}

__global__ void decode_kernel(const void* edges, int E) {
    int i = blockIdx.x * blockDim.x + threadIdx.x;
    if (i >= E) return;
    if (g_is64) {
        const long long* p = (const long long*)edges;
        g_src[i] = (int)p[i];
        g_dst[i] = (int)p[(size_t)E + i];
    } else {
        const int* p = (const int*)edges;
        g_src[i] = p[i];
        g_dst[i] = p[(size_t)E + i];
    }
}

// ------------------------- layernorm (warp per row) -------------------------
__global__ void ln_kernel(const float* __restrict__ x, const float* __restrict__ g,
                          const float* __restrict__ b, float* __restrict__ out, int N) {
    int row = (blockIdx.x * blockDim.x + threadIdx.x) >> 5;
    int lane = threadIdx.x & 31;
    if (row >= N) return;
    const float4* xr = (const float4*)x + (size_t)row * 32;
    float4 v = xr[lane];
    float s  = v.x + v.y + v.z + v.w;
    float sq = v.x*v.x + v.y*v.y + v.z*v.z + v.w*v.w;
    #pragma unroll
    for (int o = 16; o; o >>= 1) {
        s  += __shfl_xor_sync(0xffffffffu, s,  o);
        sq += __shfl_xor_sync(0xffffffffu, sq, o);
    }
    float m   = s * (1.0f / 128.0f);
    float var = sq * (1.0f / 128.0f) - m * m;
    float inv = rsqrtf(var + 1e-5f);
    float4 gg = ((const float4*)g)[lane];
    float4 bb = ((const float4*)b)[lane];
    float4 o4;
    o4.x = (v.x - m) * inv * gg.x + bb.x;
    o4.y = (v.y - m) * inv * gg.y + bb.y;
    o4.z = (v.z - m) * inv * gg.z + bb.z;
    o4.w = (v.w - m) * inv * gg.w + bb.w;
    ((float4*)out + (size_t)row * 32)[lane] = o4;
}

// ------------------------- tensor-core GEMM --------------------------------
// C = A[M,K] @ B[K,N] + bias (+C, optional GELU). K%32==0, N%128==0.
// bf16 split: a = a_hi + a_lo; computes hi*hi + hi*lo + lo*hi in fp32 accum.

__device__ __forceinline__ void mma16816(float* c, const uint32_t* a, const uint32_t* b) {
    asm volatile(
        "mma.sync.aligned.m16n8k16.row.col.f32.bf16.bf16.f32 "
        "{%0,%1,%2,%3}, {%4,%5,%6,%7}, {%8,%9}, {%0,%1,%2,%3};"
        : "+f"(c[0]), "+f"(c[1]), "+f"(c[2]), "+f"(c[3])
        : "r"(a[0]), "r"(a[1]), "r"(a[2]), "r"(a[3]), "r"(b[0]), "r"(b[1]));
}

__device__ __forceinline__ void split_pack(float x, float y, uint32_t& hi, uint32_t& lo) {
    __nv_bfloat16 hx = __float2bfloat16_rn(x);
    __nv_bfloat16 hy = __float2bfloat16_rn(y);
    __nv_bfloat16 lx = __float2bfloat16_rn(x - __bfloat162float(hx));
    __nv_bfloat16 ly = __float2bfloat16_rn(y - __bfloat162float(hy));
    hi = ((uint32_t)__bfloat16_as_ushort(hy) << 16) | (uint32_t)__bfloat16_as_ushort(hx);
    lo = ((uint32_t)__bfloat16_as_ushort(ly) << 16) | (uint32_t)__bfloat16_as_ushort(lx);
}

// XOR swizzle: word index for (row, kp). 16 words/row. Fragment loads
// (row=g 0..7 (+8), kp=kb+tg) hit all 32 banks distinct (verified per-lane).
__device__ __forceinline__ int swz(int row, int kp) {
    return (row << 4) | (kp ^ ((row & 7) << 1));
}

#define TILE_WORDS 2048           // 128 rows x 16 kp
#define BUF_WORDS  (4 * TILE_WORDS)  // Ah, Al, Bh, Bl

template<bool ACCUM, bool GELU>
__global__ __launch_bounds__(256)
void gemm_kernel(const float* __restrict__ A, const float* __restrict__ B,
                 const float* __restrict__ bias, float* __restrict__ C,
                 int M, int K, int N) {
    extern __shared__ uint32_t sm[];   // 2 * BUF_WORDS

    const int tid  = threadIdx.x;
    const int lane = tid & 31;
    const int wid  = tid >> 5;
    const int warp_m = wid & 3;   // 4 groups of 32 rows
    const int warp_n = wid >> 2;  // 2 groups of 64 cols
    const int m0 = blockIdx.y * 128, n0 = blockIdx.x * 128;
    const int g  = lane >> 2;     // fragment row/col group
    const int tg = lane & 3;      // fragment k-pair index

    float acc[2][8][4];
    #pragma unroll
    for (int i = 0; i < 2; i++)
        #pragma unroll
        for (int j = 0; j < 8; j++)
            #pragma unroll
            for (int r = 0; r < 4; r++) acc[i][j][r] = 0.0f;

    const int nk = K >> 5;        // number of 32-wide k tiles

    float2 va[8];
    float  vbx[8], vby[8];

    // ---- prefetch + stage tile 0 ----
    {
        #pragma unroll
        for (int i = 0; i < 8; i++) {
            int idx = tid + i * 256;
            int row = idx >> 4, kp = idx & 15;
            va[i] = make_float2(0.f, 0.f);
            if (m0 + row < M)
                va[i] = *(const float2*)(A + (size_t)(m0 + row) * K + kp * 2);
        }
        #pragma unroll
        for (int i = 0; i < 8; i++) {
            int idx = tid + i * 256;
            int n = idx & 127, kp = idx >> 7;
            vbx[i] = B[(size_t)(2 * kp) * N + n0 + n];
            vby[i] = B[(size_t)(2 * kp + 1) * N + n0 + n];
        }
        uint32_t* Ah = sm;
        uint32_t* Al = sm + TILE_WORDS;
        uint32_t* Bh = sm + 2 * TILE_WORDS;
        uint32_t* Bl = sm + 3 * TILE_WORDS;
        #pragma unroll
        for (int i = 0; i < 8; i++) {
            int idx = tid + i * 256;
            int row = idx >> 4, kp = idx & 15;
            uint32_t hi, lo;
            split_pack(va[i].x, va[i].y, hi, lo);
            Ah[swz(row, kp)] = hi; Al[swz(row, kp)] = lo;
        }
        #pragma unroll
        for (int i = 0; i < 8; i++) {
            int idx = tid + i * 256;
            int n = idx & 127, kp = idx >> 7;
            uint32_t hi, lo;
            split_pack(vbx[i], vby[i], hi, lo);
            Bh[swz(n, kp)] = hi; Bl[swz(n, kp)] = lo;
        }
    }

    for (int kt = 0; kt < nk; kt++) {
        __syncthreads();             // buf[kt&1] fully staged

        // ---- issue GMEM loads for tile kt+1 (latency hidden by MMAs) ----
        const bool more = (kt + 1 < nk);
        if (more) {
            int k0 = (kt + 1) << 5;
            #pragma unroll
            for (int i = 0; i < 8; i++) {
                int idx = tid + i * 256;
                int row = idx >> 4, kp = idx & 15;
                va[i] = make_float2(0.f, 0.f);
                if (m0 + row < M)
                    va[i] = *(const float2*)(A + (size_t)(m0 + row) * K + k0 + kp * 2);
            }
            #pragma unroll
            for (int i = 0; i < 8; i++) {
                int idx = tid + i * 256;
                int n = idx & 127, kp = idx >> 7;
                vbx[i] = B[(size_t)(k0 + 2 * kp) * N + n0 + n];
                vby[i] = B[(size_t)(k0 + 2 * kp + 1) * N + n0 + n];
            }
        }

        // ---- MMAs from buf[kt&1] ----
        {
            const uint32_t* Ah = sm + (kt & 1) * BUF_WORDS;
            const uint32_t* Al = Ah + TILE_WORDS;
            const uint32_t* Bh = Ah + 2 * TILE_WORDS;
            const uint32_t* Bl = Ah + 3 * TILE_WORDS;
            #pragma unroll
            for (int ks = 0; ks < 2; ks++) {
                const int kb = ks * 4;
                uint32_t ah[2][4], al[2][4];
                #pragma unroll
                for (int mt = 0; mt < 2; mt++) {
                    int r0 = warp_m * 32 + mt * 16;
                    ah[mt][0] = Ah[swz(r0 + g,     kb + tg)];
                    ah[mt][1] = Ah[swz(r0 + g + 8, kb + tg)];
                    ah[mt][2] = Ah[swz(r0 + g,     kb + tg + 8)];
                    ah[mt][3] = Ah[swz(r0 + g + 8, kb + tg + 8)];
                    al[mt][0] = Al[swz(r0 + g,     kb + tg)];
                    al[mt][1] = Al[swz(r0 + g + 8, kb + tg)];
                    al[mt][2] = Al[swz(r0 + g,     kb + tg + 8)];
                    al[mt][3] = Al[swz(r0 + g + 8, kb + tg + 8)];
                }
                #pragma unroll
                for (int nt = 0; nt < 8; nt++) {
                    int col = warp_n * 64 + nt * 8 + g;
                    uint32_t bh[2], blr[2];
                    bh[0]  = Bh[swz(col, kb + tg)];
                    bh[1]  = Bh[swz(col, kb + tg + 8)];
                    blr[0] = Bl[swz(col, kb + tg)];
                    blr[1] = Bl[swz(col, kb + tg + 8)];
                    #pragma unroll
                    for (int mt = 0; mt < 2; mt++) {
                        float* c = acc[mt][nt];
                        mma16816(c, ah[mt], bh);
                        mma16816(c, ah[mt], blr);
                        mma16816(c, al[mt], bh);
                    }
                }
            }
        }

        // ---- stage tile kt+1 into buf[(kt+1)&1] ----
        if (more) {
            uint32_t* Ah = sm + ((kt + 1) & 1) * BUF_WORDS;
            uint32_t* Al = Ah + TILE_WORDS;
            uint32_t* Bh = Ah + 2 * TILE_WORDS;
            uint32_t* Bl = Ah + 3 * TILE_WORDS;
            #pragma unroll
            for (int i = 0; i < 8; i++) {
                int idx = tid + i * 256;
                int row = idx >> 4, kp = idx & 15;
                uint32_t hi, lo;
                split_pack(va[i].x, va[i].y, hi, lo);
                Ah[swz(row, kp)] = hi; Al[swz(row, kp)] = lo;
            }
            #pragma unroll
            for (int i = 0; i < 8; i++) {
                int idx = tid + i * 256;
                int n = idx & 127, kp = idx >> 7;
                uint32_t hi, lo;
                split_pack(vbx[i], vby[i], hi, lo);
                Bh[swz(n, kp)] = hi; Bl[swz(n, kp)] = lo;
            }
        }
    }

    // ---- epilogue ----
    #pragma unroll
    for (int mt = 0; mt < 2; mt++) {
        int row = m0 + warp_m * 32 + mt * 16 + (lane >> 2);
        #pragma unroll
        for (int nt = 0; nt < 8; nt++) {
            int col = n0 + warp_n * 64 + nt * 8 + (lane & 3) * 2;
            float2 bb = *(const float2*)(bias + col);
            #pragma unroll
            for (int half = 0; half < 2; half++) {
                int r = row + half * 8;
                if (r >= M) continue;
                float v0 = acc[mt][nt][2 * half]     + bb.x;
                float v1 = acc[mt][nt][2 * half + 1] + bb.y;
                if (GELU) {
                    float u = v0;
                    v0 = 0.5f * u * (1.0f + tanhf(0.7978845608028654f * (u + 0.044715f * u * u * u)));
                    u = v1;
                    v1 = 0.5f * u * (1.0f + tanhf(0.7978845608028654f * (u + 0.044715f * u * u * u)));
                }
                float2* dst = (float2*)(C + (size_t)r * N + col);
                if (ACCUM) {
                    float2 old = *dst;
                    v0 += old.x; v1 += old.y;
                }
                *dst = make_float2(v0, v1);
            }
        }
    }
}

// ------------------------- clear per-layer accumulators ----------------------
__global__ void clear_kernel(int N) {
    int i = blockIdx.x * blockDim.x + threadIdx.x;
    if (i < 2 * N) { g_smax[i] = 0u; g_denom[i] = 0.0f; }
    if (i < N * HD) g_gout[i] = 0.0f;
}

// ------------------------- edge scores + segment max -------------------------
__global__ void score_kernel(const float* __restrict__ xl, const float* __restrict__ xr,
                             const float* __restrict__ att, int E) {
    int e = (blockIdx.x * blockDim.x + threadIdx.x) >> 5;
    int lane = threadIdx.x & 31;
    if (e >= E) return;
    int s = g_src[e], d = g_dst[e];
    const float4* xls = (const float4*)xl + (size_t)s * 64;
    const float4* xrd = (const float4*)xr + (size_t)d * 64;
    const float4* at4 = (const float4*)att;
    float sc[2];
    #pragma unroll
    for (int h = 0; h < 2; h++) {
        float4 l = xls[h * 32 + lane];
        float4 r = xrd[h * 32 + lane];
        float4 a = at4[h * 32 + lane];
        float4 v;
        v.x = l.x + r.x; v.x = v.x > 0.f ? v.x : 0.2f * v.x;
        v.y = l.y + r.y; v.y = v.y > 0.f ? v.y : 0.2f * v.y;
        v.z = l.z + r.z; v.z = v.z > 0.f ? v.z : 0.2f * v.z;
        v.w = l.w + r.w; v.w = v.w > 0.f ? v.w : 0.2f * v.w;
        float p = v.x * a.x + v.y * a.y + v.z * a.z + v.w * a.w;
        #pragma unroll
        for (int o = 16; o; o >>= 1) p += __shfl_xor_sync(0xffffffffu, p, o);
        sc[h] = p;
    }
    if (lane == 0) {
        g_score[2 * (size_t)e]     = sc[0];
        g_score[2 * (size_t)e + 1] = sc[1];
        atomicMax(&g_smax[2 * d],     fenc(sc[0]));
        atomicMax(&g_smax[2 * d + 1], fenc(sc[1]));
    }
}

// ------------------------- exp + segment sum ---------------------------------
__global__ void exp_kernel(int E2) {
    int i = blockIdx.x * blockDim.x + threadIdx.x;
    if (i >= E2) return;
    int e = i >> 1, h = i & 1;
    int d = g_dst[e];
    float sm = fdec(g_smax[2 * d + h]);
    float ex = expf(g_score[i] - sm);
    g_score[i] = ex;
    atomicAdd(&g_denom[2 * d + h], ex);
}

// ------------------------- weighted aggregation ------------------------------
__global__ void agg_kernel(const float* __restrict__ xl, int E) {
    int e = (blockIdx.x * blockDim.x + threadIdx.x) >> 5;
    int lane = threadIdx.x & 31;
    if (e >= E) return;
    int s = g_src[e], d = g_dst[e];
    float a0 = g_score[2 * (size_t)e]     / (g_denom[2 * d]     + 1e-16f);
    float a1 = g_score[2 * (size_t)e + 1] / (g_denom[2 * d + 1] + 1e-16f);
    const float4* xls = (const float4*)xl + (size_t)s * 64;
    float4 v0 = xls[lane];
    float4 v1 = xls[32 + lane];
    float* p0 = g_gout + (size_t)d * HD + lane * 4;
    atomicAdd((float4*)p0,         make_float4(a0 * v0.x, a0 * v0.y, a0 * v0.z, a0 * v0.w));
    atomicAdd((float4*)(p0 + 128), make_float4(a1 * v1.x, a1 * v1.y, a1 * v1.z, a1 * v1.w));
}

// ------------------------- add gat bias --------------------------------------
__global__ void addbias_kernel(const float* __restrict__ gat_b, int total) {
    int i = blockIdx.x * blockDim.x + threadIdx.x;
    if (i >= total) return;
    g_gout[i] += gat_b[i & (HD - 1)];
}

// ------------------------- launch --------------------------------------------
#define GEMM_SMEM (2 * BUF_WORDS * 4)   // 64 KB

extern "C" void kernel_launch(void* const* d_in, const int* in_sizes, int n_in,
                              void* d_out, int out_size) {
    const float* x_in   = (const float*)d_in[0];
    const void*  edges  = d_in[1];
    const float* ln1_g  = (const float*)d_in[2];
    const float* ln1_b  = (const float*)d_in[3];
    const float* Wl     = (const float*)d_in[4];
    const float* bl     = (const float*)d_in[5];
    const float* Wr     = (const float*)d_in[6];
    const float* br     = (const float*)d_in[7];
    const float* att    = (const float*)d_in[8];
    const float* gat_b  = (const float*)d_in[9];
    const float* projW  = (const float*)d_in[10];
    const float* projb  = (const float*)d_in[11];
    const float* ln2_g  = (const float*)d_in[12];
    const float* ln2_b  = (const float*)d_in[13];
    const float* W1     = (const float*)d_in[14];
    const float* b1     = (const float*)d_in[15];
    const float* W2     = (const float*)d_in[16];
    const float* b2     = (const float*)d_in[17];

    const int N = in_sizes[0] / DIM;
    const int E = in_sizes[1] / 2;
    float* x = (float*)d_out;

    cudaFuncSetAttribute(gemm_kernel<false, false>,
                         cudaFuncAttributeMaxDynamicSharedMemorySize, GEMM_SMEM);
    cudaFuncSetAttribute(gemm_kernel<true, false>,
                         cudaFuncAttributeMaxDynamicSharedMemorySize, GEMM_SMEM);
    cudaFuncSetAttribute(gemm_kernel<false, true>,
                         cudaFuncAttributeMaxDynamicSharedMemorySize, GEMM_SMEM);

    void *p_h, *p_xl, *p_xr, *p_gout, *p_mid;
    cudaGetSymbolAddress(&p_h, g_h);
    cudaGetSymbolAddress(&p_xl, g_xl);
    cudaGetSymbolAddress(&p_xr, g_xr);
    cudaGetSymbolAddress(&p_gout, g_gout);
    cudaGetSymbolAddress(&p_mid, g_mid);
    float* h    = (float*)p_h;
    float* xl   = (float*)p_xl;
    float* xr   = (float*)p_xr;
    float* gout = (float*)p_gout;
    float* mid  = (float*)p_mid;

    cudaMemcpyAsync(x, x_in, (size_t)N * DIM * sizeof(float), cudaMemcpyDeviceToDevice);

    detect_kernel<<<1, 256>>>(edges, E, N);
    decode_kernel<<<(E + 255) / 256, 256>>>(edges, E);

    const int ln_blocks = (N + 7) / 8;
    const int mtiles = (N + 127) / 128;

    for (int l = 0; l < 2; l++) {
        const float* Wl_l = Wl + (size_t)l * DIM * HD;
        const float* bl_l = bl + (size_t)l * HD;
        const float* Wr_l = Wr + (size_t)l * DIM * HD;
        const float* br_l = br + (size_t)l * HD;
        const float* at_l = att + (size_t)l * HD;
        const float* gb_l = gat_b + (size_t)l * HD;
        const float* pW_l = projW + (size_t)l * HD * DIM;
        const float* pb_l = projb + (size_t)l * DIM;
        const float* W1_l = W1 + (size_t)l * DIM * MLPD;
        const float* b1_l = b1 + (size_t)l * MLPD;
        const float* W2_l = W2 + (size_t)l * MLPD * DIM;
        const float* b2_l = b2 + (size_t)l * DIM;

        // PreNorm
        ln_kernel<<<ln_blocks, 256>>>(x, ln1_g + (size_t)l * DIM, ln1_b + (size_t)l * DIM, h, N);
        // xl = h@Wl+bl, xr = h@Wr+br
        gemm_kernel<false, false><<<dim3(HD / 128, mtiles), 256, GEMM_SMEM>>>(h, Wl_l, bl_l, xl, N, DIM, HD);
        gemm_kernel<false, false><<<dim3(HD / 128, mtiles), 256, GEMM_SMEM>>>(h, Wr_l, br_l, xr, N, DIM, HD);
        // GATv2 edge phase
        clear_kernel<<<(N * HD + 255) / 256, 256>>>(N);
        score_kernel<<<(E + 7) / 8, 256>>>(xl, xr, at_l, E);
        exp_kernel<<<(2 * E + 255) / 256, 256>>>(2 * E);
        agg_kernel<<<(E + 7) / 8, 256>>>(xl, E);
        addbias_kernel<<<(N * HD + 255) / 256, 256>>>(gb_l, N * HD);
        // x += gout @ proj_W + proj_b
        gemm_kernel<true, false><<<dim3(DIM / 128, mtiles), 256, GEMM_SMEM>>>(gout, pW_l, pb_l, x, N, HD, DIM);
        // FFN
        ln_kernel<<<ln_blocks, 256>>>(x, ln2_g + (size_t)l * DIM, ln2_b + (size_t)l * DIM, h, N);
        gemm_kernel<false, true><<<dim3(MLPD / 128, mtiles), 256, GEMM_SMEM>>>(h, W1_l, b1_l, mid, N, DIM, MLPD);
        gemm_kernel<true, false><<<dim3(DIM / 128, mtiles), 256, GEMM_SMEM>>>(mid, W2_l, b2_l, x, N, MLPD, DIM);
    }
}

// round 5
// speedup vs baseline: 1.5919x; 1.2557x over previous
#include <cuda_runtime.h>
#include <cuda_bf16.h>
#include <math.h>
#include <stdint.h>

// ----------------------------------------------------------------------------
// GATv2 Transformer. GEMMs: bf16 mma.sync, 3-term compensation, operands
// pre-split to bf16 hi/lo at producers, cp.async double-buffered pipeline.
// ----------------------------------------------------------------------------

#define MAXN 50000
#define MAXE 800000
#define DIM 128
#define HD 256           // HEADS*DIM
#define MLPD 512

// ------------------------- scratch (device globals) -------------------------
__device__ __align__(256) float    g_xl  [(size_t)MAXN * HD];
__device__ __align__(256) float    g_xr  [(size_t)MAXN * HD];
__device__ __align__(256) float    g_gout[(size_t)MAXN * HD];
__device__ __align__(256) uint32_t g_h_hi [(size_t)MAXN * (DIM/2)];
__device__ __align__(256) uint32_t g_h_lo [(size_t)MAXN * (DIM/2)];
__device__ __align__(256) uint32_t g_go_hi[(size_t)MAXN * (HD/2)];
__device__ __align__(256) uint32_t g_go_lo[(size_t)MAXN * (HD/2)];
__device__ __align__(256) uint32_t g_mid_hi[(size_t)MAXN * (MLPD/2)];
__device__ __align__(256) uint32_t g_mid_lo[(size_t)MAXN * (MLPD/2)];
// weights, split: per layer 114688 words (Wl 16384, Wr 16384, proj 16384, W1 32768, W2 32768)
__device__ __align__(256) uint32_t g_wb_hi[2 * 114688];
__device__ __align__(256) uint32_t g_wb_lo[2 * 114688];
__device__ __align__(256) float    g_score[(size_t)MAXE * 2];
__device__ __align__(256) unsigned g_smax[(size_t)MAXN * 2];
__device__ __align__(256) float    g_denom[(size_t)MAXN * 2];
__device__ __align__(256) int g_src[MAXE];
__device__ __align__(256) int g_dst[MAXE];
__device__ int g_is64;

// ------------------------- helpers -------------------------
__device__ __forceinline__ unsigned fenc(float f) {
    unsigned u = __float_as_uint(f);
    return (u >> 31) ? ~u : (u | 0x80000000u);
}
__device__ __forceinline__ float fdec(unsigned u) {
    return (u >> 31) ? __uint_as_float(u & 0x7fffffffu) : __uint_as_float(~u);
}
__device__ __forceinline__ void split_pack(float x, float y, uint32_t& hi, uint32_t& lo) {
    __nv_bfloat16 hx = __float2bfloat16_rn(x);
    __nv_bfloat16 hy = __float2bfloat16_rn(y);
    __nv_bfloat16 lx = __float2bfloat16_rn(x - __bfloat162float(hx));
    __nv_bfloat16 ly = __float2bfloat16_rn(y - __bfloat162float(hy));
    hi = ((uint32_t)__bfloat16_as_ushort(hy) << 16) | (uint32_t)__bfloat16_as_ushort(hx);
    lo = ((uint32_t)__bfloat16_as_ushort(ly) << 16) | (uint32_t)__bfloat16_as_ushort(lx);
}

// ------------------------- edge dtype detect/decode -------------------------
__global__ void detect_kernel(const void* edges, int E, int N) {
    __shared__ int bad;
    if (threadIdx.x == 0) bad = 0;
    __syncthreads();
    const long long* p = (const long long*)edges;
    int n = E < 2048 ? E : 2048;
    for (int i = threadIdx.x; i < n; i += blockDim.x) {
        long long v = p[i];
        if (v < 0 || v >= (long long)N) atomicOr(&bad, 1);
    }
    __syncthreads();
    if (threadIdx.x == 0) g_is64 = bad ? 0 : 1;
}

__global__ void decode_kernel(const void* edges, int E) {
    int i = blockIdx.x * blockDim.x + threadIdx.x;
    if (i >= E) return;
    if (g_is64) {
        const long long* p = (const long long*)edges;
        g_src[i] = (int)p[i];
        g_dst[i] = (int)p[(size_t)E + i];
    } else {
        const int* p = (const int*)edges;
        g_src[i] = p[i];
        g_dst[i] = p[(size_t)E + i];
    }
}

// ------------------------- weight split: W[K,N] -> hi/lo [N][K/2] ------------
__global__ void wconv_kernel(const float* __restrict__ W, uint32_t* __restrict__ hi,
                             uint32_t* __restrict__ lo, int K, int N) {
    int idx = blockIdx.x * blockDim.x + threadIdx.x;
    int kw = K >> 1;
    if (idx >= N * kw) return;
    int n = idx / kw, kp = idx - n * kw;
    float x = W[(size_t)(2 * kp) * N + n];
    float y = W[(size_t)(2 * kp + 1) * N + n];
    uint32_t h, l;
    split_pack(x, y, h, l);
    hi[idx] = h; lo[idx] = l;
}

// ------------------------- layernorm (warp/row) + split output ---------------
__global__ void ln_kernel(const float* __restrict__ x, const float* __restrict__ g,
                          const float* __restrict__ b,
                          uint32_t* __restrict__ ohi, uint32_t* __restrict__ olo, int N) {
    int row = (blockIdx.x * blockDim.x + threadIdx.x) >> 5;
    int lane = threadIdx.x & 31;
    if (row >= N) return;
    const float4* xr = (const float4*)x + (size_t)row * 32;
    float4 v = xr[lane];
    float s  = v.x + v.y + v.z + v.w;
    float sq = v.x*v.x + v.y*v.y + v.z*v.z + v.w*v.w;
    #pragma unroll
    for (int o = 16; o; o >>= 1) {
        s  += __shfl_xor_sync(0xffffffffu, s,  o);
        sq += __shfl_xor_sync(0xffffffffu, sq, o);
    }
    float m   = s * (1.0f / 128.0f);
    float var = sq * (1.0f / 128.0f) - m * m;
    float inv = rsqrtf(var + 1e-5f);
    float4 gg = ((const float4*)g)[lane];
    float4 bb = ((const float4*)b)[lane];
    float o0 = (v.x - m) * inv * gg.x + bb.x;
    float o1 = (v.y - m) * inv * gg.y + bb.y;
    float o2 = (v.z - m) * inv * gg.z + bb.z;
    float o3 = (v.w - m) * inv * gg.w + bb.w;
    uint32_t h0, l0, h1, l1;
    split_pack(o0, o1, h0, l0);
    split_pack(o2, o3, h1, l1);
    size_t base = (size_t)row * 64 + lane * 2;
    ohi[base] = h0; ohi[base + 1] = h1;
    olo[base] = l0; olo[base + 1] = l1;
}

// ------------------------- tensor-core GEMM --------------------------------
// C = A @ B + bias, operands pre-split bf16 hi/lo in [row][kp] layout.
// MODE 0: C fp32 store; 1: C fp32 accumulate; 2: GELU then split-out hi/lo.

__device__ __forceinline__ void mma16816(float* c, const uint32_t* a, const uint32_t* b) {
    asm volatile(
        "mma.sync.aligned.m16n8k16.row.col.f32.bf16.bf16.f32 "
        "{%0,%1,%2,%3}, {%4,%5,%6,%7}, {%8,%9}, {%0,%1,%2,%3};"
        : "+f"(c[0]), "+f"(c[1]), "+f"(c[2]), "+f"(c[3])
        : "r"(a[0]), "r"(a[1]), "r"(a[2]), "r"(a[3]), "r"(b[0]), "r"(b[1]));
}

__device__ __forceinline__ void cpa16(uint32_t dst, const void* src, int bytes) {
    asm volatile("cp.async.cg.shared.global [%0], [%1], 16, %2;\n"
                 :: "r"(dst), "l"(src), "r"(bytes));
}

// word index in 128x16 tile; 16B-chunk swizzle (c ^ ((row>>1)&3)).
// Fragment loads (rows g..g+7, fixed chunk) hit 32 distinct banks.
__device__ __forceinline__ int swz(int row, int kp) {
    return (row << 4) | (((kp >> 2) ^ ((row >> 1) & 3)) << 2) | (kp & 3);
}

#define TILE_WORDS 2048              // 128 rows x 16 kp
#define BUF_WORDS  (4 * TILE_WORDS)  // Ah, Al, Bh, Bl
#define GEMM_SMEM  (2 * BUF_WORDS * 4)

template<int MODE>
__global__ __launch_bounds__(256, 2)
void gemm_kernel(const uint32_t* __restrict__ Ahi, const uint32_t* __restrict__ Alo,
                 const uint32_t* __restrict__ Bhi, const uint32_t* __restrict__ Blo,
                 const float* __restrict__ bias, float* __restrict__ C,
                 uint32_t* __restrict__ Chi, uint32_t* __restrict__ Clo,
                 int M, int K, int N) {
    extern __shared__ uint32_t sm[];   // 2 * BUF_WORDS

    const int tid  = threadIdx.x;
    const int lane = tid & 31;
    const int wid  = tid >> 5;
    const int warp_m = wid & 3;
    const int warp_n = wid >> 2;
    const int m0 = blockIdx.y * 128, n0 = blockIdx.x * 128;
    const int g  = lane >> 2;
    const int tg = lane & 3;
    const int kw = K >> 1;             // words per row
    const int nk = K >> 5;             // 32-wide k tiles

    const uint32_t sbase = (uint32_t)__cvta_generic_to_shared(sm);

    float acc[2][8][4];
    #pragma unroll
    for (int i = 0; i < 2; i++)
        #pragma unroll
        for (int j = 0; j < 8; j++)
            #pragma unroll
            for (int r = 0; r < 4; r++) acc[i][j][r] = 0.0f;

    // issue cp.async for k-tile kt into buffer b
    auto issue = [&](int kt, int b) {
        uint32_t bufb = sbase + (uint32_t)(b * BUF_WORDS) * 4;
        #pragma unroll
        for (int t = 0; t < 2; t++) {
            int chunk = tid + t * 256;          // 0..511
            int row = chunk >> 2, c = chunk & 3;
            int dstw = (row << 4) | ((c ^ ((row >> 1) & 3)) << 2);
            int asz = (m0 + row < M) ? 16 : 0;
            const uint32_t* asrc = Ahi + (size_t)(m0 + row) * kw + kt * 16 + c * 4;
            const uint32_t* alsr = Alo + (size_t)(m0 + row) * kw + kt * 16 + c * 4;
            const uint32_t* bsrc = Bhi + (size_t)(n0 + row) * kw + kt * 16 + c * 4;
            const uint32_t* blsr = Blo + (size_t)(n0 + row) * kw + kt * 16 + c * 4;
            cpa16(bufb + (uint32_t)dstw * 4,                       asrc, asz);
            cpa16(bufb + (uint32_t)(TILE_WORDS + dstw) * 4,        alsr, asz);
            cpa16(bufb + (uint32_t)(2 * TILE_WORDS + dstw) * 4,    bsrc, 16);
            cpa16(bufb + (uint32_t)(3 * TILE_WORDS + dstw) * 4,    blsr, 16);
        }
        asm volatile("cp.async.commit_group;\n");
    };

    issue(0, 0);

    for (int kt = 0; kt < nk; kt++) {
        const bool more = (kt + 1 < nk);
        if (more) issue(kt + 1, (kt + 1) & 1);
        if (more) { asm volatile("cp.async.wait_group 1;\n"); }
        else      { asm volatile("cp.async.wait_group 0;\n"); }
        __syncthreads();

        const uint32_t* Ah = sm + (kt & 1) * BUF_WORDS;
        const uint32_t* Al = Ah + TILE_WORDS;
        const uint32_t* Bh = Ah + 2 * TILE_WORDS;
        const uint32_t* Bl = Ah + 3 * TILE_WORDS;
        #pragma unroll
        for (int ks = 0; ks < 2; ks++) {
            const int kb = ks * 4;
            uint32_t ah[2][4], al[2][4];
            #pragma unroll
            for (int mt = 0; mt < 2; mt++) {
                int r0 = warp_m * 32 + mt * 16;
                ah[mt][0] = Ah[swz(r0 + g,     kb + tg)];
                ah[mt][1] = Ah[swz(r0 + g + 8, kb + tg)];
                ah[mt][2] = Ah[swz(r0 + g,     kb + tg + 8)];
                ah[mt][3] = Ah[swz(r0 + g + 8, kb + tg + 8)];
                al[mt][0] = Al[swz(r0 + g,     kb + tg)];
                al[mt][1] = Al[swz(r0 + g + 8, kb + tg)];
                al[mt][2] = Al[swz(r0 + g,     kb + tg + 8)];
                al[mt][3] = Al[swz(r0 + g + 8, kb + tg + 8)];
            }
            #pragma unroll
            for (int nt = 0; nt < 8; nt++) {
                int col = warp_n * 64 + nt * 8 + g;
                uint32_t bh[2], blr[2];
                bh[0]  = Bh[swz(col, kb + tg)];
                bh[1]  = Bh[swz(col, kb + tg + 8)];
                blr[0] = Bl[swz(col, kb + tg)];
                blr[1] = Bl[swz(col, kb + tg + 8)];
                #pragma unroll
                for (int mt = 0; mt < 2; mt++) {
                    float* c = acc[mt][nt];
                    mma16816(c, ah[mt], bh);
                    mma16816(c, ah[mt], blr);
                    mma16816(c, al[mt], bh);
                }
            }
        }
        __syncthreads();
    }

    // ---- epilogue ----
    #pragma unroll
    for (int mt = 0; mt < 2; mt++) {
        int row = m0 + warp_m * 32 + mt * 16 + (lane >> 2);
        #pragma unroll
        for (int nt = 0; nt < 8; nt++) {
            int col = n0 + warp_n * 64 + nt * 8 + (lane & 3) * 2;
            float2 bb = *(const float2*)(bias + col);
            #pragma unroll
            for (int half = 0; half < 2; half++) {
                int r = row + half * 8;
                if (r >= M) continue;
                float v0 = acc[mt][nt][2 * half]     + bb.x;
                float v1 = acc[mt][nt][2 * half + 1] + bb.y;
                if (MODE == 2) {
                    float u = v0;
                    v0 = 0.5f * u * (1.0f + tanhf(0.7978845608028654f * (u + 0.044715f * u * u * u)));
                    u = v1;
                    v1 = 0.5f * u * (1.0f + tanhf(0.7978845608028654f * (u + 0.044715f * u * u * u)));
                    uint32_t h, l;
                    split_pack(v0, v1, h, l);
                    size_t w = (size_t)r * (N >> 1) + (col >> 1);
                    Chi[w] = h; Clo[w] = l;
                } else {
                    float2* dst = (float2*)(C + (size_t)r * N + col);
                    if (MODE == 1) {
                        float2 old = *dst;
                        v0 += old.x; v1 += old.y;
                    }
                    *dst = make_float2(v0, v1);
                }
            }
        }
    }
}

// ------------------------- clear per-layer accumulators ----------------------
__global__ void clear_kernel(int N) {
    int i = blockIdx.x * blockDim.x + threadIdx.x;
    if (i < 2 * N) { g_smax[i] = 0u; g_denom[i] = 0.0f; }
    if (i < N * HD) g_gout[i] = 0.0f;
}

// ------------------------- edge scores + segment max -------------------------
__global__ void score_kernel(const float* __restrict__ xl, const float* __restrict__ xr,
                             const float* __restrict__ att, int E) {
    int e = (blockIdx.x * blockDim.x + threadIdx.x) >> 5;
    int lane = threadIdx.x & 31;
    if (e >= E) return;
    int s = g_src[e], d = g_dst[e];
    const float4* xls = (const float4*)xl + (size_t)s * 64;
    const float4* xrd = (const float4*)xr + (size_t)d * 64;
    const float4* at4 = (const float4*)att;
    float sc[2];
    #pragma unroll
    for (int h = 0; h < 2; h++) {
        float4 l = xls[h * 32 + lane];
        float4 r = xrd[h * 32 + lane];
        float4 a = at4[h * 32 + lane];
        float4 v;
        v.x = l.x + r.x; v.x = v.x > 0.f ? v.x : 0.2f * v.x;
        v.y = l.y + r.y; v.y = v.y > 0.f ? v.y : 0.2f * v.y;
        v.z = l.z + r.z; v.z = v.z > 0.f ? v.z : 0.2f * v.z;
        v.w = l.w + r.w; v.w = v.w > 0.f ? v.w : 0.2f * v.w;
        float p = v.x * a.x + v.y * a.y + v.z * a.z + v.w * a.w;
        #pragma unroll
        for (int o = 16; o; o >>= 1) p += __shfl_xor_sync(0xffffffffu, p, o);
        sc[h] = p;
    }
    if (lane == 0) {
        g_score[2 * (size_t)e]     = sc[0];
        g_score[2 * (size_t)e + 1] = sc[1];
        atomicMax(&g_smax[2 * d],     fenc(sc[0]));
        atomicMax(&g_smax[2 * d + 1], fenc(sc[1]));
    }
}

// ------------------------- exp + segment sum (both heads per thread) ---------
__global__ void exp_kernel(int E) {
    int e = blockIdx.x * blockDim.x + threadIdx.x;
    if (e >= E) return;
    int d = g_dst[e];
    #pragma unroll
    for (int h = 0; h < 2; h++) {
        float sm = fdec(g_smax[2 * d + h]);
        float ex = expf(g_score[2 * (size_t)e + h] - sm);
        g_score[2 * (size_t)e + h] = ex;
        atomicAdd(&g_denom[2 * d + h], ex);
    }
}

// ------------------------- weighted aggregation ------------------------------
__global__ void agg_kernel(const float* __restrict__ xl, int E) {
    int e = (blockIdx.x * blockDim.x + threadIdx.x) >> 5;
    int lane = threadIdx.x & 31;
    if (e >= E) return;
    int s = g_src[e], d = g_dst[e];
    float a0 = g_score[2 * (size_t)e]     / (g_denom[2 * d]     + 1e-16f);
    float a1 = g_score[2 * (size_t)e + 1] / (g_denom[2 * d + 1] + 1e-16f);
    const float4* xls = (const float4*)xl + (size_t)s * 64;
    float4 v0 = xls[lane];
    float4 v1 = xls[32 + lane];
    float* p0 = g_gout + (size_t)d * HD + lane * 4;
    atomicAdd((float4*)p0,         make_float4(a0 * v0.x, a0 * v0.y, a0 * v0.z, a0 * v0.w));
    atomicAdd((float4*)(p0 + 128), make_float4(a1 * v1.x, a1 * v1.y, a1 * v1.z, a1 * v1.w));
}

// ------------------------- add gat bias + split ------------------------------
__global__ void addbias_kernel(const float* __restrict__ gat_b, int pairs) {
    int i = blockIdx.x * blockDim.x + threadIdx.x;
    if (i >= pairs) return;
    int e0 = 2 * i;
    float v0 = g_gout[e0]     + gat_b[e0 & (HD - 1)];
    float v1 = g_gout[e0 + 1] + gat_b[(e0 + 1) & (HD - 1)];
    uint32_t h, l;
    split_pack(v0, v1, h, l);
    g_go_hi[i] = h; g_go_lo[i] = l;
}

// ------------------------- launch --------------------------------------------
extern "C" void kernel_launch(void* const* d_in, const int* in_sizes, int n_in,
                              void* d_out, int out_size) {
    const float* x_in   = (const float*)d_in[0];
    const void*  edges  = d_in[1];
    const float* ln1_g  = (const float*)d_in[2];
    const float* ln1_b  = (const float*)d_in[3];
    const float* Wl     = (const float*)d_in[4];
    const float* bl     = (const float*)d_in[5];
    const float* Wr     = (const float*)d_in[6];
    const float* br     = (const float*)d_in[7];
    const float* att    = (const float*)d_in[8];
    const float* gat_b  = (const float*)d_in[9];
    const float* projW  = (const float*)d_in[10];
    const float* projb  = (const float*)d_in[11];
    const float* ln2_g  = (const float*)d_in[12];
    const float* ln2_b  = (const float*)d_in[13];
    const float* W1     = (const float*)d_in[14];
    const float* b1     = (const float*)d_in[15];
    const float* W2     = (const float*)d_in[16];
    const float* b2     = (const float*)d_in[17];

    const int N = in_sizes[0] / DIM;
    const int E = in_sizes[1] / 2;
    float* x = (float*)d_out;

    cudaFuncSetAttribute(gemm_kernel<0>, cudaFuncAttributeMaxDynamicSharedMemorySize, GEMM_SMEM);
    cudaFuncSetAttribute(gemm_kernel<1>, cudaFuncAttributeMaxDynamicSharedMemorySize, GEMM_SMEM);
    cudaFuncSetAttribute(gemm_kernel<2>, cudaFuncAttributeMaxDynamicSharedMemorySize, GEMM_SMEM);

    void *p_xl, *p_xr, *p_gout, *p_hhi, *p_hlo, *p_gohi, *p_golo, *p_mhi, *p_mlo, *p_wbhi, *p_wblo;
    cudaGetSymbolAddress(&p_xl, g_xl);
    cudaGetSymbolAddress(&p_xr, g_xr);
    cudaGetSymbolAddress(&p_gout, g_gout);
    cudaGetSymbolAddress(&p_hhi, g_h_hi);
    cudaGetSymbolAddress(&p_hlo, g_h_lo);
    cudaGetSymbolAddress(&p_gohi, g_go_hi);
    cudaGetSymbolAddress(&p_golo, g_go_lo);
    cudaGetSymbolAddress(&p_mhi, g_mid_hi);
    cudaGetSymbolAddress(&p_mlo, g_mid_lo);
    cudaGetSymbolAddress(&p_wbhi, g_wb_hi);
    cudaGetSymbolAddress(&p_wblo, g_wb_lo);
    float* xl = (float*)p_xl;
    float* xr = (float*)p_xr;
    float* gout = (float*)p_gout;
    uint32_t* hhi = (uint32_t*)p_hhi;
    uint32_t* hlo = (uint32_t*)p_hlo;
    uint32_t* gohi = (uint32_t*)p_gohi;
    uint32_t* golo = (uint32_t*)p_golo;
    uint32_t* mhi = (uint32_t*)p_mhi;
    uint32_t* mlo = (uint32_t*)p_mlo;
    uint32_t* wbhi = (uint32_t*)p_wbhi;
    uint32_t* wblo = (uint32_t*)p_wblo;

    cudaMemcpyAsync(x, x_in, (size_t)N * DIM * sizeof(float), cudaMemcpyDeviceToDevice);

    detect_kernel<<<1, 256>>>(edges, E, N);
    decode_kernel<<<(E + 255) / 256, 256>>>(edges, E);

    // split all weights (both layers)
    for (int l = 0; l < 2; l++) {
        size_t off = (size_t)l * 114688;
        wconv_kernel<<<(16384 + 255) / 256, 256>>>(Wl + (size_t)l * DIM * HD, wbhi + off, wblo + off, DIM, HD);
        wconv_kernel<<<(16384 + 255) / 256, 256>>>(Wr + (size_t)l * DIM * HD, wbhi + off + 16384, wblo + off + 16384, DIM, HD);
        wconv_kernel<<<(16384 + 255) / 256, 256>>>(projW + (size_t)l * HD * DIM, wbhi + off + 32768, wblo + off + 32768, HD, DIM);
        wconv_kernel<<<(32768 + 255) / 256, 256>>>(W1 + (size_t)l * DIM * MLPD, wbhi + off + 49152, wblo + off + 49152, DIM, MLPD);
        wconv_kernel<<<(32768 + 255) / 256, 256>>>(W2 + (size_t)l * MLPD * DIM, wbhi + off + 81920, wblo + off + 81920, MLPD, DIM);
    }

    const int ln_blocks = (N + 7) / 8;
    const int mtiles = (N + 127) / 128;

    for (int l = 0; l < 2; l++) {
        size_t off = (size_t)l * 114688;
        const uint32_t* wl_hi = wbhi + off,          *wl_lo = wblo + off;
        const uint32_t* wr_hi = wbhi + off + 16384,  *wr_lo = wblo + off + 16384;
        const uint32_t* pj_hi = wbhi + off + 32768,  *pj_lo = wblo + off + 32768;
        const uint32_t* w1_hi = wbhi + off + 49152,  *w1_lo = wblo + off + 49152;
        const uint32_t* w2_hi = wbhi + off + 81920,  *w2_lo = wblo + off + 81920;
        const float* bl_l = bl + (size_t)l * HD;
        const float* br_l = br + (size_t)l * HD;
        const float* at_l = att + (size_t)l * HD;
        const float* gb_l = gat_b + (size_t)l * HD;
        const float* pb_l = projb + (size_t)l * DIM;
        const float* b1_l = b1 + (size_t)l * MLPD;
        const float* b2_l = b2 + (size_t)l * DIM;

        // PreNorm -> split h
        ln_kernel<<<ln_blocks, 256>>>(x, ln1_g + (size_t)l * DIM, ln1_b + (size_t)l * DIM, hhi, hlo, N);
        // xl = h@Wl+bl, xr = h@Wr+br
        gemm_kernel<0><<<dim3(HD / 128, mtiles), 256, GEMM_SMEM>>>(hhi, hlo, wl_hi, wl_lo, bl_l, xl, nullptr, nullptr, N, DIM, HD);
        gemm_kernel<0><<<dim3(HD / 128, mtiles), 256, GEMM_SMEM>>>(hhi, hlo, wr_hi, wr_lo, br_l, xr, nullptr, nullptr, N, DIM, HD);
        // GATv2 edge phase
        clear_kernel<<<(N * HD + 255) / 256, 256>>>(N);
        score_kernel<<<(E + 7) / 8, 256>>>(xl, xr, at_l, E);
        exp_kernel<<<(E + 255) / 256, 256>>>(E);
        agg_kernel<<<(E + 7) / 8, 256>>>(xl, E);
        addbias_kernel<<<(N * HD / 2 + 255) / 256, 256>>>(gb_l, N * HD / 2);
        // x += gout @ proj_W + proj_b
        gemm_kernel<1><<<dim3(DIM / 128, mtiles), 256, GEMM_SMEM>>>(gohi, golo, pj_hi, pj_lo, pb_l, x, nullptr, nullptr, N, HD, DIM);
        // FFN
        ln_kernel<<<ln_blocks, 256>>>(x, ln2_g + (size_t)l * DIM, ln2_b + (size_t)l * DIM, hhi, hlo, N);
        gemm_kernel<2><<<dim3(MLPD / 128, mtiles), 256, GEMM_SMEM>>>(hhi, hlo, w1_hi, w1_lo, b1_l, nullptr, mhi, mlo, N, DIM, MLPD);
        gemm_kernel<1><<<dim3(DIM / 128, mtiles), 256, GEMM_SMEM>>>(mhi, mlo, w2_hi, w2_lo, b2_l, x, nullptr, nullptr, N, MLPD, DIM);
    }
}

// round 6
// speedup vs baseline: 2.2733x; 1.4281x over previous
#include <cuda_runtime.h>
#include <cuda_bf16.h>
#include <math.h>
#include <stdint.h>

// ----------------------------------------------------------------------------
// GATv2 Transformer. GEMMs: bf16 mma.sync + 3-term compensation, pre-split
// operands, cp.async double buffer. Edge phase: CSR-by-dst + fused online-
// softmax gather (no atomics, single pass over xl[src]).
// ----------------------------------------------------------------------------

#define MAXN 50000
#define MAXE 800000
#define DIM 128
#define HD 256           // HEADS*DIM
#define MLPD 512

// ------------------------- scratch (device globals) -------------------------
__device__ __align__(256) float    g_xlr [(size_t)MAXN * 512];   // [xl | xr] per node
__device__ __align__(256) uint32_t g_h_hi [(size_t)MAXN * (DIM/2)];
__device__ __align__(256) uint32_t g_h_lo [(size_t)MAXN * (DIM/2)];
__device__ __align__(256) uint32_t g_go_hi[(size_t)MAXN * (HD/2)];
__device__ __align__(256) uint32_t g_go_lo[(size_t)MAXN * (HD/2)];
__device__ __align__(256) uint32_t g_mid_hi[(size_t)MAXN * (MLPD/2)];
__device__ __align__(256) uint32_t g_mid_lo[(size_t)MAXN * (MLPD/2)];
// split weights per layer: WlWr 32768, proj 16384, W1 32768, W2 32768 = 114688
__device__ __align__(256) uint32_t g_wb_hi[2 * 114688];
__device__ __align__(256) uint32_t g_wb_lo[2 * 114688];
__device__ __align__(256) float    g_blr[2 * 512];
// CSR
__device__ __align__(256) int g_src[MAXE];
__device__ __align__(256) int g_dst[MAXE];
__device__ __align__(256) int g_esrc[MAXE];
__device__ __align__(256) int g_deg[MAXN];
__device__ __align__(256) int g_off[MAXN + 1];
__device__ __align__(256) int g_pos[MAXN];
__device__ int g_is64;

// ------------------------- helpers -------------------------
__device__ __forceinline__ void split_pack(float x, float y, uint32_t& hi, uint32_t& lo) {
    __nv_bfloat16 hx = __float2bfloat16_rn(x);
    __nv_bfloat16 hy = __float2bfloat16_rn(y);
    __nv_bfloat16 lx = __float2bfloat16_rn(x - __bfloat162float(hx));
    __nv_bfloat16 ly = __float2bfloat16_rn(y - __bfloat162float(hy));
    hi = ((uint32_t)__bfloat16_as_ushort(hy) << 16) | (uint32_t)__bfloat16_as_ushort(hx);
    lo = ((uint32_t)__bfloat16_as_ushort(ly) << 16) | (uint32_t)__bfloat16_as_ushort(lx);
}

// ------------------------- edge dtype detect / decode+hist -------------------
__global__ void detect_kernel(const void* edges, int E, int N) {
    __shared__ int bad;
    if (threadIdx.x == 0) bad = 0;
    __syncthreads();
    const long long* p = (const long long*)edges;
    int n = E < 2048 ? E : 2048;
    for (int i = threadIdx.x; i < n; i += blockDim.x) {
        long long v = p[i];
        if (v < 0 || v >= (long long)N) atomicOr(&bad, 1);
    }
    __syncthreads();
    if (threadIdx.x == 0) g_is64 = bad ? 0 : 1;
}

__global__ void clear_deg_kernel(int N) {
    int i = blockIdx.x * blockDim.x + threadIdx.x;
    if (i < N) g_deg[i] = 0;
}

__global__ void decode_hist_kernel(const void* edges, int E) {
    int i = blockIdx.x * blockDim.x + threadIdx.x;
    if (i >= E) return;
    int s, d;
    if (g_is64) {
        const long long* p = (const long long*)edges;
        s = (int)p[i];
        d = (int)p[(size_t)E + i];
    } else {
        const int* p = (const int*)edges;
        s = p[i];
        d = p[(size_t)E + i];
    }
    g_src[i] = s;
    g_dst[i] = d;
    atomicAdd(&g_deg[d], 1);
}

// single-block chunked inclusive scan -> exclusive offsets
__global__ void scan_kernel(int N) {
    __shared__ int sm[1024];
    __shared__ int carry;
    int tid = threadIdx.x;
    if (tid == 0) { carry = 0; g_off[0] = 0; }
    __syncthreads();
    for (int base = 0; base < N; base += 1024) {
        int i = base + tid;
        int v = (i < N) ? g_deg[i] : 0;
        sm[tid] = v;
        __syncthreads();
        #pragma unroll
        for (int o = 1; o < 1024; o <<= 1) {
            int t = (tid >= o) ? sm[tid - o] : 0;
            __syncthreads();
            sm[tid] += t;
            __syncthreads();
        }
        if (i < N) g_off[i + 1] = carry + sm[tid];
        __syncthreads();
        if (tid == 0) carry += sm[1023];
        __syncthreads();
    }
}

__global__ void copypos_kernel(int N) {
    int i = blockIdx.x * blockDim.x + threadIdx.x;
    if (i < N) g_pos[i] = g_off[i];
}

__global__ void scatter_kernel(int E) {
    int i = blockIdx.x * blockDim.x + threadIdx.x;
    if (i >= E) return;
    int p = atomicAdd(&g_pos[g_dst[i]], 1);
    g_esrc[p] = g_src[i];
}

// ------------------------- weight split: W[K,N] -> hi/lo [N][K/2] ------------
__global__ void wconv_kernel(const float* __restrict__ W, uint32_t* __restrict__ hi,
                             uint32_t* __restrict__ lo, int K, int N) {
    int idx = blockIdx.x * blockDim.x + threadIdx.x;
    int kw = K >> 1;
    if (idx >= N * kw) return;
    int n = idx / kw, kp = idx - n * kw;
    float x = W[(size_t)(2 * kp) * N + n];
    float y = W[(size_t)(2 * kp + 1) * N + n];
    uint32_t h, l;
    split_pack(x, y, h, l);
    hi[idx] = h; lo[idx] = l;
}

__global__ void bconcat_kernel(const float* __restrict__ bl, const float* __restrict__ br,
                               float* __restrict__ out) {
    int i = threadIdx.x + blockIdx.x * blockDim.x;
    if (i < 256) out[i] = bl[i];
    else if (i < 512) out[i] = br[i - 256];
}

// ------------------------- layernorm (warp/row) + split output ---------------
__global__ void ln_kernel(const float* __restrict__ x, const float* __restrict__ g,
                          const float* __restrict__ b,
                          uint32_t* __restrict__ ohi, uint32_t* __restrict__ olo, int N) {
    int row = (blockIdx.x * blockDim.x + threadIdx.x) >> 5;
    int lane = threadIdx.x & 31;
    if (row >= N) return;
    const float4* xr = (const float4*)x + (size_t)row * 32;
    float4 v = xr[lane];
    float s  = v.x + v.y + v.z + v.w;
    float sq = v.x*v.x + v.y*v.y + v.z*v.z + v.w*v.w;
    #pragma unroll
    for (int o = 16; o; o >>= 1) {
        s  += __shfl_xor_sync(0xffffffffu, s,  o);
        sq += __shfl_xor_sync(0xffffffffu, sq, o);
    }
    float m   = s * (1.0f / 128.0f);
    float var = sq * (1.0f / 128.0f) - m * m;
    float inv = rsqrtf(var + 1e-5f);
    float4 gg = ((const float4*)g)[lane];
    float4 bb = ((const float4*)b)[lane];
    float o0 = (v.x - m) * inv * gg.x + bb.x;
    float o1 = (v.y - m) * inv * gg.y + bb.y;
    float o2 = (v.z - m) * inv * gg.z + bb.z;
    float o3 = (v.w - m) * inv * gg.w + bb.w;
    uint32_t h0, l0, h1, l1;
    split_pack(o0, o1, h0, l0);
    split_pack(o2, o3, h1, l1);
    size_t base = (size_t)row * 64 + lane * 2;
    ohi[base] = h0; ohi[base + 1] = h1;
    olo[base] = l0; olo[base + 1] = l1;
}

// ------------------------- tensor-core GEMM --------------------------------
__device__ __forceinline__ void mma16816(float* c, const uint32_t* a, const uint32_t* b) {
    asm volatile(
        "mma.sync.aligned.m16n8k16.row.col.f32.bf16.bf16.f32 "
        "{%0,%1,%2,%3}, {%4,%5,%6,%7}, {%8,%9}, {%0,%1,%2,%3};"
        : "+f"(c[0]), "+f"(c[1]), "+f"(c[2]), "+f"(c[3])
        : "r"(a[0]), "r"(a[1]), "r"(a[2]), "r"(a[3]), "r"(b[0]), "r"(b[1]));
}

__device__ __forceinline__ void cpa16(uint32_t dst, const void* src, int bytes) {
    asm volatile("cp.async.cg.shared.global [%0], [%1], 16, %2;\n"
                 :: "r"(dst), "l"(src), "r"(bytes));
}

__device__ __forceinline__ int swz(int row, int kp) {
    return (row << 4) | (((kp >> 2) ^ ((row >> 1) & 3)) << 2) | (kp & 3);
}

#define TILE_WORDS 2048
#define BUF_WORDS  (4 * TILE_WORDS)
#define GEMM_SMEM  (2 * BUF_WORDS * 4)

// MODE 0: store fp32; 1: accumulate fp32; 2: GELU then split hi/lo
template<int MODE>
__global__ __launch_bounds__(256, 2)
void gemm_kernel(const uint32_t* __restrict__ Ahi, const uint32_t* __restrict__ Alo,
                 const uint32_t* __restrict__ Bhi, const uint32_t* __restrict__ Blo,
                 const float* __restrict__ bias, float* __restrict__ C,
                 uint32_t* __restrict__ Chi, uint32_t* __restrict__ Clo,
                 int M, int K, int N) {
    extern __shared__ uint32_t sm[];

    const int tid  = threadIdx.x;
    const int lane = tid & 31;
    const int wid  = tid >> 5;
    const int warp_m = wid & 3;
    const int warp_n = wid >> 2;
    const int m0 = blockIdx.y * 128, n0 = blockIdx.x * 128;
    const int g  = lane >> 2;
    const int tg = lane & 3;
    const int kw = K >> 1;
    const int nk = K >> 5;

    const uint32_t sbase = (uint32_t)__cvta_generic_to_shared(sm);

    float acc[2][8][4];
    #pragma unroll
    for (int i = 0; i < 2; i++)
        #pragma unroll
        for (int j = 0; j < 8; j++)
            #pragma unroll
            for (int r = 0; r < 4; r++) acc[i][j][r] = 0.0f;

    auto issue = [&](int kt, int b) {
        uint32_t bufb = sbase + (uint32_t)(b * BUF_WORDS) * 4;
        #pragma unroll
        for (int t = 0; t < 2; t++) {
            int chunk = tid + t * 256;
            int row = chunk >> 2, c = chunk & 3;
            int dstw = (row << 4) | ((c ^ ((row >> 1) & 3)) << 2);
            int asz = (m0 + row < M) ? 16 : 0;
            const uint32_t* asrc = Ahi + (size_t)(m0 + row) * kw + kt * 16 + c * 4;
            const uint32_t* alsr = Alo + (size_t)(m0 + row) * kw + kt * 16 + c * 4;
            const uint32_t* bsrc = Bhi + (size_t)(n0 + row) * kw + kt * 16 + c * 4;
            const uint32_t* blsr = Blo + (size_t)(n0 + row) * kw + kt * 16 + c * 4;
            cpa16(bufb + (uint32_t)dstw * 4,                    asrc, asz);
            cpa16(bufb + (uint32_t)(TILE_WORDS + dstw) * 4,     alsr, asz);
            cpa16(bufb + (uint32_t)(2 * TILE_WORDS + dstw) * 4, bsrc, 16);
            cpa16(bufb + (uint32_t)(3 * TILE_WORDS + dstw) * 4, blsr, 16);
        }
        asm volatile("cp.async.commit_group;\n");
    };

    issue(0, 0);

    for (int kt = 0; kt < nk; kt++) {
        const bool more = (kt + 1 < nk);
        if (more) issue(kt + 1, (kt + 1) & 1);
        if (more) { asm volatile("cp.async.wait_group 1;\n"); }
        else      { asm volatile("cp.async.wait_group 0;\n"); }
        __syncthreads();

        const uint32_t* Ah = sm + (kt & 1) * BUF_WORDS;
        const uint32_t* Al = Ah + TILE_WORDS;
        const uint32_t* Bh = Ah + 2 * TILE_WORDS;
        const uint32_t* Bl = Ah + 3 * TILE_WORDS;
        #pragma unroll
        for (int ks = 0; ks < 2; ks++) {
            const int kb = ks * 4;
            uint32_t ah[2][4], al[2][4];
            #pragma unroll
            for (int mt = 0; mt < 2; mt++) {
                int r0 = warp_m * 32 + mt * 16;
                ah[mt][0] = Ah[swz(r0 + g,     kb + tg)];
                ah[mt][1] = Ah[swz(r0 + g + 8, kb + tg)];
                ah[mt][2] = Ah[swz(r0 + g,     kb + tg + 8)];
                ah[mt][3] = Ah[swz(r0 + g + 8, kb + tg + 8)];
                al[mt][0] = Al[swz(r0 + g,     kb + tg)];
                al[mt][1] = Al[swz(r0 + g + 8, kb + tg)];
                al[mt][2] = Al[swz(r0 + g,     kb + tg + 8)];
                al[mt][3] = Al[swz(r0 + g + 8, kb + tg + 8)];
            }
            #pragma unroll
            for (int nt = 0; nt < 8; nt++) {
                int col = warp_n * 64 + nt * 8 + g;
                uint32_t bh[2], blr[2];
                bh[0]  = Bh[swz(col, kb + tg)];
                bh[1]  = Bh[swz(col, kb + tg + 8)];
                blr[0] = Bl[swz(col, kb + tg)];
                blr[1] = Bl[swz(col, kb + tg + 8)];
                #pragma unroll
                for (int mt = 0; mt < 2; mt++) {
                    float* c = acc[mt][nt];
                    mma16816(c, ah[mt], bh);
                    mma16816(c, ah[mt], blr);
                    mma16816(c, al[mt], bh);
                }
            }
        }
        __syncthreads();
    }

    #pragma unroll
    for (int mt = 0; mt < 2; mt++) {
        int row = m0 + warp_m * 32 + mt * 16 + (lane >> 2);
        #pragma unroll
        for (int nt = 0; nt < 8; nt++) {
            int col = n0 + warp_n * 64 + nt * 8 + (lane & 3) * 2;
            float2 bb = *(const float2*)(bias + col);
            #pragma unroll
            for (int half = 0; half < 2; half++) {
                int r = row + half * 8;
                if (r >= M) continue;
                float v0 = acc[mt][nt][2 * half]     + bb.x;
                float v1 = acc[mt][nt][2 * half + 1] + bb.y;
                if (MODE == 2) {
                    float u = v0;
                    v0 = 0.5f * u * (1.0f + tanhf(0.7978845608028654f * (u + 0.044715f * u * u * u)));
                    u = v1;
                    v1 = 0.5f * u * (1.0f + tanhf(0.7978845608028654f * (u + 0.044715f * u * u * u)));
                    uint32_t h, l;
                    split_pack(v0, v1, h, l);
                    size_t w = (size_t)r * (N >> 1) + (col >> 1);
                    Chi[w] = h; Clo[w] = l;
                } else {
                    float2* dst = (float2*)(C + (size_t)r * N + col);
                    if (MODE == 1) {
                        float2 old = *dst;
                        v0 += old.x; v1 += old.y;
                    }
                    *dst = make_float2(v0, v1);
                }
            }
        }
    }
}

// ------------------- fused GATv2 node kernel (warp per dst) ------------------
// xlr layout per node: [xl(256) | xr(256)] floats. Online softmax over CSR.
__global__ void gat_node_kernel(const float* __restrict__ xlr,
                                const float* __restrict__ att,
                                const float* __restrict__ gat_b,
                                uint32_t* __restrict__ gohi, uint32_t* __restrict__ golo,
                                int N) {
    int node = (blockIdx.x * blockDim.x + threadIdx.x) >> 5;
    int lane = threadIdx.x & 31;
    if (node >= N) return;

    const float4* base = (const float4*)xlr;
    float4 r0 = base[(size_t)node * 128 + 64 + lane];   // xr head0
    float4 r1 = base[(size_t)node * 128 + 96 + lane];   // xr head1
    float4 a0 = ((const float4*)att)[lane];
    float4 a1 = ((const float4*)att)[32 + lane];

    float m0 = -1e30f, m1 = -1e30f, d0 = 0.f, d1 = 0.f;
    float4 acc0 = make_float4(0.f, 0.f, 0.f, 0.f);
    float4 acc1 = make_float4(0.f, 0.f, 0.f, 0.f);

    int beg = g_off[node], end = g_off[node + 1];
    for (int i = beg; i < end; i++) {
        int s = g_esrc[i];
        float4 l0 = base[(size_t)s * 128 + lane];
        float4 l1 = base[(size_t)s * 128 + 32 + lane];

        float4 e0, e1;
        e0.x = l0.x + r0.x; e0.x = e0.x > 0.f ? e0.x : 0.2f * e0.x;
        e0.y = l0.y + r0.y; e0.y = e0.y > 0.f ? e0.y : 0.2f * e0.y;
        e0.z = l0.z + r0.z; e0.z = e0.z > 0.f ? e0.z : 0.2f * e0.z;
        e0.w = l0.w + r0.w; e0.w = e0.w > 0.f ? e0.w : 0.2f * e0.w;
        e1.x = l1.x + r1.x; e1.x = e1.x > 0.f ? e1.x : 0.2f * e1.x;
        e1.y = l1.y + r1.y; e1.y = e1.y > 0.f ? e1.y : 0.2f * e1.y;
        e1.z = l1.z + r1.z; e1.z = e1.z > 0.f ? e1.z : 0.2f * e1.z;
        e1.w = l1.w + r1.w; e1.w = e1.w > 0.f ? e1.w : 0.2f * e1.w;
        float p0 = e0.x * a0.x + e0.y * a0.y + e0.z * a0.z + e0.w * a0.w;
        float p1 = e1.x * a1.x + e1.y * a1.y + e1.z * a1.z + e1.w * a1.w;
        #pragma unroll
        for (int o = 16; o; o >>= 1) {
            p0 += __shfl_xor_sync(0xffffffffu, p0, o);
            p1 += __shfl_xor_sync(0xffffffffu, p1, o);
        }

        // online softmax update, head 0
        float nm0 = fmaxf(m0, p0);
        float f0 = __expf(m0 - nm0);
        float w0 = __expf(p0 - nm0);
        m0 = nm0;
        d0 = d0 * f0 + w0;
        acc0.x = acc0.x * f0 + w0 * l0.x;
        acc0.y = acc0.y * f0 + w0 * l0.y;
        acc0.z = acc0.z * f0 + w0 * l0.z;
        acc0.w = acc0.w * f0 + w0 * l0.w;
        // head 1
        float nm1 = fmaxf(m1, p1);
        float f1 = __expf(m1 - nm1);
        float w1 = __expf(p1 - nm1);
        m1 = nm1;
        d1 = d1 * f1 + w1;
        acc1.x = acc1.x * f1 + w1 * l1.x;
        acc1.y = acc1.y * f1 + w1 * l1.y;
        acc1.z = acc1.z * f1 + w1 * l1.z;
        acc1.w = acc1.w * f1 + w1 * l1.w;
    }

    float inv0 = 1.0f / (d0 + 1e-16f);
    float inv1 = 1.0f / (d1 + 1e-16f);
    const float4* gb4 = (const float4*)gat_b;
    float4 b0 = gb4[lane];
    float4 b1 = gb4[32 + lane];
    float o0 = acc0.x * inv0 + b0.x, o1 = acc0.y * inv0 + b0.y;
    float o2 = acc0.z * inv0 + b0.z, o3 = acc0.w * inv0 + b0.w;
    float o4 = acc1.x * inv1 + b1.x, o5 = acc1.y * inv1 + b1.y;
    float o6 = acc1.z * inv1 + b1.z, o7 = acc1.w * inv1 + b1.w;

    uint32_t h0, l0w, h1, l1w, h2, l2w, h3, l3w;
    split_pack(o0, o1, h0, l0w);
    split_pack(o2, o3, h1, l1w);
    split_pack(o4, o5, h2, l2w);
    split_pack(o6, o7, h3, l3w);
    size_t rb = (size_t)node * 128;        // HD/2 words per row
    gohi[rb + lane * 2]       = h0;  golo[rb + lane * 2]       = l0w;
    gohi[rb + lane * 2 + 1]   = h1;  golo[rb + lane * 2 + 1]   = l1w;
    gohi[rb + 64 + lane * 2]  = h2;  golo[rb + 64 + lane * 2]  = l2w;
    gohi[rb + 64 + lane * 2 + 1] = h3; golo[rb + 64 + lane * 2 + 1] = l3w;
}

// ------------------------- launch --------------------------------------------
extern "C" void kernel_launch(void* const* d_in, const int* in_sizes, int n_in,
                              void* d_out, int out_size) {
    const float* x_in   = (const float*)d_in[0];
    const void*  edges  = d_in[1];
    const float* ln1_g  = (const float*)d_in[2];
    const float* ln1_b  = (const float*)d_in[3];
    const float* Wl     = (const float*)d_in[4];
    const float* bl     = (const float*)d_in[5];
    const float* Wr     = (const float*)d_in[6];
    const float* br     = (const float*)d_in[7];
    const float* att    = (const float*)d_in[8];
    const float* gat_b  = (const float*)d_in[9];
    const float* projW  = (const float*)d_in[10];
    const float* projb  = (const float*)d_in[11];
    const float* ln2_g  = (const float*)d_in[12];
    const float* ln2_b  = (const float*)d_in[13];
    const float* W1     = (const float*)d_in[14];
    const float* b1     = (const float*)d_in[15];
    const float* W2     = (const float*)d_in[16];
    const float* b2     = (const float*)d_in[17];

    const int N = in_sizes[0] / DIM;
    const int E = in_sizes[1] / 2;
    float* x = (float*)d_out;

    cudaFuncSetAttribute(gemm_kernel<0>, cudaFuncAttributeMaxDynamicSharedMemorySize, GEMM_SMEM);
    cudaFuncSetAttribute(gemm_kernel<1>, cudaFuncAttributeMaxDynamicSharedMemorySize, GEMM_SMEM);
    cudaFuncSetAttribute(gemm_kernel<2>, cudaFuncAttributeMaxDynamicSharedMemorySize, GEMM_SMEM);

    void *p_xlr, *p_hhi, *p_hlo, *p_gohi, *p_golo, *p_mhi, *p_mlo, *p_wbhi, *p_wblo, *p_blr;
    cudaGetSymbolAddress(&p_xlr, g_xlr);
    cudaGetSymbolAddress(&p_hhi, g_h_hi);
    cudaGetSymbolAddress(&p_hlo, g_h_lo);
    cudaGetSymbolAddress(&p_gohi, g_go_hi);
    cudaGetSymbolAddress(&p_golo, g_go_lo);
    cudaGetSymbolAddress(&p_mhi, g_mid_hi);
    cudaGetSymbolAddress(&p_mlo, g_mid_lo);
    cudaGetSymbolAddress(&p_wbhi, g_wb_hi);
    cudaGetSymbolAddress(&p_wblo, g_wb_lo);
    cudaGetSymbolAddress(&p_blr, g_blr);
    float* xlr = (float*)p_xlr;
    uint32_t* hhi = (uint32_t*)p_hhi;
    uint32_t* hlo = (uint32_t*)p_hlo;
    uint32_t* gohi = (uint32_t*)p_gohi;
    uint32_t* golo = (uint32_t*)p_golo;
    uint32_t* mhi = (uint32_t*)p_mhi;
    uint32_t* mlo = (uint32_t*)p_mlo;
    uint32_t* wbhi = (uint32_t*)p_wbhi;
    uint32_t* wblo = (uint32_t*)p_wblo;
    float* blr = (float*)p_blr;

    cudaMemcpyAsync(x, x_in, (size_t)N * DIM * sizeof(float), cudaMemcpyDeviceToDevice);

    // edges -> CSR by dst
    detect_kernel<<<1, 256>>>(edges, E, N);
    clear_deg_kernel<<<(N + 255) / 256, 256>>>(N);
    decode_hist_kernel<<<(E + 255) / 256, 256>>>(edges, E);
    scan_kernel<<<1, 1024>>>(N);
    copypos_kernel<<<(N + 255) / 256, 256>>>(N);
    scatter_kernel<<<(E + 255) / 256, 256>>>(E);

    // split weights
    for (int l = 0; l < 2; l++) {
        size_t off = (size_t)l * 114688;
        wconv_kernel<<<(16384 + 255) / 256, 256>>>(Wl + (size_t)l * DIM * HD, wbhi + off, wblo + off, DIM, HD);
        wconv_kernel<<<(16384 + 255) / 256, 256>>>(Wr + (size_t)l * DIM * HD, wbhi + off + 16384, wblo + off + 16384, DIM, HD);
        wconv_kernel<<<(16384 + 255) / 256, 256>>>(projW + (size_t)l * HD * DIM, wbhi + off + 32768, wblo + off + 32768, HD, DIM);
        wconv_kernel<<<(32768 + 255) / 256, 256>>>(W1 + (size_t)l * DIM * MLPD, wbhi + off + 49152, wblo + off + 49152, DIM, MLPD);
        wconv_kernel<<<(32768 + 255) / 256, 256>>>(W2 + (size_t)l * MLPD * DIM, wbhi + off + 81920, wblo + off + 81920, MLPD, DIM);
        bconcat_kernel<<<2, 256>>>(bl + (size_t)l * HD, br + (size_t)l * HD, blr + (size_t)l * 512);
    }

    const int ln_blocks = (N + 7) / 8;
    const int mtiles = (N + 127) / 128;

    for (int l = 0; l < 2; l++) {
        size_t off = (size_t)l * 114688;
        const uint32_t* wlr_hi = wbhi + off,         *wlr_lo = wblo + off;
        const uint32_t* pj_hi = wbhi + off + 32768,  *pj_lo = wblo + off + 32768;
        const uint32_t* w1_hi = wbhi + off + 49152,  *w1_lo = wblo + off + 49152;
        const uint32_t* w2_hi = wbhi + off + 81920,  *w2_lo = wblo + off + 81920;
        const float* at_l = att + (size_t)l * HD;
        const float* gb_l = gat_b + (size_t)l * HD;
        const float* pb_l = projb + (size_t)l * DIM;
        const float* b1_l = b1 + (size_t)l * MLPD;
        const float* b2_l = b2 + (size_t)l * DIM;

        // PreNorm -> split h
        ln_kernel<<<ln_blocks, 256>>>(x, ln1_g + (size_t)l * DIM, ln1_b + (size_t)l * DIM, hhi, hlo, N);
        // xlr = h @ [Wl|Wr] + [bl|br]  (single fused N=512 GEMM)
        gemm_kernel<0><<<dim3(4, mtiles), 256, GEMM_SMEM>>>(hhi, hlo, wlr_hi, wlr_lo, blr + (size_t)l * 512, xlr, nullptr, nullptr, N, DIM, 512);
        // fused GATv2: scores + online softmax + aggregate + bias + split
        gat_node_kernel<<<(N + 7) / 8, 256>>>(xlr, at_l, gb_l, gohi, golo, N);
        // x += gout @ proj_W + proj_b
        gemm_kernel<1><<<dim3(DIM / 128, mtiles), 256, GEMM_SMEM>>>(gohi, golo, pj_hi, pj_lo, pb_l, x, nullptr, nullptr, N, HD, DIM);
        // FFN
        ln_kernel<<<ln_blocks, 256>>>(x, ln2_g + (size_t)l * DIM, ln2_b + (size_t)l * DIM, hhi, hlo, N);
        gemm_kernel<2><<<dim3(MLPD / 128, mtiles), 256, GEMM_SMEM>>>(hhi, hlo, w1_hi, w1_lo, b1_l, nullptr, mhi, mlo, N, DIM, MLPD);
        gemm_kernel<1><<<dim3(DIM / 128, mtiles), 256, GEMM_SMEM>>>(mhi, mlo, w2_hi, w2_lo, b2_l, x, nullptr, nullptr, N, MLPD, DIM);
    }
}

// round 7
// speedup vs baseline: 2.4829x; 1.0922x over previous
#include <cuda_runtime.h>
#include <cuda_bf16.h>
#include <math.h>
#include <stdint.h>

// ----------------------------------------------------------------------------
// GATv2 Transformer. GEMMs: bf16 mma.sync + 3-term compensation, pre-split
// operands, cp.async double buffer. Edge phase: CSR-by-dst + fused online-
// softmax gather. This round: parallel 3-phase scan + fused weight-split.
// ----------------------------------------------------------------------------

#define MAXN 50000
#define MAXE 800000
#define DIM 128
#define HD 256           // HEADS*DIM
#define MLPD 512
#define LWORDS 114688    // split-weight words per layer

// ------------------------- scratch (device globals) -------------------------
__device__ __align__(256) float    g_xlr [(size_t)MAXN * 512];   // [xl | xr] per node
__device__ __align__(256) uint32_t g_h_hi [(size_t)MAXN * (DIM/2)];
__device__ __align__(256) uint32_t g_h_lo [(size_t)MAXN * (DIM/2)];
__device__ __align__(256) uint32_t g_go_hi[(size_t)MAXN * (HD/2)];
__device__ __align__(256) uint32_t g_go_lo[(size_t)MAXN * (HD/2)];
__device__ __align__(256) uint32_t g_mid_hi[(size_t)MAXN * (MLPD/2)];
__device__ __align__(256) uint32_t g_mid_lo[(size_t)MAXN * (MLPD/2)];
__device__ __align__(256) uint32_t g_wb_hi[2 * LWORDS];
__device__ __align__(256) uint32_t g_wb_lo[2 * LWORDS];
__device__ __align__(256) float    g_blr[2 * 512];
// CSR
__device__ __align__(256) int g_src[MAXE];
__device__ __align__(256) int g_dst[MAXE];
__device__ __align__(256) int g_esrc[MAXE];
__device__ __align__(256) int g_deg[MAXN];
__device__ __align__(256) int g_off[MAXN + 1];
__device__ __align__(256) int g_pos[MAXN];
__device__ __align__(256) int g_bsum[64];
__device__ __align__(256) int g_boff[64];
__device__ int g_is64;

// ------------------------- helpers -------------------------
__device__ __forceinline__ void split_pack(float x, float y, uint32_t& hi, uint32_t& lo) {
    __nv_bfloat16 hx = __float2bfloat16_rn(x);
    __nv_bfloat16 hy = __float2bfloat16_rn(y);
    __nv_bfloat16 lx = __float2bfloat16_rn(x - __bfloat162float(hx));
    __nv_bfloat16 ly = __float2bfloat16_rn(y - __bfloat162float(hy));
    hi = ((uint32_t)__bfloat16_as_ushort(hy) << 16) | (uint32_t)__bfloat16_as_ushort(hx);
    lo = ((uint32_t)__bfloat16_as_ushort(ly) << 16) | (uint32_t)__bfloat16_as_ushort(lx);
}

// ------------------------- edge dtype detect / decode+hist -------------------
__global__ void detect_kernel(const void* edges, int E, int N) {
    __shared__ int bad;
    if (threadIdx.x == 0) bad = 0;
    __syncthreads();
    const long long* p = (const long long*)edges;
    int n = E < 2048 ? E : 2048;
    for (int i = threadIdx.x; i < n; i += blockDim.x) {
        long long v = p[i];
        if (v < 0 || v >= (long long)N) atomicOr(&bad, 1);
    }
    __syncthreads();
    if (threadIdx.x == 0) g_is64 = bad ? 0 : 1;
}

__global__ void clear_deg_kernel(int N) {
    int i = blockIdx.x * blockDim.x + threadIdx.x;
    if (i < N) g_deg[i] = 0;
}

__global__ void decode_hist_kernel(const void* edges, int E) {
    int i = blockIdx.x * blockDim.x + threadIdx.x;
    if (i >= E) return;
    int s, d;
    if (g_is64) {
        const long long* p = (const long long*)edges;
        s = (int)p[i];
        d = (int)p[(size_t)E + i];
    } else {
        const int* p = (const int*)edges;
        s = p[i];
        d = p[(size_t)E + i];
    }
    g_src[i] = s;
    g_dst[i] = d;
    atomicAdd(&g_deg[d], 1);
}

// ---- 3-phase parallel scan ----
// A: per-block (1024) warp-shuffle inclusive scan; temp -> g_off[i+1], total -> g_bsum
__global__ void scanA_kernel(int N) {
    int t = threadIdx.x;
    int i = blockIdx.x * 1024 + t;
    int lane = t & 31, w = t >> 5;
    int v = (i < N) ? g_deg[i] : 0;
    int s = v;
    #pragma unroll
    for (int o = 1; o < 32; o <<= 1) {
        int u = __shfl_up_sync(0xffffffffu, s, o);
        if (lane >= o) s += u;
    }
    __shared__ int wt[32];
    if (lane == 31) wt[w] = s;
    __syncthreads();
    if (w == 0) {
        int x = wt[lane];
        #pragma unroll
        for (int o = 1; o < 32; o <<= 1) {
            int u = __shfl_up_sync(0xffffffffu, x, o);
            if (lane >= o) x += u;
        }
        wt[lane] = x;
    }
    __syncthreads();
    if (w) s += wt[w - 1];
    if (i < N) g_off[i + 1] = s;            // within-block inclusive scan (temp)
    if (t == 1023) g_bsum[blockIdx.x] = s;  // block total
}

// B: exclusive scan of block totals (nb <= 64, one warp)
__global__ void scanB_kernel(int nb) {
    int lane = threadIdx.x;
    int v0 = (lane < nb) ? g_bsum[lane] : 0;
    int v1 = (32 + lane < nb) ? g_bsum[32 + lane] : 0;
    int s0 = v0;
    #pragma unroll
    for (int o = 1; o < 32; o <<= 1) {
        int u = __shfl_up_sync(0xffffffffu, s0, o);
        if (lane >= o) s0 += u;
    }
    int tot0 = __shfl_sync(0xffffffffu, s0, 31);
    int s1 = v1;
    #pragma unroll
    for (int o = 1; o < 32; o <<= 1) {
        int u = __shfl_up_sync(0xffffffffu, s1, o);
        if (lane >= o) s1 += u;
    }
    if (lane < nb) g_boff[lane] = s0 - v0;
    if (32 + lane < nb) g_boff[32 + lane] = tot0 + s1 - v1;
}

// C: finalize offsets + positions (also writes g_off[0])
__global__ void scanC_kernel(int N) {
    int i = blockIdx.x * blockDim.x + threadIdx.x;
    if (i == 0) g_off[0] = 0;
    if (i >= N) return;
    int b = i >> 10;
    int inc = g_off[i + 1] + g_boff[b];
    g_off[i + 1] = inc;
    g_pos[i] = inc - g_deg[i];
}

__global__ void scatter_kernel(int E) {
    int i = blockIdx.x * blockDim.x + threadIdx.x;
    if (i >= E) return;
    int p = atomicAdd(&g_pos[g_dst[i]], 1);
    g_esrc[p] = g_src[i];
}

// ---------------- fused weight split (all 5 weights x 2 layers) --------------
__global__ void wconv_all_kernel(const float* __restrict__ Wl, const float* __restrict__ Wr,
                                 const float* __restrict__ pj, const float* __restrict__ W1,
                                 const float* __restrict__ W2) {
    int idx = blockIdx.x * blockDim.x + threadIdx.x;
    if (idx >= 2 * LWORDS) return;
    int layer = idx / LWORDS;
    int r = idx - layer * LWORDS;
    const float* W; int K, N;
    if (r < 16384)      { W = Wl + (size_t)layer * 32768; K = 128; N = 256; }
    else if (r < 32768) { W = Wr + (size_t)layer * 32768; r -= 16384; K = 128; N = 256; }
    else if (r < 49152) { W = pj + (size_t)layer * 32768; r -= 32768; K = 256; N = 128; }
    else if (r < 81920) { W = W1 + (size_t)layer * 65536; r -= 49152; K = 128; N = 512; }
    else                { W = W2 + (size_t)layer * 65536; r -= 81920; K = 512; N = 128; }
    int kw = K >> 1;
    int n = r / kw, kp = r - n * kw;
    float x = W[(size_t)(2 * kp) * N + n];
    float y = W[(size_t)(2 * kp + 1) * N + n];
    uint32_t h, l;
    split_pack(x, y, h, l);
    g_wb_hi[idx] = h; g_wb_lo[idx] = l;
}

__global__ void bconcat_kernel(const float* __restrict__ bl, const float* __restrict__ br) {
    int i = threadIdx.x + blockIdx.x * blockDim.x;   // 0..1023
    if (i >= 1024) return;
    int layer = i >> 9, j = i & 511;
    float v = (j < 256) ? bl[layer * HD + j] : br[layer * HD + j - 256];
    g_blr[layer * 512 + j] = v;
}

// ------------------------- layernorm (warp/row) + split output ---------------
__global__ void ln_kernel(const float* __restrict__ x, const float* __restrict__ g,
                          const float* __restrict__ b,
                          uint32_t* __restrict__ ohi, uint32_t* __restrict__ olo, int N) {
    int row = (blockIdx.x * blockDim.x + threadIdx.x) >> 5;
    int lane = threadIdx.x & 31;
    if (row >= N) return;
    const float4* xr = (const float4*)x + (size_t)row * 32;
    float4 v = xr[lane];
    float s  = v.x + v.y + v.z + v.w;
    float sq = v.x*v.x + v.y*v.y + v.z*v.z + v.w*v.w;
    #pragma unroll
    for (int o = 16; o; o >>= 1) {
        s  += __shfl_xor_sync(0xffffffffu, s,  o);
        sq += __shfl_xor_sync(0xffffffffu, sq, o);
    }
    float m   = s * (1.0f / 128.0f);
    float var = sq * (1.0f / 128.0f) - m * m;
    float inv = rsqrtf(var + 1e-5f);
    float4 gg = ((const float4*)g)[lane];
    float4 bb = ((const float4*)b)[lane];
    float o0 = (v.x - m) * inv * gg.x + bb.x;
    float o1 = (v.y - m) * inv * gg.y + bb.y;
    float o2 = (v.z - m) * inv * gg.z + bb.z;
    float o3 = (v.w - m) * inv * gg.w + bb.w;
    uint32_t h0, l0, h1, l1;
    split_pack(o0, o1, h0, l0);
    split_pack(o2, o3, h1, l1);
    size_t base = (size_t)row * 64 + lane * 2;
    ohi[base] = h0; ohi[base + 1] = h1;
    olo[base] = l0; olo[base + 1] = l1;
}

// ------------------------- tensor-core GEMM --------------------------------
__device__ __forceinline__ void mma16816(float* c, const uint32_t* a, const uint32_t* b) {
    asm volatile(
        "mma.sync.aligned.m16n8k16.row.col.f32.bf16.bf16.f32 "
        "{%0,%1,%2,%3}, {%4,%5,%6,%7}, {%8,%9}, {%0,%1,%2,%3};"
        : "+f"(c[0]), "+f"(c[1]), "+f"(c[2]), "+f"(c[3])
        : "r"(a[0]), "r"(a[1]), "r"(a[2]), "r"(a[3]), "r"(b[0]), "r"(b[1]));
}

__device__ __forceinline__ void cpa16(uint32_t dst, const void* src, int bytes) {
    asm volatile("cp.async.cg.shared.global [%0], [%1], 16, %2;\n"
                 :: "r"(dst), "l"(src), "r"(bytes));
}

__device__ __forceinline__ int swz(int row, int kp) {
    return (row << 4) | (((kp >> 2) ^ ((row >> 1) & 3)) << 2) | (kp & 3);
}

#define TILE_WORDS 2048
#define BUF_WORDS  (4 * TILE_WORDS)
#define GEMM_SMEM  (2 * BUF_WORDS * 4)

// MODE 0: store fp32; 1: accumulate fp32; 2: GELU then split hi/lo
template<int MODE>
__global__ __launch_bounds__(256, 2)
void gemm_kernel(const uint32_t* __restrict__ Ahi, const uint32_t* __restrict__ Alo,
                 const uint32_t* __restrict__ Bhi, const uint32_t* __restrict__ Blo,
                 const float* __restrict__ bias, float* __restrict__ C,
                 uint32_t* __restrict__ Chi, uint32_t* __restrict__ Clo,
                 int M, int K, int N) {
    extern __shared__ uint32_t sm[];

    const int tid  = threadIdx.x;
    const int lane = tid & 31;
    const int wid  = tid >> 5;
    const int warp_m = wid & 3;
    const int warp_n = wid >> 2;
    const int m0 = blockIdx.y * 128, n0 = blockIdx.x * 128;
    const int g  = lane >> 2;
    const int tg = lane & 3;
    const int kw = K >> 1;
    const int nk = K >> 5;

    const uint32_t sbase = (uint32_t)__cvta_generic_to_shared(sm);

    float acc[2][8][4];
    #pragma unroll
    for (int i = 0; i < 2; i++)
        #pragma unroll
        for (int j = 0; j < 8; j++)
            #pragma unroll
            for (int r = 0; r < 4; r++) acc[i][j][r] = 0.0f;

    auto issue = [&](int kt, int b) {
        uint32_t bufb = sbase + (uint32_t)(b * BUF_WORDS) * 4;
        #pragma unroll
        for (int t = 0; t < 2; t++) {
            int chunk = tid + t * 256;
            int row = chunk >> 2, c = chunk & 3;
            int dstw = (row << 4) | ((c ^ ((row >> 1) & 3)) << 2);
            int asz = (m0 + row < M) ? 16 : 0;
            const uint32_t* asrc = Ahi + (size_t)(m0 + row) * kw + kt * 16 + c * 4;
            const uint32_t* alsr = Alo + (size_t)(m0 + row) * kw + kt * 16 + c * 4;
            const uint32_t* bsrc = Bhi + (size_t)(n0 + row) * kw + kt * 16 + c * 4;
            const uint32_t* blsr = Blo + (size_t)(n0 + row) * kw + kt * 16 + c * 4;
            cpa16(bufb + (uint32_t)dstw * 4,                    asrc, asz);
            cpa16(bufb + (uint32_t)(TILE_WORDS + dstw) * 4,     alsr, asz);
            cpa16(bufb + (uint32_t)(2 * TILE_WORDS + dstw) * 4, bsrc, 16);
            cpa16(bufb + (uint32_t)(3 * TILE_WORDS + dstw) * 4, blsr, 16);
        }
        asm volatile("cp.async.commit_group;\n");
    };

    issue(0, 0);

    for (int kt = 0; kt < nk; kt++) {
        const bool more = (kt + 1 < nk);
        if (more) issue(kt + 1, (kt + 1) & 1);
        if (more) { asm volatile("cp.async.wait_group 1;\n"); }
        else      { asm volatile("cp.async.wait_group 0;\n"); }
        __syncthreads();

        const uint32_t* Ah = sm + (kt & 1) * BUF_WORDS;
        const uint32_t* Al = Ah + TILE_WORDS;
        const uint32_t* Bh = Ah + 2 * TILE_WORDS;
        const uint32_t* Bl = Ah + 3 * TILE_WORDS;
        #pragma unroll
        for (int ks = 0; ks < 2; ks++) {
            const int kb = ks * 4;
            uint32_t ah[2][4], al[2][4];
            #pragma unroll
            for (int mt = 0; mt < 2; mt++) {
                int r0 = warp_m * 32 + mt * 16;
                ah[mt][0] = Ah[swz(r0 + g,     kb + tg)];
                ah[mt][1] = Ah[swz(r0 + g + 8, kb + tg)];
                ah[mt][2] = Ah[swz(r0 + g,     kb + tg + 8)];
                ah[mt][3] = Ah[swz(r0 + g + 8, kb + tg + 8)];
                al[mt][0] = Al[swz(r0 + g,     kb + tg)];
                al[mt][1] = Al[swz(r0 + g + 8, kb + tg)];
                al[mt][2] = Al[swz(r0 + g,     kb + tg + 8)];
                al[mt][3] = Al[swz(r0 + g + 8, kb + tg + 8)];
            }
            #pragma unroll
            for (int nt = 0; nt < 8; nt++) {
                int col = warp_n * 64 + nt * 8 + g;
                uint32_t bh[2], blr[2];
                bh[0]  = Bh[swz(col, kb + tg)];
                bh[1]  = Bh[swz(col, kb + tg + 8)];
                blr[0] = Bl[swz(col, kb + tg)];
                blr[1] = Bl[swz(col, kb + tg + 8)];
                #pragma unroll
                for (int mt = 0; mt < 2; mt++) {
                    float* c = acc[mt][nt];
                    mma16816(c, ah[mt], bh);
                    mma16816(c, ah[mt], blr);
                    mma16816(c, al[mt], bh);
                }
            }
        }
        __syncthreads();
    }

    #pragma unroll
    for (int mt = 0; mt < 2; mt++) {
        int row = m0 + warp_m * 32 + mt * 16 + (lane >> 2);
        #pragma unroll
        for (int nt = 0; nt < 8; nt++) {
            int col = n0 + warp_n * 64 + nt * 8 + (lane & 3) * 2;
            float2 bb = *(const float2*)(bias + col);
            #pragma unroll
            for (int half = 0; half < 2; half++) {
                int r = row + half * 8;
                if (r >= M) continue;
                float v0 = acc[mt][nt][2 * half]     + bb.x;
                float v1 = acc[mt][nt][2 * half + 1] + bb.y;
                if (MODE == 2) {
                    float u = v0;
                    v0 = 0.5f * u * (1.0f + tanhf(0.7978845608028654f * (u + 0.044715f * u * u * u)));
                    u = v1;
                    v1 = 0.5f * u * (1.0f + tanhf(0.7978845608028654f * (u + 0.044715f * u * u * u)));
                    uint32_t h, l;
                    split_pack(v0, v1, h, l);
                    size_t w = (size_t)r * (N >> 1) + (col >> 1);
                    Chi[w] = h; Clo[w] = l;
                } else {
                    float2* dst = (float2*)(C + (size_t)r * N + col);
                    if (MODE == 1) {
                        float2 old = *dst;
                        v0 += old.x; v1 += old.y;
                    }
                    *dst = make_float2(v0, v1);
                }
            }
        }
    }
}

// ------------------- fused GATv2 node kernel (warp per dst) ------------------
__global__ void gat_node_kernel(const float* __restrict__ xlr,
                                const float* __restrict__ att,
                                const float* __restrict__ gat_b,
                                uint32_t* __restrict__ gohi, uint32_t* __restrict__ golo,
                                int N) {
    int node = (blockIdx.x * blockDim.x + threadIdx.x) >> 5;
    int lane = threadIdx.x & 31;
    if (node >= N) return;

    const float4* base = (const float4*)xlr;
    float4 r0 = base[(size_t)node * 128 + 64 + lane];
    float4 r1 = base[(size_t)node * 128 + 96 + lane];
    float4 a0 = ((const float4*)att)[lane];
    float4 a1 = ((const float4*)att)[32 + lane];

    float m0 = -1e30f, m1 = -1e30f, d0 = 0.f, d1 = 0.f;
    float4 acc0 = make_float4(0.f, 0.f, 0.f, 0.f);
    float4 acc1 = make_float4(0.f, 0.f, 0.f, 0.f);

    int beg = g_off[node], end = g_off[node + 1];
    for (int i = beg; i < end; i++) {
        int s = g_esrc[i];
        float4 l0 = base[(size_t)s * 128 + lane];
        float4 l1 = base[(size_t)s * 128 + 32 + lane];

        float4 e0, e1;
        e0.x = l0.x + r0.x; e0.x = e0.x > 0.f ? e0.x : 0.2f * e0.x;
        e0.y = l0.y + r0.y; e0.y = e0.y > 0.f ? e0.y : 0.2f * e0.y;
        e0.z = l0.z + r0.z; e0.z = e0.z > 0.f ? e0.z : 0.2f * e0.z;
        e0.w = l0.w + r0.w; e0.w = e0.w > 0.f ? e0.w : 0.2f * e0.w;
        e1.x = l1.x + r1.x; e1.x = e1.x > 0.f ? e1.x : 0.2f * e1.x;
        e1.y = l1.y + r1.y; e1.y = e1.y > 0.f ? e1.y : 0.2f * e1.y;
        e1.z = l1.z + r1.z; e1.z = e1.z > 0.f ? e1.z : 0.2f * e1.z;
        e1.w = l1.w + r1.w; e1.w = e1.w > 0.f ? e1.w : 0.2f * e1.w;
        float p0 = e0.x * a0.x + e0.y * a0.y + e0.z * a0.z + e0.w * a0.w;
        float p1 = e1.x * a1.x + e1.y * a1.y + e1.z * a1.z + e1.w * a1.w;
        #pragma unroll
        for (int o = 16; o; o >>= 1) {
            p0 += __shfl_xor_sync(0xffffffffu, p0, o);
            p1 += __shfl_xor_sync(0xffffffffu, p1, o);
        }

        float nm0 = fmaxf(m0, p0);
        float f0 = __expf(m0 - nm0);
        float w0 = __expf(p0 - nm0);
        m0 = nm0;
        d0 = d0 * f0 + w0;
        acc0.x = acc0.x * f0 + w0 * l0.x;
        acc0.y = acc0.y * f0 + w0 * l0.y;
        acc0.z = acc0.z * f0 + w0 * l0.z;
        acc0.w = acc0.w * f0 + w0 * l0.w;
        float nm1 = fmaxf(m1, p1);
        float f1 = __expf(m1 - nm1);
        float w1 = __expf(p1 - nm1);
        m1 = nm1;
        d1 = d1 * f1 + w1;
        acc1.x = acc1.x * f1 + w1 * l1.x;
        acc1.y = acc1.y * f1 + w1 * l1.y;
        acc1.z = acc1.z * f1 + w1 * l1.z;
        acc1.w = acc1.w * f1 + w1 * l1.w;
    }

    float inv0 = 1.0f / (d0 + 1e-16f);
    float inv1 = 1.0f / (d1 + 1e-16f);
    const float4* gb4 = (const float4*)gat_b;
    float4 b0 = gb4[lane];
    float4 b1 = gb4[32 + lane];
    float o0 = acc0.x * inv0 + b0.x, o1 = acc0.y * inv0 + b0.y;
    float o2 = acc0.z * inv0 + b0.z, o3 = acc0.w * inv0 + b0.w;
    float o4 = acc1.x * inv1 + b1.x, o5 = acc1.y * inv1 + b1.y;
    float o6 = acc1.z * inv1 + b1.z, o7 = acc1.w * inv1 + b1.w;

    uint32_t h0, l0w, h1, l1w, h2, l2w, h3, l3w;
    split_pack(o0, o1, h0, l0w);
    split_pack(o2, o3, h1, l1w);
    split_pack(o4, o5, h2, l2w);
    split_pack(o6, o7, h3, l3w);
    size_t rb = (size_t)node * 128;
    gohi[rb + lane * 2]          = h0;  golo[rb + lane * 2]          = l0w;
    gohi[rb + lane * 2 + 1]      = h1;  golo[rb + lane * 2 + 1]      = l1w;
    gohi[rb + 64 + lane * 2]     = h2;  golo[rb + 64 + lane * 2]     = l2w;
    gohi[rb + 64 + lane * 2 + 1] = h3;  golo[rb + 64 + lane * 2 + 1] = l3w;
}

// ------------------------- launch --------------------------------------------
extern "C" void kernel_launch(void* const* d_in, const int* in_sizes, int n_in,
                              void* d_out, int out_size) {
    const float* x_in   = (const float*)d_in[0];
    const void*  edges  = d_in[1];
    const float* ln1_g  = (const float*)d_in[2];
    const float* ln1_b  = (const float*)d_in[3];
    const float* Wl     = (const float*)d_in[4];
    const float* bl     = (const float*)d_in[5];
    const float* Wr     = (const float*)d_in[6];
    const float* br     = (const float*)d_in[7];
    const float* att    = (const float*)d_in[8];
    const float* gat_b  = (const float*)d_in[9];
    const float* projW  = (const float*)d_in[10];
    const float* projb  = (const float*)d_in[11];
    const float* ln2_g  = (const float*)d_in[12];
    const float* ln2_b  = (const float*)d_in[13];
    const float* W1     = (const float*)d_in[14];
    const float* b1     = (const float*)d_in[15];
    const float* W2     = (const float*)d_in[16];
    const float* b2     = (const float*)d_in[17];

    const int N = in_sizes[0] / DIM;
    const int E = in_sizes[1] / 2;
    float* x = (float*)d_out;

    cudaFuncSetAttribute(gemm_kernel<0>, cudaFuncAttributeMaxDynamicSharedMemorySize, GEMM_SMEM);
    cudaFuncSetAttribute(gemm_kernel<1>, cudaFuncAttributeMaxDynamicSharedMemorySize, GEMM_SMEM);
    cudaFuncSetAttribute(gemm_kernel<2>, cudaFuncAttributeMaxDynamicSharedMemorySize, GEMM_SMEM);

    void *p_xlr, *p_hhi, *p_hlo, *p_gohi, *p_golo, *p_mhi, *p_mlo, *p_wbhi, *p_wblo, *p_blr;
    cudaGetSymbolAddress(&p_xlr, g_xlr);
    cudaGetSymbolAddress(&p_hhi, g_h_hi);
    cudaGetSymbolAddress(&p_hlo, g_h_lo);
    cudaGetSymbolAddress(&p_gohi, g_go_hi);
    cudaGetSymbolAddress(&p_golo, g_go_lo);
    cudaGetSymbolAddress(&p_mhi, g_mid_hi);
    cudaGetSymbolAddress(&p_mlo, g_mid_lo);
    cudaGetSymbolAddress(&p_wbhi, g_wb_hi);
    cudaGetSymbolAddress(&p_wblo, g_wb_lo);
    cudaGetSymbolAddress(&p_blr, g_blr);
    float* xlr = (float*)p_xlr;
    uint32_t* hhi = (uint32_t*)p_hhi;
    uint32_t* hlo = (uint32_t*)p_hlo;
    uint32_t* gohi = (uint32_t*)p_gohi;
    uint32_t* golo = (uint32_t*)p_golo;
    uint32_t* mhi = (uint32_t*)p_mhi;
    uint32_t* mlo = (uint32_t*)p_mlo;
    uint32_t* wbhi = (uint32_t*)p_wbhi;
    uint32_t* wblo = (uint32_t*)p_wblo;
    float* blr = (float*)p_blr;

    cudaMemcpyAsync(x, x_in, (size_t)N * DIM * sizeof(float), cudaMemcpyDeviceToDevice);

    // edges -> CSR by dst (parallel scan)
    const int nb = (N + 1023) / 1024;
    detect_kernel<<<1, 256>>>(edges, E, N);
    clear_deg_kernel<<<(N + 255) / 256, 256>>>(N);
    decode_hist_kernel<<<(E + 255) / 256, 256>>>(edges, E);
    scanA_kernel<<<nb, 1024>>>(N);
    scanB_kernel<<<1, 32>>>(nb);
    scanC_kernel<<<(N + 255) / 256, 256>>>(N);
    scatter_kernel<<<(E + 255) / 256, 256>>>(E);

    // split all weights in one launch
    wconv_all_kernel<<<(2 * LWORDS + 255) / 256, 256>>>(Wl, Wr, projW, W1, W2);
    bconcat_kernel<<<4, 256>>>(bl, br);

    const int ln_blocks = (N + 7) / 8;
    const int mtiles = (N + 127) / 128;

    for (int l = 0; l < 2; l++) {
        size_t off = (size_t)l * LWORDS;
        const uint32_t* wlr_hi = wbhi + off,         *wlr_lo = wblo + off;
        const uint32_t* pj_hi = wbhi + off + 32768,  *pj_lo = wblo + off + 32768;
        const uint32_t* w1_hi = wbhi + off + 49152,  *w1_lo = wblo + off + 49152;
        const uint32_t* w2_hi = wbhi + off + 81920,  *w2_lo = wblo + off + 81920;
        const float* at_l = att + (size_t)l * HD;
        const float* gb_l = gat_b + (size_t)l * HD;
        const float* pb_l = projb + (size_t)l * DIM;
        const float* b1_l = b1 + (size_t)l * MLPD;
        const float* b2_l = b2 + (size_t)l * DIM;

        ln_kernel<<<ln_blocks, 256>>>(x, ln1_g + (size_t)l * DIM, ln1_b + (size_t)l * DIM, hhi, hlo, N);
        gemm_kernel<0><<<dim3(4, mtiles), 256, GEMM_SMEM>>>(hhi, hlo, wlr_hi, wlr_lo, blr + (size_t)l * 512, xlr, nullptr, nullptr, N, DIM, 512);
        gat_node_kernel<<<(N + 7) / 8, 256>>>(xlr, at_l, gb_l, gohi, golo, N);
        gemm_kernel<1><<<dim3(DIM / 128, mtiles), 256, GEMM_SMEM>>>(gohi, golo, pj_hi, pj_lo, pb_l, x, nullptr, nullptr, N, HD, DIM);
        ln_kernel<<<ln_blocks, 256>>>(x, ln2_g + (size_t)l * DIM, ln2_b + (size_t)l * DIM, hhi, hlo, N);
        gemm_kernel<2><<<dim3(MLPD / 128, mtiles), 256, GEMM_SMEM>>>(hhi, hlo, w1_hi, w1_lo, b1_l, nullptr, mhi, mlo, N, DIM, MLPD);
        gemm_kernel<1><<<dim3(DIM / 128, mtiles), 256, GEMM_SMEM>>>(mhi, mlo, w2_hi, w2_lo, b2_l, x, nullptr, nullptr, N, MLPD, DIM);
    }
}

// round 8
// speedup vs baseline: 2.5622x; 1.0320x over previous
#include <cuda_runtime.h>
#include <cuda_bf16.h>
#include <math.h>
#include <stdint.h>

// ----------------------------------------------------------------------------
// GATv2 Transformer. GEMMs: bf16 mma.sync + 3-term compensation, pre-split
// operands, cp.async double buffer, LN fused into N=128 epilogues (MODE 3).
// Edge phase: CSR-by-dst + dual-state online-softmax gather.
// ----------------------------------------------------------------------------

#define MAXN 50000
#define MAXE 800000
#define DIM 128
#define HD 256
#define MLPD 512
#define LWORDS 114688

// ------------------------- scratch (device globals) -------------------------
__device__ __align__(256) float    g_xlr [(size_t)MAXN * 512];
__device__ __align__(256) uint32_t g_h_hi [(size_t)MAXN * (DIM/2)];
__device__ __align__(256) uint32_t g_h_lo [(size_t)MAXN * (DIM/2)];
__device__ __align__(256) uint32_t g_go_hi[(size_t)MAXN * (HD/2)];
__device__ __align__(256) uint32_t g_go_lo[(size_t)MAXN * (HD/2)];
__device__ __align__(256) uint32_t g_mid_hi[(size_t)MAXN * (MLPD/2)];
__device__ __align__(256) uint32_t g_mid_lo[(size_t)MAXN * (MLPD/2)];
__device__ __align__(256) uint32_t g_wb_hi[2 * LWORDS];
__device__ __align__(256) uint32_t g_wb_lo[2 * LWORDS];
__device__ __align__(256) float    g_blr[2 * 512];
// CSR
__device__ __align__(256) int g_src[MAXE];
__device__ __align__(256) int g_dst[MAXE];
__device__ __align__(256) int g_esrc[MAXE];
__device__ __align__(256) int g_deg[MAXN];
__device__ __align__(256) int g_off[MAXN + 1];
__device__ __align__(256) int g_pos[MAXN];
__device__ __align__(256) int g_bsum[64];
__device__ __align__(256) int g_boff[64];
__device__ int g_is64;

// ------------------------- helpers -------------------------
__device__ __forceinline__ void split_pack(float x, float y, uint32_t& hi, uint32_t& lo) {
    __nv_bfloat16 hx = __float2bfloat16_rn(x);
    __nv_bfloat16 hy = __float2bfloat16_rn(y);
    __nv_bfloat16 lx = __float2bfloat16_rn(x - __bfloat162float(hx));
    __nv_bfloat16 ly = __float2bfloat16_rn(y - __bfloat162float(hy));
    hi = ((uint32_t)__bfloat16_as_ushort(hy) << 16) | (uint32_t)__bfloat16_as_ushort(hx);
    lo = ((uint32_t)__bfloat16_as_ushort(ly) << 16) | (uint32_t)__bfloat16_as_ushort(lx);
}

// ------------------------- edge dtype detect / decode+hist -------------------
__global__ void detect_kernel(const void* edges, int E, int N) {
    __shared__ int bad;
    if (threadIdx.x == 0) bad = 0;
    __syncthreads();
    const long long* p = (const long long*)edges;
    int n = E < 2048 ? E : 2048;
    for (int i = threadIdx.x; i < n; i += blockDim.x) {
        long long v = p[i];
        if (v < 0 || v >= (long long)N) atomicOr(&bad, 1);
    }
    __syncthreads();
    if (threadIdx.x == 0) g_is64 = bad ? 0 : 1;
}

__global__ void clear_deg_kernel(int N) {
    int i = blockIdx.x * blockDim.x + threadIdx.x;
    if (i < N) g_deg[i] = 0;
}

__global__ void decode_hist_kernel(const void* edges, int E) {
    int i = blockIdx.x * blockDim.x + threadIdx.x;
    if (i >= E) return;
    int s, d;
    if (g_is64) {
        const long long* p = (const long long*)edges;
        s = (int)p[i];
        d = (int)p[(size_t)E + i];
    } else {
        const int* p = (const int*)edges;
        s = p[i];
        d = p[(size_t)E + i];
    }
    g_src[i] = s;
    g_dst[i] = d;
    atomicAdd(&g_deg[d], 1);
}

// ---- 3-phase parallel scan ----
__global__ void scanA_kernel(int N) {
    int t = threadIdx.x;
    int i = blockIdx.x * 1024 + t;
    int lane = t & 31, w = t >> 5;
    int v = (i < N) ? g_deg[i] : 0;
    int s = v;
    #pragma unroll
    for (int o = 1; o < 32; o <<= 1) {
        int u = __shfl_up_sync(0xffffffffu, s, o);
        if (lane >= o) s += u;
    }
    __shared__ int wt[32];
    if (lane == 31) wt[w] = s;
    __syncthreads();
    if (w == 0) {
        int x = wt[lane];
        #pragma unroll
        for (int o = 1; o < 32; o <<= 1) {
            int u = __shfl_up_sync(0xffffffffu, x, o);
            if (lane >= o) x += u;
        }
        wt[lane] = x;
    }
    __syncthreads();
    if (w) s += wt[w - 1];
    if (i < N) g_off[i + 1] = s;
    if (t == 1023) g_bsum[blockIdx.x] = s;
}

__global__ void scanB_kernel(int nb) {
    int lane = threadIdx.x;
    int v0 = (lane < nb) ? g_bsum[lane] : 0;
    int v1 = (32 + lane < nb) ? g_bsum[32 + lane] : 0;
    int s0 = v0;
    #pragma unroll
    for (int o = 1; o < 32; o <<= 1) {
        int u = __shfl_up_sync(0xffffffffu, s0, o);
        if (lane >= o) s0 += u;
    }
    int tot0 = __shfl_sync(0xffffffffu, s0, 31);
    int s1 = v1;
    #pragma unroll
    for (int o = 1; o < 32; o <<= 1) {
        int u = __shfl_up_sync(0xffffffffu, s1, o);
        if (lane >= o) s1 += u;
    }
    if (lane < nb) g_boff[lane] = s0 - v0;
    if (32 + lane < nb) g_boff[32 + lane] = tot0 + s1 - v1;
}

__global__ void scanC_kernel(int N) {
    int i = blockIdx.x * blockDim.x + threadIdx.x;
    if (i == 0) g_off[0] = 0;
    if (i >= N) return;
    int b = i >> 10;
    int inc = g_off[i + 1] + g_boff[b];
    g_off[i + 1] = inc;
    g_pos[i] = inc - g_deg[i];
}

__global__ void scatter_kernel(int E) {
    int i = blockIdx.x * blockDim.x + threadIdx.x;
    if (i >= E) return;
    int p = atomicAdd(&g_pos[g_dst[i]], 1);
    g_esrc[p] = g_src[i];
}

// ---------------- fused weight split ----------------------------------------
__global__ void wconv_all_kernel(const float* __restrict__ Wl, const float* __restrict__ Wr,
                                 const float* __restrict__ pj, const float* __restrict__ W1,
                                 const float* __restrict__ W2) {
    int idx = blockIdx.x * blockDim.x + threadIdx.x;
    if (idx >= 2 * LWORDS) return;
    int layer = idx / LWORDS;
    int r = idx - layer * LWORDS;
    const float* W; int K, N;
    if (r < 16384)      { W = Wl + (size_t)layer * 32768; K = 128; N = 256; }
    else if (r < 32768) { W = Wr + (size_t)layer * 32768; r -= 16384; K = 128; N = 256; }
    else if (r < 49152) { W = pj + (size_t)layer * 32768; r -= 32768; K = 256; N = 128; }
    else if (r < 81920) { W = W1 + (size_t)layer * 65536; r -= 49152; K = 128; N = 512; }
    else                { W = W2 + (size_t)layer * 65536; r -= 81920; K = 512; N = 128; }
    int kw = K >> 1;
    int n = r / kw, kp = r - n * kw;
    float x = W[(size_t)(2 * kp) * N + n];
    float y = W[(size_t)(2 * kp + 1) * N + n];
    uint32_t h, l;
    split_pack(x, y, h, l);
    g_wb_hi[idx] = h; g_wb_lo[idx] = l;
}

__global__ void bconcat_kernel(const float* __restrict__ bl, const float* __restrict__ br) {
    int i = threadIdx.x + blockIdx.x * blockDim.x;
    if (i >= 1024) return;
    int layer = i >> 9, j = i & 511;
    float v = (j < 256) ? bl[layer * HD + j] : br[layer * HD + j - 256];
    g_blr[layer * 512 + j] = v;
}

// ------------------------- standalone layernorm ------------------------------
__global__ void ln_kernel(const float* __restrict__ x, const float* __restrict__ g,
                          const float* __restrict__ b,
                          uint32_t* __restrict__ ohi, uint32_t* __restrict__ olo, int N) {
    int row = (blockIdx.x * blockDim.x + threadIdx.x) >> 5;
    int lane = threadIdx.x & 31;
    if (row >= N) return;
    const float4* xr = (const float4*)x + (size_t)row * 32;
    float4 v = xr[lane];
    float s  = v.x + v.y + v.z + v.w;
    float sq = v.x*v.x + v.y*v.y + v.z*v.z + v.w*v.w;
    #pragma unroll
    for (int o = 16; o; o >>= 1) {
        s  += __shfl_xor_sync(0xffffffffu, s,  o);
        sq += __shfl_xor_sync(0xffffffffu, sq, o);
    }
    float m   = s * (1.0f / 128.0f);
    float var = sq * (1.0f / 128.0f) - m * m;
    float inv = rsqrtf(var + 1e-5f);
    float4 gg = ((const float4*)g)[lane];
    float4 bb = ((const float4*)b)[lane];
    float o0 = (v.x - m) * inv * gg.x + bb.x;
    float o1 = (v.y - m) * inv * gg.y + bb.y;
    float o2 = (v.z - m) * inv * gg.z + bb.z;
    float o3 = (v.w - m) * inv * gg.w + bb.w;
    uint32_t h0, l0, h1, l1;
    split_pack(o0, o1, h0, l0);
    split_pack(o2, o3, h1, l1);
    size_t base = (size_t)row * 64 + lane * 2;
    ohi[base] = h0; ohi[base + 1] = h1;
    olo[base] = l0; olo[base + 1] = l1;
}

// ------------------------- tensor-core GEMM --------------------------------
__device__ __forceinline__ void mma16816(float* c, const uint32_t* a, const uint32_t* b) {
    asm volatile(
        "mma.sync.aligned.m16n8k16.row.col.f32.bf16.bf16.f32 "
        "{%0,%1,%2,%3}, {%4,%5,%6,%7}, {%8,%9}, {%0,%1,%2,%3};"
        : "+f"(c[0]), "+f"(c[1]), "+f"(c[2]), "+f"(c[3])
        : "r"(a[0]), "r"(a[1]), "r"(a[2]), "r"(a[3]), "r"(b[0]), "r"(b[1]));
}

__device__ __forceinline__ void cpa16(uint32_t dst, const void* src, int bytes) {
    asm volatile("cp.async.cg.shared.global [%0], [%1], 16, %2;\n"
                 :: "r"(dst), "l"(src), "r"(bytes));
}

__device__ __forceinline__ int swz(int row, int kp) {
    return (row << 4) | (((kp >> 2) ^ ((row >> 1) & 3)) << 2) | (kp & 3);
}

#define TILE_WORDS 2048
#define BUF_WORDS  (4 * TILE_WORDS)
#define GEMM_SMEM  (2 * BUF_WORDS * 4)

// MODE 0: store fp32; 1: accumulate fp32; 2: GELU then split hi/lo;
// MODE 3: accumulate fp32 + fused LayerNorm -> writes x (C) and split h (N==128)
template<int MODE>
__global__ __launch_bounds__(256, 2)
void gemm_kernel(const uint32_t* __restrict__ Ahi, const uint32_t* __restrict__ Alo,
                 const uint32_t* __restrict__ Bhi, const uint32_t* __restrict__ Blo,
                 const float* __restrict__ bias, float* __restrict__ C,
                 uint32_t* __restrict__ Chi, uint32_t* __restrict__ Clo,
                 const float* __restrict__ lng, const float* __restrict__ lnb,
                 int M, int K, int N) {
    extern __shared__ uint32_t sm[];

    const int tid  = threadIdx.x;
    const int lane = tid & 31;
    const int wid  = tid >> 5;
    const int warp_m = wid & 3;
    const int warp_n = wid >> 2;
    const int m0 = blockIdx.y * 128, n0 = blockIdx.x * 128;
    const int g  = lane >> 2;
    const int tg = lane & 3;
    const int kw = K >> 1;
    const int nk = K >> 5;

    const uint32_t sbase = (uint32_t)__cvta_generic_to_shared(sm);

    float acc[2][8][4];
    #pragma unroll
    for (int i = 0; i < 2; i++)
        #pragma unroll
        for (int j = 0; j < 8; j++)
            #pragma unroll
            for (int r = 0; r < 4; r++) acc[i][j][r] = 0.0f;

    auto issue = [&](int kt, int b) {
        uint32_t bufb = sbase + (uint32_t)(b * BUF_WORDS) * 4;
        #pragma unroll
        for (int t = 0; t < 2; t++) {
            int chunk = tid + t * 256;
            int row = chunk >> 2, c = chunk & 3;
            int dstw = (row << 4) | ((c ^ ((row >> 1) & 3)) << 2);
            int asz = (m0 + row < M) ? 16 : 0;
            const uint32_t* asrc = Ahi + (size_t)(m0 + row) * kw + kt * 16 + c * 4;
            const uint32_t* alsr = Alo + (size_t)(m0 + row) * kw + kt * 16 + c * 4;
            const uint32_t* bsrc = Bhi + (size_t)(n0 + row) * kw + kt * 16 + c * 4;
            const uint32_t* blsr = Blo + (size_t)(n0 + row) * kw + kt * 16 + c * 4;
            cpa16(bufb + (uint32_t)dstw * 4,                    asrc, asz);
            cpa16(bufb + (uint32_t)(TILE_WORDS + dstw) * 4,     alsr, asz);
            cpa16(bufb + (uint32_t)(2 * TILE_WORDS + dstw) * 4, bsrc, 16);
            cpa16(bufb + (uint32_t)(3 * TILE_WORDS + dstw) * 4, blsr, 16);
        }
        asm volatile("cp.async.commit_group;\n");
    };

    issue(0, 0);

    for (int kt = 0; kt < nk; kt++) {
        const bool more = (kt + 1 < nk);
        if (more) issue(kt + 1, (kt + 1) & 1);
        if (more) { asm volatile("cp.async.wait_group 1;\n"); }
        else      { asm volatile("cp.async.wait_group 0;\n"); }
        __syncthreads();

        const uint32_t* Ah = sm + (kt & 1) * BUF_WORDS;
        const uint32_t* Al = Ah + TILE_WORDS;
        const uint32_t* Bh = Ah + 2 * TILE_WORDS;
        const uint32_t* Bl = Ah + 3 * TILE_WORDS;
        #pragma unroll
        for (int ks = 0; ks < 2; ks++) {
            const int kb = ks * 4;
            uint32_t ah[2][4], al[2][4];
            #pragma unroll
            for (int mt = 0; mt < 2; mt++) {
                int r0 = warp_m * 32 + mt * 16;
                ah[mt][0] = Ah[swz(r0 + g,     kb + tg)];
                ah[mt][1] = Ah[swz(r0 + g + 8, kb + tg)];
                ah[mt][2] = Ah[swz(r0 + g,     kb + tg + 8)];
                ah[mt][3] = Ah[swz(r0 + g + 8, kb + tg + 8)];
                al[mt][0] = Al[swz(r0 + g,     kb + tg)];
                al[mt][1] = Al[swz(r0 + g + 8, kb + tg)];
                al[mt][2] = Al[swz(r0 + g,     kb + tg + 8)];
                al[mt][3] = Al[swz(r0 + g + 8, kb + tg + 8)];
            }
            #pragma unroll
            for (int nt = 0; nt < 8; nt++) {
                int col = warp_n * 64 + nt * 8 + g;
                uint32_t bh[2], blr[2];
                bh[0]  = Bh[swz(col, kb + tg)];
                bh[1]  = Bh[swz(col, kb + tg + 8)];
                blr[0] = Bl[swz(col, kb + tg)];
                blr[1] = Bl[swz(col, kb + tg + 8)];
                #pragma unroll
                for (int mt = 0; mt < 2; mt++) {
                    float* c = acc[mt][nt];
                    mma16816(c, ah[mt], bh);
                    mma16816(c, ah[mt], blr);
                    mma16816(c, al[mt], bh);
                }
            }
        }
        __syncthreads();
    }

    // ---- epilogue ----
    float* rowbuf = (float*)sm;   // MODE 3: 128x128 staging (reuses pipeline smem)
    #pragma unroll
    for (int mt = 0; mt < 2; mt++) {
        int rloc = warp_m * 32 + mt * 16 + (lane >> 2);
        int row = m0 + rloc;
        #pragma unroll
        for (int nt = 0; nt < 8; nt++) {
            int col = n0 + warp_n * 64 + nt * 8 + (lane & 3) * 2;
            float2 bb = *(const float2*)(bias + col);
            #pragma unroll
            for (int half = 0; half < 2; half++) {
                int r = row + half * 8;
                if (r >= M) continue;
                float v0 = acc[mt][nt][2 * half]     + bb.x;
                float v1 = acc[mt][nt][2 * half + 1] + bb.y;
                if (MODE == 2) {
                    float u = v0;
                    v0 = 0.5f * u * (1.0f + tanhf(0.7978845608028654f * (u + 0.044715f * u * u * u)));
                    u = v1;
                    v1 = 0.5f * u * (1.0f + tanhf(0.7978845608028654f * (u + 0.044715f * u * u * u)));
                    uint32_t h, l;
                    split_pack(v0, v1, h, l);
                    size_t w = (size_t)r * (N >> 1) + (col >> 1);
                    Chi[w] = h; Clo[w] = l;
                } else if (MODE == 3) {
                    float2 old = *(float2*)(C + (size_t)r * N + col);
                    rowbuf[(rloc + half * 8) * 128 + (col - n0)]     = v0 + old.x;
                    rowbuf[(rloc + half * 8) * 128 + (col - n0) + 1] = v1 + old.y;
                } else {
                    float2* dst = (float2*)(C + (size_t)r * N + col);
                    if (MODE == 1) {
                        float2 old = *dst;
                        v0 += old.x; v1 += old.y;
                    }
                    *dst = make_float2(v0, v1);
                }
            }
        }
    }

    if (MODE == 3) {
        __syncthreads();
        float4 gg = ((const float4*)lng)[lane];
        float4 bb2 = ((const float4*)lnb)[lane];
        for (int rr = wid * 16; rr < wid * 16 + 16; rr++) {
            int r = m0 + rr;
            if (r >= M) break;
            float4 v = ((const float4*)(rowbuf + rr * 128))[lane];
            float s  = v.x + v.y + v.z + v.w;
            float sq = v.x*v.x + v.y*v.y + v.z*v.z + v.w*v.w;
            #pragma unroll
            for (int o = 16; o; o >>= 1) {
                s  += __shfl_xor_sync(0xffffffffu, s,  o);
                sq += __shfl_xor_sync(0xffffffffu, sq, o);
            }
            float m   = s * (1.0f / 128.0f);
            float var = sq * (1.0f / 128.0f) - m * m;
            float inv = rsqrtf(var + 1e-5f);
            // write updated x
            ((float4*)(C + (size_t)r * 128))[lane] = v;
            float o0 = (v.x - m) * inv * gg.x + bb2.x;
            float o1 = (v.y - m) * inv * gg.y + bb2.y;
            float o2 = (v.z - m) * inv * gg.z + bb2.z;
            float o3 = (v.w - m) * inv * gg.w + bb2.w;
            uint32_t h0, l0, h1, l1;
            split_pack(o0, o1, h0, l0);
            split_pack(o2, o3, h1, l1);
            size_t base = (size_t)r * 64 + lane * 2;
            Chi[base] = h0; Chi[base + 1] = h1;
            Clo[base] = l0; Clo[base + 1] = l1;
        }
    }
}

// ------------------- fused GATv2 node kernel (warp per dst) ------------------
// Dual independent online-softmax states (even/odd edges) merged at the end.
__global__ void gat_node_kernel(const float* __restrict__ xlr,
                                const float* __restrict__ att,
                                const float* __restrict__ gat_b,
                                uint32_t* __restrict__ gohi, uint32_t* __restrict__ golo,
                                int N) {
    int node = (blockIdx.x * blockDim.x + threadIdx.x) >> 5;
    int lane = threadIdx.x & 31;
    if (node >= N) return;

    const float4* base = (const float4*)xlr;
    float4 r0 = base[(size_t)node * 128 + 64 + lane];
    float4 r1 = base[(size_t)node * 128 + 96 + lane];
    float4 a0 = ((const float4*)att)[lane];
    float4 a1 = ((const float4*)att)[32 + lane];

    // state A and state B (independent chains)
    float mA0 = -1e30f, mA1 = -1e30f, dA0 = 0.f, dA1 = 0.f;
    float mB0 = -1e30f, mB1 = -1e30f, dB0 = 0.f, dB1 = 0.f;
    float4 aA0 = make_float4(0.f,0.f,0.f,0.f), aA1 = make_float4(0.f,0.f,0.f,0.f);
    float4 aB0 = make_float4(0.f,0.f,0.f,0.f), aB1 = make_float4(0.f,0.f,0.f,0.f);

    int beg = g_off[node], end = g_off[node + 1];

    auto process = [&](int s, float& m0, float& m1, float& d0, float& d1,
                       float4& acc0, float4& acc1) {
        float4 l0 = base[(size_t)s * 128 + lane];
        float4 l1 = base[(size_t)s * 128 + 32 + lane];
        float4 e0, e1;
        e0.x = l0.x + r0.x; e0.x = e0.x > 0.f ? e0.x : 0.2f * e0.x;
        e0.y = l0.y + r0.y; e0.y = e0.y > 0.f ? e0.y : 0.2f * e0.y;
        e0.z = l0.z + r0.z; e0.z = e0.z > 0.f ? e0.z : 0.2f * e0.z;
        e0.w = l0.w + r0.w; e0.w = e0.w > 0.f ? e0.w : 0.2f * e0.w;
        e1.x = l1.x + r1.x; e1.x = e1.x > 0.f ? e1.x : 0.2f * e1.x;
        e1.y = l1.y + r1.y; e1.y = e1.y > 0.f ? e1.y : 0.2f * e1.y;
        e1.z = l1.z + r1.z; e1.z = e1.z > 0.f ? e1.z : 0.2f * e1.z;
        e1.w = l1.w + r1.w; e1.w = e1.w > 0.f ? e1.w : 0.2f * e1.w;
        float p0 = e0.x * a0.x + e0.y * a0.y + e0.z * a0.z + e0.w * a0.w;
        float p1 = e1.x * a1.x + e1.y * a1.y + e1.z * a1.z + e1.w * a1.w;
        #pragma unroll
        for (int o = 16; o; o >>= 1) {
            p0 += __shfl_xor_sync(0xffffffffu, p0, o);
            p1 += __shfl_xor_sync(0xffffffffu, p1, o);
        }
        float nm0 = fmaxf(m0, p0);
        float f0 = __expf(m0 - nm0);
        float w0 = __expf(p0 - nm0);
        m0 = nm0;
        d0 = d0 * f0 + w0;
        acc0.x = acc0.x * f0 + w0 * l0.x;
        acc0.y = acc0.y * f0 + w0 * l0.y;
        acc0.z = acc0.z * f0 + w0 * l0.z;
        acc0.w = acc0.w * f0 + w0 * l0.w;
        float nm1 = fmaxf(m1, p1);
        float f1 = __expf(m1 - nm1);
        float w1 = __expf(p1 - nm1);
        m1 = nm1;
        d1 = d1 * f1 + w1;
        acc1.x = acc1.x * f1 + w1 * l1.x;
        acc1.y = acc1.y * f1 + w1 * l1.y;
        acc1.z = acc1.z * f1 + w1 * l1.z;
        acc1.w = acc1.w * f1 + w1 * l1.w;
    };

    int i = beg;
    for (; i + 1 < end; i += 2) {
        int sA = g_esrc[i];
        int sB = g_esrc[i + 1];
        process(sA, mA0, mA1, dA0, dA1, aA0, aA1);
        process(sB, mB0, mB1, dB0, dB1, aB0, aB1);
    }
    if (i < end) process(g_esrc[i], mA0, mA1, dA0, dA1, aA0, aA1);

    // merge B into A
    {
        float m = fmaxf(mA0, mB0);
        float fA = __expf(mA0 - m), fB = __expf(mB0 - m);
        dA0 = dA0 * fA + dB0 * fB;
        aA0.x = aA0.x * fA + aB0.x * fB;
        aA0.y = aA0.y * fA + aB0.y * fB;
        aA0.z = aA0.z * fA + aB0.z * fB;
        aA0.w = aA0.w * fA + aB0.w * fB;
        m = fmaxf(mA1, mB1);
        fA = __expf(mA1 - m); fB = __expf(mB1 - m);
        dA1 = dA1 * fA + dB1 * fB;
        aA1.x = aA1.x * fA + aB1.x * fB;
        aA1.y = aA1.y * fA + aB1.y * fB;
        aA1.z = aA1.z * fA + aB1.z * fB;
        aA1.w = aA1.w * fA + aB1.w * fB;
    }

    float inv0 = 1.0f / (dA0 + 1e-16f);
    float inv1 = 1.0f / (dA1 + 1e-16f);
    const float4* gb4 = (const float4*)gat_b;
    float4 b0 = gb4[lane];
    float4 b1 = gb4[32 + lane];
    float o0 = aA0.x * inv0 + b0.x, o1 = aA0.y * inv0 + b0.y;
    float o2 = aA0.z * inv0 + b0.z, o3 = aA0.w * inv0 + b0.w;
    float o4 = aA1.x * inv1 + b1.x, o5 = aA1.y * inv1 + b1.y;
    float o6 = aA1.z * inv1 + b1.z, o7 = aA1.w * inv1 + b1.w;

    uint32_t h0, l0w, h1, l1w, h2, l2w, h3, l3w;
    split_pack(o0, o1, h0, l0w);
    split_pack(o2, o3, h1, l1w);
    split_pack(o4, o5, h2, l2w);
    split_pack(o6, o7, h3, l3w);
    size_t rb = (size_t)node * 128;
    gohi[rb + lane * 2]          = h0;  golo[rb + lane * 2]          = l0w;
    gohi[rb + lane * 2 + 1]      = h1;  golo[rb + lane * 2 + 1]      = l1w;
    gohi[rb + 64 + lane * 2]     = h2;  golo[rb + 64 + lane * 2]     = l2w;
    gohi[rb + 64 + lane * 2 + 1] = h3;  golo[rb + 64 + lane * 2 + 1] = l3w;
}

// ------------------------- launch --------------------------------------------
extern "C" void kernel_launch(void* const* d_in, const int* in_sizes, int n_in,
                              void* d_out, int out_size) {
    const float* x_in   = (const float*)d_in[0];
    const void*  edges  = d_in[1];
    const float* ln1_g  = (const float*)d_in[2];
    const float* ln1_b  = (const float*)d_in[3];
    const float* Wl     = (const float*)d_in[4];
    const float* bl     = (const float*)d_in[5];
    const float* Wr     = (const float*)d_in[6];
    const float* br     = (const float*)d_in[7];
    const float* att    = (const float*)d_in[8];
    const float* gat_b  = (const float*)d_in[9];
    const float* projW  = (const float*)d_in[10];
    const float* projb  = (const float*)d_in[11];
    const float* ln2_g  = (const float*)d_in[12];
    const float* ln2_b  = (const float*)d_in[13];
    const float* W1     = (const float*)d_in[14];
    const float* b1     = (const float*)d_in[15];
    const float* W2     = (const float*)d_in[16];
    const float* b2     = (const float*)d_in[17];

    const int N = in_sizes[0] / DIM;
    const int E = in_sizes[1] / 2;
    float* x = (float*)d_out;

    cudaFuncSetAttribute(gemm_kernel<0>, cudaFuncAttributeMaxDynamicSharedMemorySize, GEMM_SMEM);
    cudaFuncSetAttribute(gemm_kernel<1>, cudaFuncAttributeMaxDynamicSharedMemorySize, GEMM_SMEM);
    cudaFuncSetAttribute(gemm_kernel<2>, cudaFuncAttributeMaxDynamicSharedMemorySize, GEMM_SMEM);
    cudaFuncSetAttribute(gemm_kernel<3>, cudaFuncAttributeMaxDynamicSharedMemorySize, GEMM_SMEM);

    void *p_xlr, *p_hhi, *p_hlo, *p_gohi, *p_golo, *p_mhi, *p_mlo, *p_wbhi, *p_wblo, *p_blr;
    cudaGetSymbolAddress(&p_xlr, g_xlr);
    cudaGetSymbolAddress(&p_hhi, g_h_hi);
    cudaGetSymbolAddress(&p_hlo, g_h_lo);
    cudaGetSymbolAddress(&p_gohi, g_go_hi);
    cudaGetSymbolAddress(&p_golo, g_go_lo);
    cudaGetSymbolAddress(&p_mhi, g_mid_hi);
    cudaGetSymbolAddress(&p_mlo, g_mid_lo);
    cudaGetSymbolAddress(&p_wbhi, g_wb_hi);
    cudaGetSymbolAddress(&p_wblo, g_wb_lo);
    cudaGetSymbolAddress(&p_blr, g_blr);
    float* xlr = (float*)p_xlr;
    uint32_t* hhi = (uint32_t*)p_hhi;
    uint32_t* hlo = (uint32_t*)p_hlo;
    uint32_t* gohi = (uint32_t*)p_gohi;
    uint32_t* golo = (uint32_t*)p_golo;
    uint32_t* mhi = (uint32_t*)p_mhi;
    uint32_t* mlo = (uint32_t*)p_mlo;
    uint32_t* wbhi = (uint32_t*)p_wbhi;
    uint32_t* wblo = (uint32_t*)p_wblo;
    float* blr = (float*)p_blr;

    cudaMemcpyAsync(x, x_in, (size_t)N * DIM * sizeof(float), cudaMemcpyDeviceToDevice);

    const int nb = (N + 1023) / 1024;
    detect_kernel<<<1, 256>>>(edges, E, N);
    clear_deg_kernel<<<(N + 255) / 256, 256>>>(N);
    decode_hist_kernel<<<(E + 255) / 256, 256>>>(edges, E);
    scanA_kernel<<<nb, 1024>>>(N);
    scanB_kernel<<<1, 32>>>(nb);
    scanC_kernel<<<(N + 255) / 256, 256>>>(N);
    scatter_kernel<<<(E + 255) / 256, 256>>>(E);

    wconv_all_kernel<<<(2 * LWORDS + 255) / 256, 256>>>(Wl, Wr, projW, W1, W2);
    bconcat_kernel<<<4, 256>>>(bl, br);

    const int ln_blocks = (N + 7) / 8;
    const int mtiles = (N + 127) / 128;

    // initial PreNorm (layer 0)
    ln_kernel<<<ln_blocks, 256>>>(x, ln1_g, ln1_b, hhi, hlo, N);

    for (int l = 0; l < 2; l++) {
        size_t off = (size_t)l * LWORDS;
        const uint32_t* wlr_hi = wbhi + off,         *wlr_lo = wblo + off;
        const uint32_t* pj_hi = wbhi + off + 32768,  *pj_lo = wblo + off + 32768;
        const uint32_t* w1_hi = wbhi + off + 49152,  *w1_lo = wblo + off + 49152;
        const uint32_t* w2_hi = wbhi + off + 81920,  *w2_lo = wblo + off + 81920;
        const float* at_l = att + (size_t)l * HD;
        const float* gb_l = gat_b + (size_t)l * HD;
        const float* pb_l = projb + (size_t)l * DIM;
        const float* b1_l = b1 + (size_t)l * MLPD;
        const float* b2_l = b2 + (size_t)l * DIM;

        // xlr = h @ [Wl|Wr] + blr
        gemm_kernel<0><<<dim3(4, mtiles), 256, GEMM_SMEM>>>(
            hhi, hlo, wlr_hi, wlr_lo, blr + (size_t)l * 512, xlr, nullptr, nullptr,
            nullptr, nullptr, N, DIM, 512);
        // fused GATv2
        gat_node_kernel<<<(N + 7) / 8, 256>>>(xlr, at_l, gb_l, gohi, golo, N);
        // x += gout @ proj + pb; fused LN2 -> h
        gemm_kernel<3><<<dim3(1, mtiles), 256, GEMM_SMEM>>>(
            gohi, golo, pj_hi, pj_lo, pb_l, x, hhi, hlo,
            ln2_g + (size_t)l * DIM, ln2_b + (size_t)l * DIM, N, HD, DIM);
        // mid = gelu(h @ W1 + b1) split
        gemm_kernel<2><<<dim3(4, mtiles), 256, GEMM_SMEM>>>(
            hhi, hlo, w1_hi, w1_lo, b1_l, nullptr, mhi, mlo,
            nullptr, nullptr, N, DIM, MLPD);
        // x += mid @ W2 + b2; fused LN1 of next layer (except after last layer)
        if (l == 0) {
            gemm_kernel<3><<<dim3(1, mtiles), 256, GEMM_SMEM>>>(
                mhi, mlo, w2_hi, w2_lo, b2_l, x, hhi, hlo,
                ln1_g + DIM, ln1_b + DIM, N, MLPD, DIM);
        } else {
            gemm_kernel<1><<<dim3(1, mtiles), 256, GEMM_SMEM>>>(
                mhi, mlo, w2_hi, w2_lo, b2_l, x, nullptr, nullptr,
                nullptr, nullptr, N, MLPD, DIM);
        }
    }
}

// round 9
// speedup vs baseline: 2.7197x; 1.0614x over previous
#include <cuda_runtime.h>
#include <cuda_fp16.h>
#include <math.h>
#include <stdint.h>

// ----------------------------------------------------------------------------
// GATv2 Transformer. GEMMs: fp16 mma.sync, A split hi+lo (2-term compensation),
// weights single fp16, cp.async double buffer, LN fused into N=128 epilogues.
// Edge phase: CSR-by-dst + dual-state online-softmax gather.
// ----------------------------------------------------------------------------

#define MAXN 50000
#define MAXE 800000
#define DIM 128
#define HD 256
#define MLPD 512
#define LWORDS 114688

// ------------------------- scratch (device globals) -------------------------
__device__ __align__(256) float    g_xlr [(size_t)MAXN * 512];
__device__ __align__(256) uint32_t g_h_hi [(size_t)MAXN * (DIM/2)];
__device__ __align__(256) uint32_t g_h_lo [(size_t)MAXN * (DIM/2)];
__device__ __align__(256) uint32_t g_go_hi[(size_t)MAXN * (HD/2)];
__device__ __align__(256) uint32_t g_go_lo[(size_t)MAXN * (HD/2)];
__device__ __align__(256) uint32_t g_mid_hi[(size_t)MAXN * (MLPD/2)];
__device__ __align__(256) uint32_t g_mid_lo[(size_t)MAXN * (MLPD/2)];
__device__ __align__(256) uint32_t g_wb[2 * LWORDS];      // weights, single fp16
__device__ __align__(256) float    g_blr[2 * 512];
// CSR
__device__ __align__(256) int g_src[MAXE];
__device__ __align__(256) int g_dst[MAXE];
__device__ __align__(256) int g_esrc[MAXE];
__device__ __align__(256) int g_deg[MAXN];
__device__ __align__(256) int g_off[MAXN + 1];
__device__ __align__(256) int g_pos[MAXN];
__device__ __align__(256) int g_bsum[64];
__device__ __align__(256) int g_boff[64];
__device__ int g_is64;

// ------------------------- helpers -------------------------
// fp16 split: x = hi + lo, hi/lo fp16; packs (x,y) pairwise.
__device__ __forceinline__ void split_pack(float x, float y, uint32_t& hi, uint32_t& lo) {
    __half hx = __float2half_rn(x);
    __half hy = __float2half_rn(y);
    __half lx = __float2half_rn(x - __half2float(hx));
    __half ly = __float2half_rn(y - __half2float(hy));
    hi = ((uint32_t)__half_as_ushort(hy) << 16) | (uint32_t)__half_as_ushort(hx);
    lo = ((uint32_t)__half_as_ushort(ly) << 16) | (uint32_t)__half_as_ushort(lx);
}
__device__ __forceinline__ uint32_t pack_h(float x, float y) {
    return ((uint32_t)__half_as_ushort(__float2half_rn(y)) << 16)
         | (uint32_t)__half_as_ushort(__float2half_rn(x));
}

// ------------------------- edge dtype detect / decode+hist -------------------
__global__ void detect_kernel(const void* edges, int E, int N) {
    __shared__ int bad;
    if (threadIdx.x == 0) bad = 0;
    __syncthreads();
    const long long* p = (const long long*)edges;
    int n = E < 2048 ? E : 2048;
    for (int i = threadIdx.x; i < n; i += blockDim.x) {
        long long v = p[i];
        if (v < 0 || v >= (long long)N) atomicOr(&bad, 1);
    }
    __syncthreads();
    if (threadIdx.x == 0) g_is64 = bad ? 0 : 1;
}

__global__ void clear_deg_kernel(int N) {
    int i = blockIdx.x * blockDim.x + threadIdx.x;
    if (i < N) g_deg[i] = 0;
}

__global__ void decode_hist_kernel(const void* edges, int E) {
    int i = blockIdx.x * blockDim.x + threadIdx.x;
    if (i >= E) return;
    int s, d;
    if (g_is64) {
        const long long* p = (const long long*)edges;
        s = (int)p[i];
        d = (int)p[(size_t)E + i];
    } else {
        const int* p = (const int*)edges;
        s = p[i];
        d = p[(size_t)E + i];
    }
    g_src[i] = s;
    g_dst[i] = d;
    atomicAdd(&g_deg[d], 1);
}

// ---- 3-phase parallel scan ----
__global__ void scanA_kernel(int N) {
    int t = threadIdx.x;
    int i = blockIdx.x * 1024 + t;
    int lane = t & 31, w = t >> 5;
    int v = (i < N) ? g_deg[i] : 0;
    int s = v;
    #pragma unroll
    for (int o = 1; o < 32; o <<= 1) {
        int u = __shfl_up_sync(0xffffffffu, s, o);
        if (lane >= o) s += u;
    }
    __shared__ int wt[32];
    if (lane == 31) wt[w] = s;
    __syncthreads();
    if (w == 0) {
        int x = wt[lane];
        #pragma unroll
        for (int o = 1; o < 32; o <<= 1) {
            int u = __shfl_up_sync(0xffffffffu, x, o);
            if (lane >= o) x += u;
        }
        wt[lane] = x;
    }
    __syncthreads();
    if (w) s += wt[w - 1];
    if (i < N) g_off[i + 1] = s;
    if (t == 1023) g_bsum[blockIdx.x] = s;
}

__global__ void scanB_kernel(int nb) {
    int lane = threadIdx.x;
    int v0 = (lane < nb) ? g_bsum[lane] : 0;
    int v1 = (32 + lane < nb) ? g_bsum[32 + lane] : 0;
    int s0 = v0;
    #pragma unroll
    for (int o = 1; o < 32; o <<= 1) {
        int u = __shfl_up_sync(0xffffffffu, s0, o);
        if (lane >= o) s0 += u;
    }
    int tot0 = __shfl_sync(0xffffffffu, s0, 31);
    int s1 = v1;
    #pragma unroll
    for (int o = 1; o < 32; o <<= 1) {
        int u = __shfl_up_sync(0xffffffffu, s1, o);
        if (lane >= o) s1 += u;
    }
    if (lane < nb) g_boff[lane] = s0 - v0;
    if (32 + lane < nb) g_boff[32 + lane] = tot0 + s1 - v1;
}

__global__ void scanC_kernel(int N) {
    int i = blockIdx.x * blockDim.x + threadIdx.x;
    if (i == 0) g_off[0] = 0;
    if (i >= N) return;
    int b = i >> 10;
    int inc = g_off[i + 1] + g_boff[b];
    g_off[i + 1] = inc;
    g_pos[i] = inc - g_deg[i];
}

__global__ void scatter_kernel(int E) {
    int i = blockIdx.x * blockDim.x + threadIdx.x;
    if (i >= E) return;
    int p = atomicAdd(&g_pos[g_dst[i]], 1);
    g_esrc[p] = g_src[i];
}

// ---------------- fused weight convert (single fp16) -------------------------
__global__ void wconv_all_kernel(const float* __restrict__ Wl, const float* __restrict__ Wr,
                                 const float* __restrict__ pj, const float* __restrict__ W1,
                                 const float* __restrict__ W2) {
    int idx = blockIdx.x * blockDim.x + threadIdx.x;
    if (idx >= 2 * LWORDS) return;
    int layer = idx / LWORDS;
    int r = idx - layer * LWORDS;
    const float* W; int K, N;
    if (r < 16384)      { W = Wl + (size_t)layer * 32768; K = 128; N = 256; }
    else if (r < 32768) { W = Wr + (size_t)layer * 32768; r -= 16384; K = 128; N = 256; }
    else if (r < 49152) { W = pj + (size_t)layer * 32768; r -= 32768; K = 256; N = 128; }
    else if (r < 81920) { W = W1 + (size_t)layer * 65536; r -= 49152; K = 128; N = 512; }
    else                { W = W2 + (size_t)layer * 65536; r -= 81920; K = 512; N = 128; }
    int kw = K >> 1;
    int n = r / kw, kp = r - n * kw;
    float x = W[(size_t)(2 * kp) * N + n];
    float y = W[(size_t)(2 * kp + 1) * N + n];
    g_wb[idx] = pack_h(x, y);
}

__global__ void bconcat_kernel(const float* __restrict__ bl, const float* __restrict__ br) {
    int i = threadIdx.x + blockIdx.x * blockDim.x;
    if (i >= 1024) return;
    int layer = i >> 9, j = i & 511;
    float v = (j < 256) ? bl[layer * HD + j] : br[layer * HD + j - 256];
    g_blr[layer * 512 + j] = v;
}

// ------------------------- standalone layernorm ------------------------------
__global__ void ln_kernel(const float* __restrict__ x, const float* __restrict__ g,
                          const float* __restrict__ b,
                          uint32_t* __restrict__ ohi, uint32_t* __restrict__ olo, int N) {
    int row = (blockIdx.x * blockDim.x + threadIdx.x) >> 5;
    int lane = threadIdx.x & 31;
    if (row >= N) return;
    const float4* xr = (const float4*)x + (size_t)row * 32;
    float4 v = xr[lane];
    float s  = v.x + v.y + v.z + v.w;
    float sq = v.x*v.x + v.y*v.y + v.z*v.z + v.w*v.w;
    #pragma unroll
    for (int o = 16; o; o >>= 1) {
        s  += __shfl_xor_sync(0xffffffffu, s,  o);
        sq += __shfl_xor_sync(0xffffffffu, sq, o);
    }
    float m   = s * (1.0f / 128.0f);
    float var = sq * (1.0f / 128.0f) - m * m;
    float inv = rsqrtf(var + 1e-5f);
    float4 gg = ((const float4*)g)[lane];
    float4 bb = ((const float4*)b)[lane];
    float o0 = (v.x - m) * inv * gg.x + bb.x;
    float o1 = (v.y - m) * inv * gg.y + bb.y;
    float o2 = (v.z - m) * inv * gg.z + bb.z;
    float o3 = (v.w - m) * inv * gg.w + bb.w;
    uint32_t h0, l0, h1, l1;
    split_pack(o0, o1, h0, l0);
    split_pack(o2, o3, h1, l1);
    size_t base = (size_t)row * 64 + lane * 2;
    ohi[base] = h0; ohi[base + 1] = h1;
    olo[base] = l0; olo[base + 1] = l1;
}

// ------------------------- tensor-core GEMM --------------------------------
__device__ __forceinline__ void mma16816(float* c, const uint32_t* a, const uint32_t* b) {
    asm volatile(
        "mma.sync.aligned.m16n8k16.row.col.f32.f16.f16.f32 "
        "{%0,%1,%2,%3}, {%4,%5,%6,%7}, {%8,%9}, {%0,%1,%2,%3};"
        : "+f"(c[0]), "+f"(c[1]), "+f"(c[2]), "+f"(c[3])
        : "r"(a[0]), "r"(a[1]), "r"(a[2]), "r"(a[3]), "r"(b[0]), "r"(b[1]));
}

__device__ __forceinline__ void cpa16(uint32_t dst, const void* src, int bytes) {
    asm volatile("cp.async.cg.shared.global [%0], [%1], 16, %2;\n"
                 :: "r"(dst), "l"(src), "r"(bytes));
}

__device__ __forceinline__ int swz(int row, int kp) {
    return (row << 4) | (((kp >> 2) ^ ((row >> 1) & 3)) << 2) | (kp & 3);
}

#define TILE_WORDS 2048
#define BUF_WORDS  (3 * TILE_WORDS)          // Ah, Al, Bh
#define GEMM_SMEM  (2 * BUF_WORDS * 4)       // 48 KB
#define GEMM_SMEM3 65536                     // MODE 3 needs 64 KB rowbuf

// MODE 0: store fp32; 1: accumulate fp32; 2: GELU then split hi/lo;
// MODE 3: accumulate fp32 + fused LayerNorm -> writes x (C) and split h (N==128)
template<int MODE>
__global__ __launch_bounds__(256, 2)
void gemm_kernel(const uint32_t* __restrict__ Ahi, const uint32_t* __restrict__ Alo,
                 const uint32_t* __restrict__ Bh_g,
                 const float* __restrict__ bias, float* __restrict__ C,
                 uint32_t* __restrict__ Chi, uint32_t* __restrict__ Clo,
                 const float* __restrict__ lng, const float* __restrict__ lnb,
                 int M, int K, int N) {
    extern __shared__ uint32_t sm[];

    const int tid  = threadIdx.x;
    const int lane = tid & 31;
    const int wid  = tid >> 5;
    const int warp_m = wid & 3;
    const int warp_n = wid >> 2;
    const int m0 = blockIdx.y * 128, n0 = blockIdx.x * 128;
    const int g  = lane >> 2;
    const int tg = lane & 3;
    const int kw = K >> 1;
    const int nk = K >> 5;

    const uint32_t sbase = (uint32_t)__cvta_generic_to_shared(sm);

    float acc[2][8][4];
    #pragma unroll
    for (int i = 0; i < 2; i++)
        #pragma unroll
        for (int j = 0; j < 8; j++)
            #pragma unroll
            for (int r = 0; r < 4; r++) acc[i][j][r] = 0.0f;

    auto issue = [&](int kt, int b) {
        uint32_t bufb = sbase + (uint32_t)(b * BUF_WORDS) * 4;
        #pragma unroll
        for (int t = 0; t < 2; t++) {
            int chunk = tid + t * 256;
            int row = chunk >> 2, c = chunk & 3;
            int dstw = (row << 4) | ((c ^ ((row >> 1) & 3)) << 2);
            int asz = (m0 + row < M) ? 16 : 0;
            const uint32_t* asrc = Ahi + (size_t)(m0 + row) * kw + kt * 16 + c * 4;
            const uint32_t* alsr = Alo + (size_t)(m0 + row) * kw + kt * 16 + c * 4;
            const uint32_t* bsrc = Bh_g + (size_t)(n0 + row) * kw + kt * 16 + c * 4;
            cpa16(bufb + (uint32_t)dstw * 4,                    asrc, asz);
            cpa16(bufb + (uint32_t)(TILE_WORDS + dstw) * 4,     alsr, asz);
            cpa16(bufb + (uint32_t)(2 * TILE_WORDS + dstw) * 4, bsrc, 16);
        }
        asm volatile("cp.async.commit_group;\n");
    };

    issue(0, 0);

    for (int kt = 0; kt < nk; kt++) {
        const bool more = (kt + 1 < nk);
        if (more) issue(kt + 1, (kt + 1) & 1);
        if (more) { asm volatile("cp.async.wait_group 1;\n"); }
        else      { asm volatile("cp.async.wait_group 0;\n"); }
        __syncthreads();

        const uint32_t* Ah = sm + (kt & 1) * BUF_WORDS;
        const uint32_t* Al = Ah + TILE_WORDS;
        const uint32_t* Bh = Ah + 2 * TILE_WORDS;
        #pragma unroll
        for (int ks = 0; ks < 2; ks++) {
            const int kb = ks * 4;
            uint32_t ah[2][4], al[2][4];
            #pragma unroll
            for (int mt = 0; mt < 2; mt++) {
                int r0 = warp_m * 32 + mt * 16;
                ah[mt][0] = Ah[swz(r0 + g,     kb + tg)];
                ah[mt][1] = Ah[swz(r0 + g + 8, kb + tg)];
                ah[mt][2] = Ah[swz(r0 + g,     kb + tg + 8)];
                ah[mt][3] = Ah[swz(r0 + g + 8, kb + tg + 8)];
                al[mt][0] = Al[swz(r0 + g,     kb + tg)];
                al[mt][1] = Al[swz(r0 + g + 8, kb + tg)];
                al[mt][2] = Al[swz(r0 + g,     kb + tg + 8)];
                al[mt][3] = Al[swz(r0 + g + 8, kb + tg + 8)];
            }
            #pragma unroll
            for (int nt = 0; nt < 8; nt++) {
                int col = warp_n * 64 + nt * 8 + g;
                uint32_t bh[2];
                bh[0] = Bh[swz(col, kb + tg)];
                bh[1] = Bh[swz(col, kb + tg + 8)];
                #pragma unroll
                for (int mt = 0; mt < 2; mt++) {
                    float* c = acc[mt][nt];
                    mma16816(c, ah[mt], bh);
                    mma16816(c, al[mt], bh);
                }
            }
        }
        __syncthreads();
    }

    // ---- epilogue ----
    float* rowbuf = (float*)sm;   // MODE 3: 128x128 staging
    #pragma unroll
    for (int mt = 0; mt < 2; mt++) {
        int rloc = warp_m * 32 + mt * 16 + (lane >> 2);
        int row = m0 + rloc;
        #pragma unroll
        for (int nt = 0; nt < 8; nt++) {
            int col = n0 + warp_n * 64 + nt * 8 + (lane & 3) * 2;
            float2 bb = *(const float2*)(bias + col);
            #pragma unroll
            for (int half = 0; half < 2; half++) {
                int r = row + half * 8;
                if (r >= M) continue;
                float v0 = acc[mt][nt][2 * half]     + bb.x;
                float v1 = acc[mt][nt][2 * half + 1] + bb.y;
                if (MODE == 2) {
                    float u = v0;
                    v0 = 0.5f * u * (1.0f + tanhf(0.7978845608028654f * (u + 0.044715f * u * u * u)));
                    u = v1;
                    v1 = 0.5f * u * (1.0f + tanhf(0.7978845608028654f * (u + 0.044715f * u * u * u)));
                    uint32_t h, l;
                    split_pack(v0, v1, h, l);
                    size_t w = (size_t)r * (N >> 1) + (col >> 1);
                    Chi[w] = h; Clo[w] = l;
                } else if (MODE == 3) {
                    float2 old = *(float2*)(C + (size_t)r * N + col);
                    rowbuf[(rloc + half * 8) * 128 + (col - n0)]     = v0 + old.x;
                    rowbuf[(rloc + half * 8) * 128 + (col - n0) + 1] = v1 + old.y;
                } else {
                    float2* dst = (float2*)(C + (size_t)r * N + col);
                    if (MODE == 1) {
                        float2 old = *dst;
                        v0 += old.x; v1 += old.y;
                    }
                    *dst = make_float2(v0, v1);
                }
            }
        }
    }

    if (MODE == 3) {
        __syncthreads();
        float4 gg = ((const float4*)lng)[lane];
        float4 bb2 = ((const float4*)lnb)[lane];
        for (int rr = wid * 16; rr < wid * 16 + 16; rr++) {
            int r = m0 + rr;
            if (r >= M) break;
            float4 v = ((const float4*)(rowbuf + rr * 128))[lane];
            float s  = v.x + v.y + v.z + v.w;
            float sq = v.x*v.x + v.y*v.y + v.z*v.z + v.w*v.w;
            #pragma unroll
            for (int o = 16; o; o >>= 1) {
                s  += __shfl_xor_sync(0xffffffffu, s,  o);
                sq += __shfl_xor_sync(0xffffffffu, sq, o);
            }
            float m   = s * (1.0f / 128.0f);
            float var = sq * (1.0f / 128.0f) - m * m;
            float inv = rsqrtf(var + 1e-5f);
            ((float4*)(C + (size_t)r * 128))[lane] = v;
            float o0 = (v.x - m) * inv * gg.x + bb2.x;
            float o1 = (v.y - m) * inv * gg.y + bb2.y;
            float o2 = (v.z - m) * inv * gg.z + bb2.z;
            float o3 = (v.w - m) * inv * gg.w + bb2.w;
            uint32_t h0, l0, h1, l1;
            split_pack(o0, o1, h0, l0);
            split_pack(o2, o3, h1, l1);
            size_t base = (size_t)r * 64 + lane * 2;
            Chi[base] = h0; Chi[base + 1] = h1;
            Clo[base] = l0; Clo[base + 1] = l1;
        }
    }
}

// ------------------- fused GATv2 node kernel (warp per dst) ------------------
__global__ void gat_node_kernel(const float* __restrict__ xlr,
                                const float* __restrict__ att,
                                const float* __restrict__ gat_b,
                                uint32_t* __restrict__ gohi, uint32_t* __restrict__ golo,
                                int N) {
    int node = (blockIdx.x * blockDim.x + threadIdx.x) >> 5;
    int lane = threadIdx.x & 31;
    if (node >= N) return;

    const float4* base = (const float4*)xlr;
    float4 r0 = base[(size_t)node * 128 + 64 + lane];
    float4 r1 = base[(size_t)node * 128 + 96 + lane];
    float4 a0 = ((const float4*)att)[lane];
    float4 a1 = ((const float4*)att)[32 + lane];

    float mA0 = -1e30f, mA1 = -1e30f, dA0 = 0.f, dA1 = 0.f;
    float mB0 = -1e30f, mB1 = -1e30f, dB0 = 0.f, dB1 = 0.f;
    float4 aA0 = make_float4(0.f,0.f,0.f,0.f), aA1 = make_float4(0.f,0.f,0.f,0.f);
    float4 aB0 = make_float4(0.f,0.f,0.f,0.f), aB1 = make_float4(0.f,0.f,0.f,0.f);

    int beg = g_off[node], end = g_off[node + 1];

    auto process = [&](int s, float& m0, float& m1, float& d0, float& d1,
                       float4& acc0, float4& acc1) {
        float4 l0 = base[(size_t)s * 128 + lane];
        float4 l1 = base[(size_t)s * 128 + 32 + lane];
        float4 e0, e1;
        e0.x = l0.x + r0.x; e0.x = e0.x > 0.f ? e0.x : 0.2f * e0.x;
        e0.y = l0.y + r0.y; e0.y = e0.y > 0.f ? e0.y : 0.2f * e0.y;
        e0.z = l0.z + r0.z; e0.z = e0.z > 0.f ? e0.z : 0.2f * e0.z;
        e0.w = l0.w + r0.w; e0.w = e0.w > 0.f ? e0.w : 0.2f * e0.w;
        e1.x = l1.x + r1.x; e1.x = e1.x > 0.f ? e1.x : 0.2f * e1.x;
        e1.y = l1.y + r1.y; e1.y = e1.y > 0.f ? e1.y : 0.2f * e1.y;
        e1.z = l1.z + r1.z; e1.z = e1.z > 0.f ? e1.z : 0.2f * e1.z;
        e1.w = l1.w + r1.w; e1.w = e1.w > 0.f ? e1.w : 0.2f * e1.w;
        float p0 = e0.x * a0.x + e0.y * a0.y + e0.z * a0.z + e0.w * a0.w;
        float p1 = e1.x * a1.x + e1.y * a1.y + e1.z * a1.z + e1.w * a1.w;
        #pragma unroll
        for (int o = 16; o; o >>= 1) {
            p0 += __shfl_xor_sync(0xffffffffu, p0, o);
            p1 += __shfl_xor_sync(0xffffffffu, p1, o);
        }
        float nm0 = fmaxf(m0, p0);
        float f0 = __expf(m0 - nm0);
        float w0 = __expf(p0 - nm0);
        m0 = nm0;
        d0 = d0 * f0 + w0;
        acc0.x = acc0.x * f0 + w0 * l0.x;
        acc0.y = acc0.y * f0 + w0 * l0.y;
        acc0.z = acc0.z * f0 + w0 * l0.z;
        acc0.w = acc0.w * f0 + w0 * l0.w;
        float nm1 = fmaxf(m1, p1);
        float f1 = __expf(m1 - nm1);
        float w1 = __expf(p1 - nm1);
        m1 = nm1;
        d1 = d1 * f1 + w1;
        acc1.x = acc1.x * f1 + w1 * l1.x;
        acc1.y = acc1.y * f1 + w1 * l1.y;
        acc1.z = acc1.z * f1 + w1 * l1.z;
        acc1.w = acc1.w * f1 + w1 * l1.w;
    };

    int i = beg;
    for (; i + 1 < end; i += 2) {
        int sA = g_esrc[i];
        int sB = g_esrc[i + 1];
        process(sA, mA0, mA1, dA0, dA1, aA0, aA1);
        process(sB, mB0, mB1, dB0, dB1, aB0, aB1);
    }
    if (i < end) process(g_esrc[i], mA0, mA1, dA0, dA1, aA0, aA1);

    {
        float m = fmaxf(mA0, mB0);
        float fA = __expf(mA0 - m), fB = __expf(mB0 - m);
        dA0 = dA0 * fA + dB0 * fB;
        aA0.x = aA0.x * fA + aB0.x * fB;
        aA0.y = aA0.y * fA + aB0.y * fB;
        aA0.z = aA0.z * fA + aB0.z * fB;
        aA0.w = aA0.w * fA + aB0.w * fB;
        m = fmaxf(mA1, mB1);
        fA = __expf(mA1 - m); fB = __expf(mB1 - m);
        dA1 = dA1 * fA + dB1 * fB;
        aA1.x = aA1.x * fA + aB1.x * fB;
        aA1.y = aA1.y * fA + aB1.y * fB;
        aA1.z = aA1.z * fA + aB1.z * fB;
        aA1.w = aA1.w * fA + aB1.w * fB;
    }

    float inv0 = 1.0f / (dA0 + 1e-16f);
    float inv1 = 1.0f / (dA1 + 1e-16f);
    const float4* gb4 = (const float4*)gat_b;
    float4 b0 = gb4[lane];
    float4 b1 = gb4[32 + lane];
    float o0 = aA0.x * inv0 + b0.x, o1 = aA0.y * inv0 + b0.y;
    float o2 = aA0.z * inv0 + b0.z, o3 = aA0.w * inv0 + b0.w;
    float o4 = aA1.x * inv1 + b1.x, o5 = aA1.y * inv1 + b1.y;
    float o6 = aA1.z * inv1 + b1.z, o7 = aA1.w * inv1 + b1.w;

    uint32_t h0, l0w, h1, l1w, h2, l2w, h3, l3w;
    split_pack(o0, o1, h0, l0w);
    split_pack(o2, o3, h1, l1w);
    split_pack(o4, o5, h2, l2w);
    split_pack(o6, o7, h3, l3w);
    size_t rb = (size_t)node * 128;
    gohi[rb + lane * 2]          = h0;  golo[rb + lane * 2]          = l0w;
    gohi[rb + lane * 2 + 1]      = h1;  golo[rb + lane * 2 + 1]      = l1w;
    gohi[rb + 64 + lane * 2]     = h2;  golo[rb + 64 + lane * 2]     = l2w;
    gohi[rb + 64 + lane * 2 + 1] = h3;  golo[rb + 64 + lane * 2 + 1] = l3w;
}

// ------------------------- launch --------------------------------------------
extern "C" void kernel_launch(void* const* d_in, const int* in_sizes, int n_in,
                              void* d_out, int out_size) {
    const float* x_in   = (const float*)d_in[0];
    const void*  edges  = d_in[1];
    const float* ln1_g  = (const float*)d_in[2];
    const float* ln1_b  = (const float*)d_in[3];
    const float* Wl     = (const float*)d_in[4];
    const float* bl     = (const float*)d_in[5];
    const float* Wr     = (const float*)d_in[6];
    const float* br     = (const float*)d_in[7];
    const float* att    = (const float*)d_in[8];
    const float* gat_b  = (const float*)d_in[9];
    const float* projW  = (const float*)d_in[10];
    const float* projb  = (const float*)d_in[11];
    const float* ln2_g  = (const float*)d_in[12];
    const float* ln2_b  = (const float*)d_in[13];
    const float* W1     = (const float*)d_in[14];
    const float* b1     = (const float*)d_in[15];
    const float* W2     = (const float*)d_in[16];
    const float* b2     = (const float*)d_in[17];

    const int N = in_sizes[0] / DIM;
    const int E = in_sizes[1] / 2;
    float* x = (float*)d_out;

    cudaFuncSetAttribute(gemm_kernel<0>, cudaFuncAttributeMaxDynamicSharedMemorySize, GEMM_SMEM);
    cudaFuncSetAttribute(gemm_kernel<1>, cudaFuncAttributeMaxDynamicSharedMemorySize, GEMM_SMEM);
    cudaFuncSetAttribute(gemm_kernel<2>, cudaFuncAttributeMaxDynamicSharedMemorySize, GEMM_SMEM);
    cudaFuncSetAttribute(gemm_kernel<3>, cudaFuncAttributeMaxDynamicSharedMemorySize, GEMM_SMEM3);

    void *p_xlr, *p_hhi, *p_hlo, *p_gohi, *p_golo, *p_mhi, *p_mlo, *p_wb, *p_blr;
    cudaGetSymbolAddress(&p_xlr, g_xlr);
    cudaGetSymbolAddress(&p_hhi, g_h_hi);
    cudaGetSymbolAddress(&p_hlo, g_h_lo);
    cudaGetSymbolAddress(&p_gohi, g_go_hi);
    cudaGetSymbolAddress(&p_golo, g_go_lo);
    cudaGetSymbolAddress(&p_mhi, g_mid_hi);
    cudaGetSymbolAddress(&p_mlo, g_mid_lo);
    cudaGetSymbolAddress(&p_wb, g_wb);
    cudaGetSymbolAddress(&p_blr, g_blr);
    float* xlr = (float*)p_xlr;
    uint32_t* hhi = (uint32_t*)p_hhi;
    uint32_t* hlo = (uint32_t*)p_hlo;
    uint32_t* gohi = (uint32_t*)p_gohi;
    uint32_t* golo = (uint32_t*)p_golo;
    uint32_t* mhi = (uint32_t*)p_mhi;
    uint32_t* mlo = (uint32_t*)p_mlo;
    uint32_t* wb = (uint32_t*)p_wb;
    float* blr = (float*)p_blr;

    cudaMemcpyAsync(x, x_in, (size_t)N * DIM * sizeof(float), cudaMemcpyDeviceToDevice);

    const int nb = (N + 1023) / 1024;
    detect_kernel<<<1, 256>>>(edges, E, N);
    clear_deg_kernel<<<(N + 255) / 256, 256>>>(N);
    decode_hist_kernel<<<(E + 255) / 256, 256>>>(edges, E);
    scanA_kernel<<<nb, 1024>>>(N);
    scanB_kernel<<<1, 32>>>(nb);
    scanC_kernel<<<(N + 255) / 256, 256>>>(N);
    scatter_kernel<<<(E + 255) / 256, 256>>>(E);

    wconv_all_kernel<<<(2 * LWORDS + 255) / 256, 256>>>(Wl, Wr, projW, W1, W2);
    bconcat_kernel<<<4, 256>>>(bl, br);

    const int ln_blocks = (N + 7) / 8;
    const int mtiles = (N + 127) / 128;

    ln_kernel<<<ln_blocks, 256>>>(x, ln1_g, ln1_b, hhi, hlo, N);

    for (int l = 0; l < 2; l++) {
        size_t off = (size_t)l * LWORDS;
        const uint32_t* wlr = wb + off;
        const uint32_t* pj  = wb + off + 32768;
        const uint32_t* w1  = wb + off + 49152;
        const uint32_t* w2  = wb + off + 81920;
        const float* at_l = att + (size_t)l * HD;
        const float* gb_l = gat_b + (size_t)l * HD;
        const float* pb_l = projb + (size_t)l * DIM;
        const float* b1_l = b1 + (size_t)l * MLPD;
        const float* b2_l = b2 + (size_t)l * DIM;

        gemm_kernel<0><<<dim3(4, mtiles), 256, GEMM_SMEM>>>(
            hhi, hlo, wlr, blr + (size_t)l * 512, xlr, nullptr, nullptr,
            nullptr, nullptr, N, DIM, 512);
        gat_node_kernel<<<(N + 7) / 8, 256>>>(xlr, at_l, gb_l, gohi, golo, N);
        gemm_kernel<3><<<dim3(1, mtiles), 256, GEMM_SMEM3>>>(
            gohi, golo, pj, pb_l, x, hhi, hlo,
            ln2_g + (size_t)l * DIM, ln2_b + (size_t)l * DIM, N, HD, DIM);
        gemm_kernel<2><<<dim3(4, mtiles), 256, GEMM_SMEM>>>(
            hhi, hlo, w1, b1_l, nullptr, mhi, mlo,
            nullptr, nullptr, N, DIM, MLPD);
        if (l == 0) {
            gemm_kernel<3><<<dim3(1, mtiles), 256, GEMM_SMEM3>>>(
                mhi, mlo, w2, b2_l, x, hhi, hlo,
                ln1_g + DIM, ln1_b + DIM, N, MLPD, DIM);
        } else {
            gemm_kernel<1><<<dim3(1, mtiles), 256, GEMM_SMEM>>>(
                mhi, mlo, w2, b2_l, x, nullptr, nullptr,
                nullptr, nullptr, N, MLPD, DIM);
        }
    }
}